// round 8
// baseline (speedup 1.0000x reference)
#include <cuda_runtime.h>
#include <cuda_bf16.h>
#include <cstdint>
#include <cstdio>
#include <math.h>

#define B_  16
#define N_  1024
#define C_  768
#define NH  12
#define HD_ 64
#define QC  2496   // 3*768 + 3*64
#define XC  832    // 768 + 64
#define M1_INV (1.0f/12582912.0f)
#define M2_INV (1.0f/1048576.0f)
#define LR_ 0.001f

// ---------------- scratch ----------------
__device__ float g_qkv[B_*N_*QC];
__device__ float g_gw_part[2*NH*128*HD_*HD_];
__device__ float g_gw_stage[24*8*HD_*HD_];
__device__ float g_gw[2*NH*HD_*HD_];
__device__ float g_gw3_part[B_*64*9];
__device__ float g_gw3[64*9];
__device__ float g_sumsq[25];
__device__ float g_mw1[NH*HD_*HD_];
__device__ float g_mw2[NH*HD_*HD_];
__device__ float g_mw3[64*9];
// bf16 split operands for tensor-core GEMMs
__device__ __nv_bfloat16 g_xh[B_*N_*C_],  g_xl[B_*N_*C_];
__device__ __nv_bfloat16 g_xch[B_*N_*XC], g_xcl[B_*N_*XC];
__device__ __nv_bfloat16 g_wqh[QC*C_],    g_wql[QC*C_];     // [N=2496][K=768]
__device__ __nv_bfloat16 g_wph[C_*XC],    g_wpl[C_*XC];     // [N=768][K=832]

// ---------------- PTX helpers (sm_80-baseline ISA only; scalar asm operands) ----
__device__ __forceinline__ unsigned int smem_to_u32(const void* smem_ptr) {
    unsigned int addr;
    asm("{ .reg .u64 tmp; cvta.to.shared.u64 tmp, %1; cvt.u32.u64 %0, tmp; }"
        : "=r"(addr) : "l"(smem_ptr));
    return addr;
}
__device__ __forceinline__ void cp_async16(unsigned int saddr, const void* gaddr) {
    asm volatile("cp.async.cg.shared.global [%0], [%1], 16;"
                 :: "r"(saddr), "l"(gaddr) : "memory");
}
__device__ __forceinline__ void cp_commit() {
    asm volatile("cp.async.commit_group;" ::: "memory");
}
__device__ __forceinline__ void cp_wait0() {
    asm volatile("cp.async.wait_group 0;" ::: "memory");
}
__device__ __forceinline__ void ldm_x4(unsigned int& r0, unsigned int& r1,
                                       unsigned int& r2, unsigned int& r3,
                                       unsigned int a) {
    asm volatile("ldmatrix.sync.aligned.m8n8.x4.shared.b16 {%0,%1,%2,%3}, [%4];"
                 : "=r"(r0), "=r"(r1), "=r"(r2), "=r"(r3) : "r"(a));
}
__device__ __forceinline__ void mma_bf16(float& c0, float& c1, float& c2, float& c3,
                                         unsigned int a0, unsigned int a1,
                                         unsigned int a2, unsigned int a3,
                                         unsigned int b0, unsigned int b1) {
    asm volatile("mma.sync.aligned.m16n8k16.row.col.f32.bf16.bf16.f32 "
                 "{%0,%1,%2,%3}, {%4,%5,%6,%7}, {%8,%9}, {%0,%1,%2,%3};"
                 : "+f"(c0), "+f"(c1), "+f"(c2), "+f"(c3)
                 : "r"(a0), "r"(a1), "r"(a2), "r"(a3), "r"(b0), "r"(b1));
}

// ---------------- split / transpose conversions ----------------
__device__ __forceinline__ unsigned int pack_bf2(__nv_bfloat16 a, __nv_bfloat16 b) {
    return (unsigned int)__bfloat16_as_ushort(a) |
           ((unsigned int)__bfloat16_as_ushort(b) << 16);
}
__global__ __launch_bounds__(256) void split_convert(
    const float* __restrict__ X, __nv_bfloat16* __restrict__ H,
    __nv_bfloat16* __restrict__ L, int n4)
{
    int i = blockIdx.x * 256 + threadIdx.x;
    if (i >= n4) return;
    float4 v = ((const float4*)X)[i];
    __nv_bfloat16 h0 = __float2bfloat16(v.x), h1 = __float2bfloat16(v.y);
    __nv_bfloat16 h2 = __float2bfloat16(v.z), h3 = __float2bfloat16(v.w);
    __nv_bfloat16 l0 = __float2bfloat16(v.x - __bfloat162float(h0));
    __nv_bfloat16 l1 = __float2bfloat16(v.y - __bfloat162float(h1));
    __nv_bfloat16 l2 = __float2bfloat16(v.z - __bfloat162float(h2));
    __nv_bfloat16 l3 = __float2bfloat16(v.w - __bfloat162float(h3));
    uint2 hh, ll;
    hh.x = pack_bf2(h0, h1); hh.y = pack_bf2(h2, h3);
    ll.x = pack_bf2(l0, l1); ll.y = pack_bf2(l2, l3);
    ((uint2*)H)[i] = hh;
    ((uint2*)L)[i] = ll;
}
// W[K][N] -> T[N][K] split into hi/lo
__global__ __launch_bounds__(256) void transpose_split(
    const float* __restrict__ W, __nv_bfloat16* __restrict__ Th,
    __nv_bfloat16* __restrict__ Tl, int K, int N)
{
    __shared__ float s[32][33];
    const int n0 = blockIdx.x * 32, k0 = blockIdx.y * 32;
    const int tx = threadIdx.x & 31, ty = threadIdx.x >> 5;
    for (int r = ty; r < 32; r += 8)
        s[r][tx] = W[(size_t)(k0 + r) * N + n0 + tx];
    __syncthreads();
    for (int r = ty; r < 32; r += 8) {
        float v = s[tx][r];
        __nv_bfloat16 h = __float2bfloat16(v);
        Th[(size_t)(n0 + r) * K + k0 + tx] = h;
        Tl[(size_t)(n0 + r) * K + k0 + tx] = __float2bfloat16(v - __bfloat162float(h));
    }
}

// ---------------- HMMA GEMM: C[M,Nfull] = A[M,K] @ Bt[Nfull,K]^T + bias ---------
// bf16 hi/lo split, 3-term accumulation. 128x128 block, BK=32, 8 warps (64x32),
// cp.async.cg double buffering, ONE __syncthreads per K-iteration.
#define SROW   40
#define ARR_B  (128*SROW*2)       // 10240 bytes per array
#define STG_B  (4*ARR_B)          // 40960 bytes per stage
#define TCG_SMEM (2*STG_B)        // 81920

__global__ __launch_bounds__(256) void tc_gemm(
    const __nv_bfloat16* __restrict__ Ah, const __nv_bfloat16* __restrict__ Al,
    const __nv_bfloat16* __restrict__ Bh, const __nv_bfloat16* __restrict__ Bl,
    const float* __restrict__ bias, float* __restrict__ C,
    int Nfull, int K)
{
    extern __shared__ __nv_bfloat16 smb[];
    const unsigned int smem_u = smem_to_u32(smb);
    const int t = threadIdx.x, lane = t & 31, wid = t >> 5;
    const int m0 = blockIdx.y * 128, n0 = blockIdx.x * 128;
    const int nb = min(128, Nfull - n0);
    const int wm = (wid >> 2) * 64, wn = (wid & 3) * 32;

    float acc[4][4][4];
#pragma unroll
    for (int a = 0; a < 4; a++)
#pragma unroll
        for (int b = 0; b < 4; b++)
#pragma unroll
            for (int c = 0; c < 4; c++) acc[a][b][c] = 0.f;

    // ---- load plan: each thread fills row r0 and r0+64 of each of 4 arrays ----
    const int r0 = t >> 2, c4 = t & 3;
    const unsigned int s0 = (unsigned int)((r0 * SROW + c4 * 8) * 2);
    const unsigned int o2 = (unsigned int)(64 * SROW * 2);
    const bool v0 = (n0 + r0)      < Nfull;
    const bool v1 = (n0 + 64 + r0) < Nfull;
    const size_t offA0 = (size_t)(m0 + r0) * K + c4 * 8;
    const size_t offA1 = offA0 + (size_t)64 * K;
    const size_t offB0 = (size_t)(v0 ? (n0 + r0)      : 0) * K + c4 * 8;
    const size_t offB1 = (size_t)(v1 ? (n0 + 64 + r0) : 0) * K + c4 * 8;

#define ISSUE(stg, ks) do {                                                  \
        unsigned int _sb = smem_u + (unsigned int)(stg) * STG_B;             \
        const int _ko = (ks) * 32;                                           \
        cp_async16(_sb + s0,                    Ah + offA0 + _ko);           \
        cp_async16(_sb + s0 + o2,               Ah + offA1 + _ko);           \
        cp_async16(_sb + ARR_B + s0,            Al + offA0 + _ko);           \
        cp_async16(_sb + ARR_B + s0 + o2,       Al + offA1 + _ko);           \
        if (v0) {                                                            \
            cp_async16(_sb + 2*ARR_B + s0,      Bh + offB0 + _ko);           \
            cp_async16(_sb + 3*ARR_B + s0,      Bl + offB0 + _ko);           \
        }                                                                    \
        if (v1) {                                                            \
            cp_async16(_sb + 2*ARR_B + s0 + o2, Bh + offB1 + _ko);           \
            cp_async16(_sb + 3*ARR_B + s0 + o2, Bl + offB1 + _ko);           \
        }                                                                    \
        cp_commit();                                                         \
    } while (0)

    const int nk = K / 32;
    ISSUE(0, 0);

    for (int s = 0; s < nk; s++) {
        cp_wait0();
        __syncthreads();
        if (s + 1 < nk) ISSUE((s + 1) & 1, s + 1);

        const unsigned int sb = smem_u + (unsigned int)(s & 1) * STG_B;
#pragma unroll
        for (int kc = 0; kc < 32; kc += 16) {
            unsigned int bh[4][2], bl[4][2];
#pragma unroll
            for (int q = 0; q < 2; q++) {
                unsigned int brow = (unsigned int)(wn + q * 16 + (lane & 7) +
                                                   ((lane >> 4) << 3));
                unsigned int koff = (unsigned int)(((lane >> 3) & 1) * 8);
                unsigned int ab = sb + 2u * ARR_B + (brow * SROW + kc + koff) * 2;
                ldm_x4(bh[2*q][0], bh[2*q][1], bh[2*q+1][0], bh[2*q+1][1], ab);
                ldm_x4(bl[2*q][0], bl[2*q][1], bl[2*q+1][0], bl[2*q+1][1],
                       ab + ARR_B);
            }
#pragma unroll
            for (int mt = 0; mt < 4; mt++) {
                unsigned int arow = (unsigned int)(wm + mt * 16 + (lane & 15));
                unsigned int koff = (unsigned int)((lane >> 4) * 8);
                unsigned int aa = sb + (arow * SROW + kc + koff) * 2;
                unsigned int ah0, ah1, ah2, ah3, al0, al1, al2, al3;
                ldm_x4(ah0, ah1, ah2, ah3, aa);
                ldm_x4(al0, al1, al2, al3, aa + ARR_B);
#pragma unroll
                for (int nt = 0; nt < 4; nt++) {
                    mma_bf16(acc[mt][nt][0], acc[mt][nt][1],
                             acc[mt][nt][2], acc[mt][nt][3],
                             ah0, ah1, ah2, ah3, bh[nt][0], bh[nt][1]);
                    mma_bf16(acc[mt][nt][0], acc[mt][nt][1],
                             acc[mt][nt][2], acc[mt][nt][3],
                             ah0, ah1, ah2, ah3, bl[nt][0], bl[nt][1]);
                    mma_bf16(acc[mt][nt][0], acc[mt][nt][1],
                             acc[mt][nt][2], acc[mt][nt][3],
                             al0, al1, al2, al3, bh[nt][0], bh[nt][1]);
                }
            }
        }
    }
#undef ISSUE

    // ---- epilogue ----
    const int g = lane >> 2, tq = lane & 3;
#pragma unroll
    for (int mt = 0; mt < 4; mt++) {
        const int row = m0 + wm + mt * 16 + g;
#pragma unroll
        for (int nt = 0; nt < 4; nt++) {
            const int col = n0 + wn + nt * 8 + tq * 2;
            if (col < Nfull) {
                float b0 = bias[col], b1 = bias[col + 1];
                float2 o1; o1.x = acc[mt][nt][0] + b0; o1.y = acc[mt][nt][1] + b1;
                float2 o2v; o2v.x = acc[mt][nt][2] + b0; o2v.y = acc[mt][nt][3] + b1;
                *(float2*)(C + (size_t)row * Nfull + col) = o1;
                *(float2*)(C + (size_t)(row + 8) * Nfull + col) = o2v;
            }
        }
    }
}

// ---------------- packed f32x2 helpers ----------------
__device__ __forceinline__ unsigned long long pack_dup(float x) {
    unsigned long long d;
    asm("mov.b64 %0, {%1, %1};" : "=l"(d) : "f"(x));
    return d;
}
__device__ __forceinline__ void fma2(unsigned long long &d,
                                     unsigned long long a, unsigned long long b) {
    asm("fma.rn.f32x2 %0, %1, %2, %0;" : "+l"(d) : "l"(a), "l"(b));
}
__device__ __forceinline__ float2 unpack2(unsigned long long v) {
    float lo, hi;
    asm("mov.b64 {%0, %1}, %2;" : "=f"(lo), "=f"(hi) : "l"(v));
    return make_float2(lo, hi);
}

// ---------------- TTT gradient kernel ----------------
__global__ __launch_bounds__(256) void ttt_grad_kernel(
    const float* __restrict__ w1g, const float* __restrict__ w2g)
{
    extern __shared__ float sm_f[];
    float* w1s = sm_f;
    float* w2s = sm_f + 4096;
    float* k1t = sm_f + 8192;
    float* gA  = sm_f + 8192 + 64 * 132;
    float* gB  = gA + 128 * 64;

    const int tid   = threadIdx.x;
    const int chunk = blockIdx.x;
    const int head  = blockIdx.y;
    const int b     = blockIdx.z;
    const int n0    = chunk * 128;

    for (int e = tid * 4; e < 4096; e += 1024) {
        *(float4*)&w1s[e] = *(const float4*)&w1g[head * 4096 + e];
        *(float4*)&w2s[e] = *(const float4*)&w2g[head * 4096 + e];
    }
    {
        const float* src = g_qkv + (size_t)(b * N_ + n0) * QC + C_ + head * HD_;
        int i  = tid >> 4;
        int k4 = (tid & 15) * 4;
        for (int p = 0; p < 8; p++, i += 16) {
            float4 v = *(const float4*)(src + (size_t)i * QC + k4);
            k1t[(k4 + 0) * 132 + i] = v.x;
            k1t[(k4 + 1) * 132 + i] = v.y;
            k1t[(k4 + 2) * 132 + i] = v.z;
            k1t[(k4 + 3) * 132 + i] = v.w;
        }
    }
    __syncthreads();

    const int ty = tid >> 4, tx = tid & 15;
    const int i0 = ty * 8, j0 = tx * 4;
    unsigned long long accA2[8][2], accB2[8][2];
#pragma unroll
    for (int i = 0; i < 8; i++)
#pragma unroll
        for (int j = 0; j < 2; j++) { accA2[i][j] = 0ULL; accB2[i][j] = 0ULL; }

#pragma unroll 8
    for (int kk = 0; kk < 64; kk++) {
        float a[8];
        *(float4*)&a[0] = *(float4*)&k1t[kk * 132 + i0];
        *(float4*)&a[4] = *(float4*)&k1t[kk * 132 + i0 + 4];
        unsigned long long b1[2], b2[2];
        b1[0] = *(const unsigned long long*)&w1s[kk * 64 + j0];
        b1[1] = *(const unsigned long long*)&w1s[kk * 64 + j0 + 2];
        b2[0] = *(const unsigned long long*)&w2s[kk * 64 + j0];
        b2[1] = *(const unsigned long long*)&w2s[kk * 64 + j0 + 2];
#pragma unroll
        for (int i = 0; i < 8; i++) {
            unsigned long long a2 = pack_dup(a[i]);
            fma2(accA2[i][0], a2, b1[0]);
            fma2(accA2[i][1], a2, b1[1]);
            fma2(accB2[i][0], a2, b2[0]);
            fma2(accB2[i][1], a2, b2[1]);
        }
    }

    const float* v1p = g_qkv + (size_t)(b * N_ + n0 + i0) * QC + 2 * C_ + head * HD_ + j0;
#pragma unroll
    for (int i = 0; i < 8; i++) {
        float4 vv = *(const float4*)(v1p + (size_t)i * QC);
        float v[4] = {vv.x, vv.y, vv.z, vv.w};
        float Aarr[4], Barr[4];
        float2 tt;
        tt = unpack2(accA2[i][0]); Aarr[0] = tt.x; Aarr[1] = tt.y;
        tt = unpack2(accA2[i][1]); Aarr[2] = tt.x; Aarr[3] = tt.y;
        tt = unpack2(accB2[i][0]); Barr[0] = tt.x; Barr[1] = tt.y;
        tt = unpack2(accB2[i][1]); Barr[2] = tt.x; Barr[3] = tt.y;
#pragma unroll
        for (int j = 0; j < 4; j++) {
            float Av = Aarr[j], Bv = Barr[j];
            float sig = 1.f / (1.f + expf(-Bv));
            float sil = Bv * sig;
            float g   = (Av * sil - v[j]) * M1_INV;
            gA[(i0 + i) * 64 + j0 + j] = g * sil;
            gB[(i0 + i) * 64 + j0 + j] = g * Av * sig * (1.f + Bv * (1.f - sig));
        }
    }
    __syncthreads();

    const int k0 = ty * 4, jj0 = tx * 4;
    unsigned long long r1[4][2], r2[4][2];
#pragma unroll
    for (int q = 0; q < 4; q++)
#pragma unroll
        for (int r = 0; r < 2; r++) { r1[q][r] = 0ULL; r2[q][r] = 0ULL; }

#pragma unroll 4
    for (int i = 0; i < 128; i++) {
        float a[4];
#pragma unroll
        for (int q = 0; q < 4; q++) a[q] = k1t[(k0 + q) * 132 + i];
        unsigned long long bA[2], bB[2];
        bA[0] = *(const unsigned long long*)&gA[i * 64 + jj0];
        bA[1] = *(const unsigned long long*)&gA[i * 64 + jj0 + 2];
        bB[0] = *(const unsigned long long*)&gB[i * 64 + jj0];
        bB[1] = *(const unsigned long long*)&gB[i * 64 + jj0 + 2];
#pragma unroll
        for (int q = 0; q < 4; q++) {
            unsigned long long a2 = pack_dup(a[q]);
            fma2(r1[q][0], a2, bA[0]);
            fma2(r1[q][1], a2, bA[1]);
            fma2(r2[q][0], a2, bB[0]);
            fma2(r2[q][1], a2, bB[1]);
        }
    }

    const int pidx = b * 8 + chunk;
    float* d1 = g_gw_part + ((size_t)(0 * NH + head) * 128 + pidx) * 4096;
    float* d2 = g_gw_part + ((size_t)(1 * NH + head) * 128 + pidx) * 4096;
#pragma unroll
    for (int q = 0; q < 4; q++) {
        float2 p;
        p = unpack2(r1[q][0]); *(float2*)&d1[(k0 + q) * 64 + jj0]     = p;
        p = unpack2(r1[q][1]); *(float2*)&d1[(k0 + q) * 64 + jj0 + 2] = p;
        p = unpack2(r2[q][0]); *(float2*)&d2[(k0 + q) * 64 + jj0]     = p;
        p = unpack2(r2[q][1]); *(float2*)&d2[(k0 + q) * 64 + jj0 + 2] = p;
    }
}

// ---------------- TTT forward kernel (writes bf16 hi/lo directly) ----------------
__global__ __launch_bounds__(256) void ttt_fwd_kernel()
{
    extern __shared__ float sm_f[];
    float* w1s = sm_f;
    float* w2s = sm_f + 4096;
    float* q1t = sm_f + 8192;

    const int tid   = threadIdx.x;
    const int chunk = blockIdx.x;
    const int head  = blockIdx.y;
    const int b     = blockIdx.z;
    const int n0    = chunk * 128;

    for (int e = tid * 4; e < 4096; e += 1024) {
        *(float4*)&w1s[e] = *(const float4*)&g_mw1[head * 4096 + e];
        *(float4*)&w2s[e] = *(const float4*)&g_mw2[head * 4096 + e];
    }
    {
        const float* src = g_qkv + (size_t)(b * N_ + n0) * QC + head * HD_;
        int i  = tid >> 4;
        int k4 = (tid & 15) * 4;
        for (int p = 0; p < 8; p++, i += 16) {
            float4 v = *(const float4*)(src + (size_t)i * QC + k4);
            q1t[(k4 + 0) * 132 + i] = v.x;
            q1t[(k4 + 1) * 132 + i] = v.y;
            q1t[(k4 + 2) * 132 + i] = v.z;
            q1t[(k4 + 3) * 132 + i] = v.w;
        }
    }
    __syncthreads();

    const int ty = tid >> 4, tx = tid & 15;
    const int i0 = ty * 8, j0 = tx * 4;
    unsigned long long accA2[8][2], accB2[8][2];
#pragma unroll
    for (int i = 0; i < 8; i++)
#pragma unroll
        for (int j = 0; j < 2; j++) { accA2[i][j] = 0ULL; accB2[i][j] = 0ULL; }

#pragma unroll 8
    for (int kk = 0; kk < 64; kk++) {
        float a[8];
        *(float4*)&a[0] = *(float4*)&q1t[kk * 132 + i0];
        *(float4*)&a[4] = *(float4*)&q1t[kk * 132 + i0 + 4];
        unsigned long long b1[2], b2[2];
        b1[0] = *(const unsigned long long*)&w1s[kk * 64 + j0];
        b1[1] = *(const unsigned long long*)&w1s[kk * 64 + j0 + 2];
        b2[0] = *(const unsigned long long*)&w2s[kk * 64 + j0];
        b2[1] = *(const unsigned long long*)&w2s[kk * 64 + j0 + 2];
#pragma unroll
        for (int i = 0; i < 8; i++) {
            unsigned long long a2 = pack_dup(a[i]);
            fma2(accA2[i][0], a2, b1[0]);
            fma2(accA2[i][1], a2, b1[1]);
            fma2(accB2[i][0], a2, b2[0]);
            fma2(accB2[i][1], a2, b2[1]);
        }
    }

#pragma unroll
    for (int i = 0; i < 8; i++) {
        float Aarr[4], Barr[4];
        float2 tt;
        tt = unpack2(accA2[i][0]); Aarr[0] = tt.x; Aarr[1] = tt.y;
        tt = unpack2(accA2[i][1]); Aarr[2] = tt.x; Aarr[3] = tt.y;
        tt = unpack2(accB2[i][0]); Barr[0] = tt.x; Barr[1] = tt.y;
        tt = unpack2(accB2[i][1]); Barr[2] = tt.x; Barr[3] = tt.y;
        float out[4];
#pragma unroll
        for (int j = 0; j < 4; j++) {
            float sig = 1.f / (1.f + expf(-Barr[j]));
            out[j] = Aarr[j] * (Barr[j] * sig);
        }
        __nv_bfloat16 h0 = __float2bfloat16(out[0]), h1 = __float2bfloat16(out[1]);
        __nv_bfloat16 h2 = __float2bfloat16(out[2]), h3 = __float2bfloat16(out[3]);
        __nv_bfloat16 l0 = __float2bfloat16(out[0] - __bfloat162float(h0));
        __nv_bfloat16 l1 = __float2bfloat16(out[1] - __bfloat162float(h1));
        __nv_bfloat16 l2 = __float2bfloat16(out[2] - __bfloat162float(h2));
        __nv_bfloat16 l3 = __float2bfloat16(out[3] - __bfloat162float(h3));
        uint2 hh, ll;
        hh.x = pack_bf2(h0, h1); hh.y = pack_bf2(h2, h3);
        ll.x = pack_bf2(l0, l1); ll.y = pack_bf2(l2, l3);
        const size_t idx = (size_t)(b * N_ + n0 + i0 + i) * XC + head * HD_ + j0;
        *(uint2*)(g_xch + idx) = hh;
        *(uint2*)(g_xcl + idx) = ll;
    }
}

// ---------------- conv grad ----------------
__global__ __launch_bounds__(256) void conv_grad_kernel(const float* __restrict__ w3g)
{
    const int bc = blockIdx.x;
    const int b = bc >> 6, c = bc & 63;
    const int tid = threadIdx.x;
    __shared__ float k2s[32][33];
    __shared__ float wk[9];
    __shared__ float red[256];

    if (tid < 9) wk[tid] = w3g[c * 9 + tid];
    const float* base = g_qkv + (size_t)(b * N_) * QC;
    for (int p = tid; p < 1024; p += 256)
        k2s[p >> 5][p & 31] = base[(size_t)p * QC + 2368 + c];
    __syncthreads();

    float acc[9];
#pragma unroll
    for (int q = 0; q < 9; q++) acc[q] = 0.f;

    for (int p = tid; p < 1024; p += 256) {
        const int y = p >> 5, x = p & 31;
        float t[9];
#pragma unroll
        for (int dy = 0; dy < 3; dy++)
#pragma unroll
            for (int dx = 0; dx < 3; dx++) {
                int yy = y + dy - 1, xx = x + dx - 1;
                t[dy * 3 + dx] = (yy >= 0 && yy < 32 && xx >= 0 && xx < 32)
                                 ? k2s[yy][xx] : 0.f;
            }
        float f = 0.f;
#pragma unroll
        for (int q = 0; q < 9; q++) f = fmaf(wk[q], t[q], f);
        float v = base[(size_t)p * QC + 2432 + c];
        float g = (f - v) * M2_INV;
#pragma unroll
        for (int q = 0; q < 9; q++) acc[q] = fmaf(g, t[q], acc[q]);
    }

    for (int q = 0; q < 9; q++) {
        red[tid] = acc[q];
        __syncthreads();
        for (int s = 128; s > 0; s >>= 1) {
            if (tid < s) red[tid] += red[tid + s];
            __syncthreads();
        }
        if (tid == 0) g_gw3_part[(size_t)bc * 9 + q] = red[0];
        __syncthreads();
    }
}

__global__ void conv_grad_reduce_kernel()
{
    const int tid = threadIdx.x;
    __shared__ float red[576];
    float s = 0.f;
    const int c = tid / 9, q = tid % 9;
    for (int b = 0; b < B_; b++) s += g_gw3_part[(size_t)(b * 64 + c) * 9 + q];
    g_gw3[tid] = s;
    red[tid] = s * s;
    __syncthreads();
    if (tid < 64) red[tid] += red[tid + 512];
    __syncthreads();
    for (int st = 256; st > 0; st >>= 1) {
        if (tid < st && tid + st < 576) red[tid] += red[tid + st];
        __syncthreads();
    }
    if (tid == 0) g_sumsq[24] = red[0];
}

// ---------------- two-stage gw reduce ----------------
__global__ __launch_bounds__(256) void reduce_gw_stage1()
{
    const int th = blockIdx.x >> 3;
    const int g  = blockIdx.x & 7;
    const int tid = threadIdx.x;
    const float* src = g_gw_part + ((size_t)th * 128 + g * 16) * 4096;
    float s[16];
#pragma unroll
    for (int q = 0; q < 16; q++) s[q] = 0.f;
    for (int p = 0; p < 16; p++) {
        const float* row = src + (size_t)p * 4096 + tid;
#pragma unroll
        for (int q = 0; q < 16; q++) s[q] += row[q * 256];
    }
    float* dst = g_gw_stage + (size_t)(th * 8 + g) * 4096 + tid;
#pragma unroll
    for (int q = 0; q < 16; q++) dst[q * 256] = s[q];
}

__global__ __launch_bounds__(256) void reduce_gw_stage2()
{
    const int th  = blockIdx.x;
    const int tid = threadIdx.x;
    const float* src = g_gw_stage + (size_t)th * 8 * 4096;
    float* dst = g_gw + (size_t)th * 4096;

    float s[16];
#pragma unroll
    for (int q = 0; q < 16; q++) s[q] = 0.f;
    for (int p = 0; p < 8; p++) {
        const float* row = src + (size_t)p * 4096 + tid;
#pragma unroll
        for (int q = 0; q < 16; q++) s[q] += row[q * 256];
    }
    float ss = 0.f;
#pragma unroll
    for (int q = 0; q < 16; q++) { dst[tid + q * 256] = s[q]; ss += s[q] * s[q]; }

    __shared__ float red[256];
    red[tid] = ss;
    __syncthreads();
    for (int st = 128; st > 0; st >>= 1) {
        if (tid < st) red[tid] += red[tid + st];
        __syncthreads();
    }
    if (tid == 0) g_sumsq[th] = red[0];
}

// ---------------- weight update (scales fused) ----------------
__global__ void update_w_kernel(const float* __restrict__ w1g,
                                const float* __restrict__ w2g,
                                const float* __restrict__ w3g)
{
    __shared__ float sc[3];
    if (threadIdx.x == 0) {
        float s1 = 0.f, s2 = 0.f;
        for (int h = 0; h < NH; h++) { s1 += g_sumsq[h]; s2 += g_sumsq[NH + h]; }
        sc[0] = LR_ / (sqrtf(s1) + 1.f);
        sc[1] = LR_ / (sqrtf(s2) + 1.f);
        sc[2] = LR_ / (sqrtf(g_sumsq[24]) + 1.f);
    }
    __syncthreads();
    const int i = blockIdx.x * 256 + threadIdx.x;
    if (i < 49152) {
        g_mw1[i] = w1g[i] - sc[0] * g_gw[i];
    } else if (i < 98304) {
        const int k = i - 49152;
        g_mw2[k] = w2g[k] - sc[1] * g_gw[49152 + k];
    } else if (i < 98880) {
        const int k = i - 98304;
        g_mw3[k] = w3g[k] - sc[2] * g_gw3[k];
    }
}

// ---------------- conv forward (writes bf16 hi/lo directly) ----------------
__global__ __launch_bounds__(256) void conv_fwd_kernel()
{
    const int bc = blockIdx.x;
    const int b = bc >> 6, c = bc & 63;
    const int tid = threadIdx.x;
    __shared__ float q2s[32][33];
    __shared__ float wk[9];
    if (tid < 9) wk[tid] = g_mw3[c * 9 + tid];
    const float* base = g_qkv + (size_t)(b * N_) * QC;
    for (int p = tid; p < 1024; p += 256)
        q2s[p >> 5][p & 31] = base[(size_t)p * QC + 2304 + c];
    __syncthreads();

    for (int p = tid; p < 1024; p += 256) {
        const int y = p >> 5, x = p & 31;
        float f = 0.f;
#pragma unroll
        for (int dy = 0; dy < 3; dy++)
#pragma unroll
            for (int dx = 0; dx < 3; dx++) {
                int yy = y + dy - 1, xx = x + dx - 1;
                if (yy >= 0 && yy < 32 && xx >= 0 && xx < 32)
                    f = fmaf(wk[dy * 3 + dx], q2s[yy][xx], f);
            }
        __nv_bfloat16 h = __float2bfloat16(f);
        __nv_bfloat16 l = __float2bfloat16(f - __bfloat162float(h));
        const size_t idx = (size_t)(b * N_ + p) * XC + 768 + c;
        g_xch[idx] = h;
        g_xcl[idx] = l;
    }
}

// ---------------- launch ----------------
extern "C" void kernel_launch(void* const* d_in, const int* in_sizes, int n_in,
                              void* d_out, int out_size)
{
    const float *x = nullptr, *Wqkv = nullptr, *bqkv = nullptr, *w1 = nullptr,
                *w2 = nullptr, *w3 = nullptr, *Wproj = nullptr, *bproj = nullptr;
    for (int i = 0; i < n_in; i++) {
        const int s = in_sizes[i];
        const float* p = (const float*)d_in[i];
        if      (s == B_*N_*C_)   x = p;
        else if (s == C_*QC)      Wqkv = p;
        else if (s == QC)         bqkv = p;
        else if (s == NH*HD_*HD_) { if (!w1) w1 = p; else w2 = p; }
        else if (s == 64*9)       w3 = p;
        else if (s == XC*C_)      Wproj = p;
        else if (s == C_)         bproj = p;
    }

    float* qkv_ptr = nullptr;
    __nv_bfloat16 *xh, *xl, *xch, *xcl, *wqh, *wql, *wph, *wpl;
    cudaGetSymbolAddress((void**)&qkv_ptr,  g_qkv);
    cudaGetSymbolAddress((void**)&xh,  g_xh);
    cudaGetSymbolAddress((void**)&xl,  g_xl);
    cudaGetSymbolAddress((void**)&xch, g_xch);
    cudaGetSymbolAddress((void**)&xcl, g_xcl);
    cudaGetSymbolAddress((void**)&wqh, g_wqh);
    cudaGetSymbolAddress((void**)&wql, g_wql);
    cudaGetSymbolAddress((void**)&wph, g_wph);
    cudaGetSymbolAddress((void**)&wpl, g_wpl);

    cudaFuncSetAttribute(ttt_grad_kernel,
        cudaFuncAttributeMaxDynamicSharedMemorySize, 132096);
    cudaFuncSetAttribute(ttt_fwd_kernel,
        cudaFuncAttributeMaxDynamicSharedMemorySize, 66560);
    cudaFuncSetAttribute(tc_gemm,
        cudaFuncAttributeMaxDynamicSharedMemorySize, TCG_SMEM);

    // 1. split x, transpose+split weights
    split_convert<<<(B_*N_*C_/4 + 255)/256, 256>>>(x, xh, xl, B_*N_*C_/4);
    transpose_split<<<dim3(QC/32, C_/32), 256>>>(Wqkv, wqh, wql, C_, QC);
    transpose_split<<<dim3(C_/32, XC/32), 256>>>(Wproj, wph, wpl, XC, C_);

    // 2. qkv = x @ Wqkv + bqkv  (HMMA, 3-term bf16 split)
    tc_gemm<<<dim3((QC + 127)/128, (B_*N_)/128), 256, TCG_SMEM>>>(
        xh, xl, wqh, wql, bqkv, qkv_ptr, QC, C_);

    // 3. TTT + conv gradients, reduce, update (scales fused)
    ttt_grad_kernel<<<dim3(8, NH, B_), 256, 132096>>>(w1, w2);
    conv_grad_kernel<<<B_ * 64, 256>>>(w3);
    conv_grad_reduce_kernel<<<1, 576>>>();
    reduce_gw_stage1<<<192, 256>>>();
    reduce_gw_stage2<<<24, 256>>>();
    update_w_kernel<<<(98880 + 255)/256, 256>>>(w1, w2, w3);

    // 4. post-update forward (writes bf16 splits directly)
    ttt_fwd_kernel<<<dim3(8, NH, B_), 256, 66560>>>();
    conv_fwd_kernel<<<B_ * 64, 256>>>();

    // 5. proj GEMM
    tc_gemm<<<dim3(C_/128, (B_*N_)/128), 256, TCG_SMEM>>>(
        xch, xcl, wph, wpl, bproj, (float*)d_out, C_, XC);
}

// round 9
// speedup vs baseline: 1.0185x; 1.0185x over previous
#include <cuda_runtime.h>
#include <cuda_bf16.h>
#include <cstdint>
#include <cstdio>
#include <math.h>

#define B_  16
#define N_  1024
#define C_  768
#define NH  12
#define HD_ 64
#define QC  2496   // 3*768 + 3*64
#define XC  832    // 768 + 64
#define M1_INV (1.0f/12582912.0f)
#define M2_INV (1.0f/1048576.0f)
#define LR_ 0.001f

// ---------------- scratch ----------------
__device__ float g_qkv[B_*N_*QC];
__device__ float g_gw_part[2*NH*128*HD_*HD_];
__device__ float g_gw_stage[24*8*HD_*HD_];
__device__ float g_gw[2*NH*HD_*HD_];
__device__ float g_gw3_part[B_*64*9];
__device__ float g_gw3[64*9];
__device__ float g_sumsq[25];
__device__ float g_mw1[NH*HD_*HD_];
__device__ float g_mw2[NH*HD_*HD_];
__device__ float g_mw3[64*9];
// bf16 split operands for tensor-core GEMMs
__device__ __nv_bfloat16 g_xh[B_*N_*C_],  g_xl[B_*N_*C_];
__device__ __nv_bfloat16 g_xch[B_*N_*XC], g_xcl[B_*N_*XC];
__device__ __nv_bfloat16 g_wqh[QC*C_],    g_wql[QC*C_];     // [N=2496][K=768]
__device__ __nv_bfloat16 g_wph[C_*XC],    g_wpl[C_*XC];     // [N=768][K=832]

// ---------------- PTX helpers ----------------
__device__ __forceinline__ unsigned int smem_to_u32(const void* smem_ptr) {
    unsigned int addr;
    asm("{ .reg .u64 tmp; cvta.to.shared.u64 tmp, %1; cvt.u32.u64 %0, tmp; }"
        : "=r"(addr) : "l"(smem_ptr));
    return addr;
}
__device__ __forceinline__ void cp_async16(unsigned int saddr, const void* gaddr) {
    asm volatile("cp.async.cg.shared.global [%0], [%1], 16;"
                 :: "r"(saddr), "l"(gaddr) : "memory");
}
__device__ __forceinline__ void cp_commit() {
    asm volatile("cp.async.commit_group;" ::: "memory");
}
__device__ __forceinline__ void cp_wait1() {
    asm volatile("cp.async.wait_group 1;" ::: "memory");
}
__device__ __forceinline__ void cp_wait0() {
    asm volatile("cp.async.wait_group 0;" ::: "memory");
}
__device__ __forceinline__ void ldm_x4(unsigned int& r0, unsigned int& r1,
                                       unsigned int& r2, unsigned int& r3,
                                       unsigned int a) {
    asm volatile("ldmatrix.sync.aligned.m8n8.x4.shared.b16 {%0,%1,%2,%3}, [%4];"
                 : "=r"(r0), "=r"(r1), "=r"(r2), "=r"(r3) : "r"(a));
}
__device__ __forceinline__ void mma_bf16(float& c0, float& c1, float& c2, float& c3,
                                         unsigned int a0, unsigned int a1,
                                         unsigned int a2, unsigned int a3,
                                         unsigned int b0, unsigned int b1) {
    asm volatile("mma.sync.aligned.m16n8k16.row.col.f32.bf16.bf16.f32 "
                 "{%0,%1,%2,%3}, {%4,%5,%6,%7}, {%8,%9}, {%0,%1,%2,%3};"
                 : "+f"(c0), "+f"(c1), "+f"(c2), "+f"(c3)
                 : "r"(a0), "r"(a1), "r"(a2), "r"(a3), "r"(b0), "r"(b1));
}

// ---------------- split / transpose conversions ----------------
__device__ __forceinline__ unsigned int pack_bf2(__nv_bfloat16 a, __nv_bfloat16 b) {
    return (unsigned int)__bfloat16_as_ushort(a) |
           ((unsigned int)__bfloat16_as_ushort(b) << 16);
}
__global__ __launch_bounds__(256) void split_convert(
    const float* __restrict__ X, __nv_bfloat16* __restrict__ H,
    __nv_bfloat16* __restrict__ L, int n4)
{
    int i = blockIdx.x * 256 + threadIdx.x;
    if (i >= n4) return;
    float4 v = ((const float4*)X)[i];
    __nv_bfloat16 h0 = __float2bfloat16(v.x), h1 = __float2bfloat16(v.y);
    __nv_bfloat16 h2 = __float2bfloat16(v.z), h3 = __float2bfloat16(v.w);
    __nv_bfloat16 l0 = __float2bfloat16(v.x - __bfloat162float(h0));
    __nv_bfloat16 l1 = __float2bfloat16(v.y - __bfloat162float(h1));
    __nv_bfloat16 l2 = __float2bfloat16(v.z - __bfloat162float(h2));
    __nv_bfloat16 l3 = __float2bfloat16(v.w - __bfloat162float(h3));
    uint2 hh, ll;
    hh.x = pack_bf2(h0, h1); hh.y = pack_bf2(h2, h3);
    ll.x = pack_bf2(l0, l1); ll.y = pack_bf2(l2, l3);
    ((uint2*)H)[i] = hh;
    ((uint2*)L)[i] = ll;
}
// W[K][N] -> T[N][K] split into hi/lo
__global__ __launch_bounds__(256) void transpose_split(
    const float* __restrict__ W, __nv_bfloat16* __restrict__ Th,
    __nv_bfloat16* __restrict__ Tl, int K, int N)
{
    __shared__ float s[32][33];
    const int n0 = blockIdx.x * 32, k0 = blockIdx.y * 32;
    const int tx = threadIdx.x & 31, ty = threadIdx.x >> 5;
    for (int r = ty; r < 32; r += 8)
        s[r][tx] = W[(size_t)(k0 + r) * N + n0 + tx];
    __syncthreads();
    for (int r = ty; r < 32; r += 8) {
        float v = s[tx][r];
        __nv_bfloat16 h = __float2bfloat16(v);
        Th[(size_t)(n0 + r) * K + k0 + tx] = h;
        Tl[(size_t)(n0 + r) * K + k0 + tx] = __float2bfloat16(v - __bfloat162float(h));
    }
}

// ---------------- HMMA GEMM: C[M,Nfull] = A[M,K] @ Bt[Nfull,K]^T + bias ---------
// bf16 hi/lo split, 3-term accumulation. 128x128 block, BK=32, 4 warps (64x64),
// cp.async.cg double buffering, R7-style issue-then-wait pipeline.
#define SROW   40
#define ARR_B  (128*SROW*2)       // 10240 bytes per array
#define STG_B  (4*ARR_B)          // 40960 bytes per stage
#define TCG_SMEM (2*STG_B)        // 81920

__global__ __launch_bounds__(128) void tc_gemm(
    const __nv_bfloat16* __restrict__ Ah, const __nv_bfloat16* __restrict__ Al,
    const __nv_bfloat16* __restrict__ Bh, const __nv_bfloat16* __restrict__ Bl,
    const float* __restrict__ bias, float* __restrict__ C,
    int Nfull, int K)
{
    extern __shared__ __nv_bfloat16 smb[];
    const unsigned int smem_u = smem_to_u32(smb);
    const int t = threadIdx.x, lane = t & 31, wid = t >> 5;     // 4 warps
    const int m0 = blockIdx.y * 128, n0 = blockIdx.x * 128;
    const int wm = (wid >> 1) * 64, wn = (wid & 1) * 64;

    float acc[4][8][4];
#pragma unroll
    for (int a = 0; a < 4; a++)
#pragma unroll
        for (int b = 0; b < 8; b++)
#pragma unroll
            for (int c = 0; c < 4; c++) acc[a][b][c] = 0.f;

    // ---- load plan: thread t fills rows r0, r0+32, r0+64, r0+96 of each array --
    const int r0 = t >> 2, c4 = t & 3;
    const unsigned int s0 = (unsigned int)((r0 * SROW + c4 * 8) * 2);
    const unsigned int sstep = (unsigned int)(32 * SROW * 2);
    bool vB[4];
    size_t offA[4], offB[4];
#pragma unroll
    for (int j = 0; j < 4; j++) {
        const int rr = r0 + 32 * j;
        vB[j]   = (n0 + rr) < Nfull;
        offA[j] = (size_t)(m0 + rr) * K + c4 * 8;
        offB[j] = (size_t)(vB[j] ? (n0 + rr) : 0) * K + c4 * 8;
    }

#define ISSUE(stg, ks) do {                                                  \
        unsigned int _sb = smem_u + (unsigned int)(stg) * STG_B;             \
        const int _ko = (ks) * 32;                                           \
        _Pragma("unroll")                                                    \
        for (int j = 0; j < 4; j++) {                                        \
            unsigned int _s = _sb + s0 + (unsigned int)j * sstep;            \
            cp_async16(_s,             Ah + offA[j] + _ko);                  \
            cp_async16(_s + ARR_B,     Al + offA[j] + _ko);                  \
            if (vB[j]) {                                                     \
                cp_async16(_s + 2*ARR_B, Bh + offB[j] + _ko);                \
                cp_async16(_s + 3*ARR_B, Bl + offB[j] + _ko);                \
            }                                                                \
        }                                                                    \
        cp_commit();                                                         \
    } while (0)

    const int nk = K / 32;
    ISSUE(0, 0);

    for (int s = 0; s < nk; s++) {
        if (s + 1 < nk) { ISSUE((s + 1) & 1, s + 1); cp_wait1(); }
        else            { cp_wait0(); }
        __syncthreads();

        const unsigned int sb = smem_u + (unsigned int)(s & 1) * STG_B;
#pragma unroll
        for (int kc = 0; kc < 32; kc += 16) {
            // B fragments: 8 n-tiles (hi & lo)
            unsigned int bh[8][2], bl[8][2];
#pragma unroll
            for (int q = 0; q < 4; q++) {
                unsigned int brow = (unsigned int)(wn + q * 16 + (lane & 7) +
                                                   ((lane >> 4) << 3));
                unsigned int koff = (unsigned int)(((lane >> 3) & 1) * 8);
                unsigned int ab = sb + 2u * ARR_B + (brow * SROW + kc + koff) * 2;
                ldm_x4(bh[2*q][0], bh[2*q][1], bh[2*q+1][0], bh[2*q+1][1], ab);
                ldm_x4(bl[2*q][0], bl[2*q][1], bl[2*q+1][0], bl[2*q+1][1],
                       ab + ARR_B);
            }
#pragma unroll
            for (int mt = 0; mt < 4; mt++) {
                unsigned int arow = (unsigned int)(wm + mt * 16 + (lane & 15));
                unsigned int koff = (unsigned int)((lane >> 4) * 8);
                unsigned int aa = sb + (arow * SROW + kc + koff) * 2;
                unsigned int ah0, ah1, ah2, ah3, al0, al1, al2, al3;
                ldm_x4(ah0, ah1, ah2, ah3, aa);
                ldm_x4(al0, al1, al2, al3, aa + ARR_B);
#pragma unroll
                for (int nt = 0; nt < 8; nt++) {
                    mma_bf16(acc[mt][nt][0], acc[mt][nt][1],
                             acc[mt][nt][2], acc[mt][nt][3],
                             ah0, ah1, ah2, ah3, bh[nt][0], bh[nt][1]);
                    mma_bf16(acc[mt][nt][0], acc[mt][nt][1],
                             acc[mt][nt][2], acc[mt][nt][3],
                             ah0, ah1, ah2, ah3, bl[nt][0], bl[nt][1]);
                    mma_bf16(acc[mt][nt][0], acc[mt][nt][1],
                             acc[mt][nt][2], acc[mt][nt][3],
                             al0, al1, al2, al3, bh[nt][0], bh[nt][1]);
                }
            }
        }
        __syncthreads();
    }
#undef ISSUE

    // ---- epilogue ----
    const int g = lane >> 2, tq = lane & 3;
#pragma unroll
    for (int mt = 0; mt < 4; mt++) {
        const int row = m0 + wm + mt * 16 + g;
#pragma unroll
        for (int nt = 0; nt < 8; nt++) {
            const int col = n0 + wn + nt * 8 + tq * 2;
            if (col < Nfull) {
                float b0 = bias[col], b1 = bias[col + 1];
                float2 o1; o1.x = acc[mt][nt][0] + b0; o1.y = acc[mt][nt][1] + b1;
                float2 o2v; o2v.x = acc[mt][nt][2] + b0; o2v.y = acc[mt][nt][3] + b1;
                *(float2*)(C + (size_t)row * Nfull + col) = o1;
                *(float2*)(C + (size_t)(row + 8) * Nfull + col) = o2v;
            }
        }
    }
}

// ---------------- packed f32x2 helpers ----------------
__device__ __forceinline__ unsigned long long pack_dup(float x) {
    unsigned long long d;
    asm("mov.b64 %0, {%1, %1};" : "=l"(d) : "f"(x));
    return d;
}
__device__ __forceinline__ void fma2(unsigned long long &d,
                                     unsigned long long a, unsigned long long b) {
    asm("fma.rn.f32x2 %0, %1, %2, %0;" : "+l"(d) : "l"(a), "l"(b));
}
__device__ __forceinline__ float2 unpack2(unsigned long long v) {
    float lo, hi;
    asm("mov.b64 {%0, %1}, %2;" : "=f"(lo), "=f"(hi) : "l"(v));
    return make_float2(lo, hi);
}

// ---------------- TTT gradient kernel ----------------
__global__ __launch_bounds__(256) void ttt_grad_kernel(
    const float* __restrict__ w1g, const float* __restrict__ w2g)
{
    extern __shared__ float sm_f[];
    float* w1s = sm_f;
    float* w2s = sm_f + 4096;
    float* k1t = sm_f + 8192;
    float* gA  = sm_f + 8192 + 64 * 132;
    float* gB  = gA + 128 * 64;

    const int tid   = threadIdx.x;
    const int chunk = blockIdx.x;
    const int head  = blockIdx.y;
    const int b     = blockIdx.z;
    const int n0    = chunk * 128;

    for (int e = tid * 4; e < 4096; e += 1024) {
        *(float4*)&w1s[e] = *(const float4*)&w1g[head * 4096 + e];
        *(float4*)&w2s[e] = *(const float4*)&w2g[head * 4096 + e];
    }
    {
        const float* src = g_qkv + (size_t)(b * N_ + n0) * QC + C_ + head * HD_;
        int i  = tid >> 4;
        int k4 = (tid & 15) * 4;
        for (int p = 0; p < 8; p++, i += 16) {
            float4 v = *(const float4*)(src + (size_t)i * QC + k4);
            k1t[(k4 + 0) * 132 + i] = v.x;
            k1t[(k4 + 1) * 132 + i] = v.y;
            k1t[(k4 + 2) * 132 + i] = v.z;
            k1t[(k4 + 3) * 132 + i] = v.w;
        }
    }
    __syncthreads();

    const int ty = tid >> 4, tx = tid & 15;
    const int i0 = ty * 8, j0 = tx * 4;
    unsigned long long accA2[8][2], accB2[8][2];
#pragma unroll
    for (int i = 0; i < 8; i++)
#pragma unroll
        for (int j = 0; j < 2; j++) { accA2[i][j] = 0ULL; accB2[i][j] = 0ULL; }

#pragma unroll 8
    for (int kk = 0; kk < 64; kk++) {
        float a[8];
        *(float4*)&a[0] = *(float4*)&k1t[kk * 132 + i0];
        *(float4*)&a[4] = *(float4*)&k1t[kk * 132 + i0 + 4];
        unsigned long long b1[2], b2[2];
        b1[0] = *(const unsigned long long*)&w1s[kk * 64 + j0];
        b1[1] = *(const unsigned long long*)&w1s[kk * 64 + j0 + 2];
        b2[0] = *(const unsigned long long*)&w2s[kk * 64 + j0];
        b2[1] = *(const unsigned long long*)&w2s[kk * 64 + j0 + 2];
#pragma unroll
        for (int i = 0; i < 8; i++) {
            unsigned long long a2 = pack_dup(a[i]);
            fma2(accA2[i][0], a2, b1[0]);
            fma2(accA2[i][1], a2, b1[1]);
            fma2(accB2[i][0], a2, b2[0]);
            fma2(accB2[i][1], a2, b2[1]);
        }
    }

    const float* v1p = g_qkv + (size_t)(b * N_ + n0 + i0) * QC + 2 * C_ + head * HD_ + j0;
#pragma unroll
    for (int i = 0; i < 8; i++) {
        float4 vv = *(const float4*)(v1p + (size_t)i * QC);
        float v[4] = {vv.x, vv.y, vv.z, vv.w};
        float Aarr[4], Barr[4];
        float2 tt;
        tt = unpack2(accA2[i][0]); Aarr[0] = tt.x; Aarr[1] = tt.y;
        tt = unpack2(accA2[i][1]); Aarr[2] = tt.x; Aarr[3] = tt.y;
        tt = unpack2(accB2[i][0]); Barr[0] = tt.x; Barr[1] = tt.y;
        tt = unpack2(accB2[i][1]); Barr[2] = tt.x; Barr[3] = tt.y;
#pragma unroll
        for (int j = 0; j < 4; j++) {
            float Av = Aarr[j], Bv = Barr[j];
            float sig = 1.f / (1.f + expf(-Bv));
            float sil = Bv * sig;
            float g   = (Av * sil - v[j]) * M1_INV;
            gA[(i0 + i) * 64 + j0 + j] = g * sil;
            gB[(i0 + i) * 64 + j0 + j] = g * Av * sig * (1.f + Bv * (1.f - sig));
        }
    }
    __syncthreads();

    const int k0 = ty * 4, jj0 = tx * 4;
    unsigned long long r1[4][2], r2[4][2];
#pragma unroll
    for (int q = 0; q < 4; q++)
#pragma unroll
        for (int r = 0; r < 2; r++) { r1[q][r] = 0ULL; r2[q][r] = 0ULL; }

#pragma unroll 4
    for (int i = 0; i < 128; i++) {
        float a[4];
#pragma unroll
        for (int q = 0; q < 4; q++) a[q] = k1t[(k0 + q) * 132 + i];
        unsigned long long bA[2], bB[2];
        bA[0] = *(const unsigned long long*)&gA[i * 64 + jj0];
        bA[1] = *(const unsigned long long*)&gA[i * 64 + jj0 + 2];
        bB[0] = *(const unsigned long long*)&gB[i * 64 + jj0];
        bB[1] = *(const unsigned long long*)&gB[i * 64 + jj0 + 2];
#pragma unroll
        for (int q = 0; q < 4; q++) {
            unsigned long long a2 = pack_dup(a[q]);
            fma2(r1[q][0], a2, bA[0]);
            fma2(r1[q][1], a2, bA[1]);
            fma2(r2[q][0], a2, bB[0]);
            fma2(r2[q][1], a2, bB[1]);
        }
    }

    const int pidx = b * 8 + chunk;
    float* d1 = g_gw_part + ((size_t)(0 * NH + head) * 128 + pidx) * 4096;
    float* d2 = g_gw_part + ((size_t)(1 * NH + head) * 128 + pidx) * 4096;
#pragma unroll
    for (int q = 0; q < 4; q++) {
        float2 p;
        p = unpack2(r1[q][0]); *(float2*)&d1[(k0 + q) * 64 + jj0]     = p;
        p = unpack2(r1[q][1]); *(float2*)&d1[(k0 + q) * 64 + jj0 + 2] = p;
        p = unpack2(r2[q][0]); *(float2*)&d2[(k0 + q) * 64 + jj0]     = p;
        p = unpack2(r2[q][1]); *(float2*)&d2[(k0 + q) * 64 + jj0 + 2] = p;
    }
}

// ---------------- TTT forward kernel (writes bf16 hi/lo directly) ----------------
__global__ __launch_bounds__(256) void ttt_fwd_kernel()
{
    extern __shared__ float sm_f[];
    float* w1s = sm_f;
    float* w2s = sm_f + 4096;
    float* q1t = sm_f + 8192;

    const int tid   = threadIdx.x;
    const int chunk = blockIdx.x;
    const int head  = blockIdx.y;
    const int b     = blockIdx.z;
    const int n0    = chunk * 128;

    for (int e = tid * 4; e < 4096; e += 1024) {
        *(float4*)&w1s[e] = *(const float4*)&g_mw1[head * 4096 + e];
        *(float4*)&w2s[e] = *(const float4*)&g_mw2[head * 4096 + e];
    }
    {
        const float* src = g_qkv + (size_t)(b * N_ + n0) * QC + head * HD_;
        int i  = tid >> 4;
        int k4 = (tid & 15) * 4;
        for (int p = 0; p < 8; p++, i += 16) {
            float4 v = *(const float4*)(src + (size_t)i * QC + k4);
            q1t[(k4 + 0) * 132 + i] = v.x;
            q1t[(k4 + 1) * 132 + i] = v.y;
            q1t[(k4 + 2) * 132 + i] = v.z;
            q1t[(k4 + 3) * 132 + i] = v.w;
        }
    }
    __syncthreads();

    const int ty = tid >> 4, tx = tid & 15;
    const int i0 = ty * 8, j0 = tx * 4;
    unsigned long long accA2[8][2], accB2[8][2];
#pragma unroll
    for (int i = 0; i < 8; i++)
#pragma unroll
        for (int j = 0; j < 2; j++) { accA2[i][j] = 0ULL; accB2[i][j] = 0ULL; }

#pragma unroll 8
    for (int kk = 0; kk < 64; kk++) {
        float a[8];
        *(float4*)&a[0] = *(float4*)&q1t[kk * 132 + i0];
        *(float4*)&a[4] = *(float4*)&q1t[kk * 132 + i0 + 4];
        unsigned long long b1[2], b2[2];
        b1[0] = *(const unsigned long long*)&w1s[kk * 64 + j0];
        b1[1] = *(const unsigned long long*)&w1s[kk * 64 + j0 + 2];
        b2[0] = *(const unsigned long long*)&w2s[kk * 64 + j0];
        b2[1] = *(const unsigned long long*)&w2s[kk * 64 + j0 + 2];
#pragma unroll
        for (int i = 0; i < 8; i++) {
            unsigned long long a2 = pack_dup(a[i]);
            fma2(accA2[i][0], a2, b1[0]);
            fma2(accA2[i][1], a2, b1[1]);
            fma2(accB2[i][0], a2, b2[0]);
            fma2(accB2[i][1], a2, b2[1]);
        }
    }

#pragma unroll
    for (int i = 0; i < 8; i++) {
        float Aarr[4], Barr[4];
        float2 tt;
        tt = unpack2(accA2[i][0]); Aarr[0] = tt.x; Aarr[1] = tt.y;
        tt = unpack2(accA2[i][1]); Aarr[2] = tt.x; Aarr[3] = tt.y;
        tt = unpack2(accB2[i][0]); Barr[0] = tt.x; Barr[1] = tt.y;
        tt = unpack2(accB2[i][1]); Barr[2] = tt.x; Barr[3] = tt.y;
        float out[4];
#pragma unroll
        for (int j = 0; j < 4; j++) {
            float sig = 1.f / (1.f + expf(-Barr[j]));
            out[j] = Aarr[j] * (Barr[j] * sig);
        }
        __nv_bfloat16 h0 = __float2bfloat16(out[0]), h1 = __float2bfloat16(out[1]);
        __nv_bfloat16 h2 = __float2bfloat16(out[2]), h3 = __float2bfloat16(out[3]);
        __nv_bfloat16 l0 = __float2bfloat16(out[0] - __bfloat162float(h0));
        __nv_bfloat16 l1 = __float2bfloat16(out[1] - __bfloat162float(h1));
        __nv_bfloat16 l2 = __float2bfloat16(out[2] - __bfloat162float(h2));
        __nv_bfloat16 l3 = __float2bfloat16(out[3] - __bfloat162float(h3));
        uint2 hh, ll;
        hh.x = pack_bf2(h0, h1); hh.y = pack_bf2(h2, h3);
        ll.x = pack_bf2(l0, l1); ll.y = pack_bf2(l2, l3);
        const size_t idx = (size_t)(b * N_ + n0 + i0 + i) * XC + head * HD_ + j0;
        *(uint2*)(g_xch + idx) = hh;
        *(uint2*)(g_xcl + idx) = ll;
    }
}

// ---------------- conv grad ----------------
__global__ __launch_bounds__(256) void conv_grad_kernel(const float* __restrict__ w3g)
{
    const int bc = blockIdx.x;
    const int b = bc >> 6, c = bc & 63;
    const int tid = threadIdx.x;
    __shared__ float k2s[32][33];
    __shared__ float wk[9];
    __shared__ float red[256];

    if (tid < 9) wk[tid] = w3g[c * 9 + tid];
    const float* base = g_qkv + (size_t)(b * N_) * QC;
    for (int p = tid; p < 1024; p += 256)
        k2s[p >> 5][p & 31] = base[(size_t)p * QC + 2368 + c];
    __syncthreads();

    float acc[9];
#pragma unroll
    for (int q = 0; q < 9; q++) acc[q] = 0.f;

    for (int p = tid; p < 1024; p += 256) {
        const int y = p >> 5, x = p & 31;
        float t[9];
#pragma unroll
        for (int dy = 0; dy < 3; dy++)
#pragma unroll
            for (int dx = 0; dx < 3; dx++) {
                int yy = y + dy - 1, xx = x + dx - 1;
                t[dy * 3 + dx] = (yy >= 0 && yy < 32 && xx >= 0 && xx < 32)
                                 ? k2s[yy][xx] : 0.f;
            }
        float f = 0.f;
#pragma unroll
        for (int q = 0; q < 9; q++) f = fmaf(wk[q], t[q], f);
        float v = base[(size_t)p * QC + 2432 + c];
        float g = (f - v) * M2_INV;
#pragma unroll
        for (int q = 0; q < 9; q++) acc[q] = fmaf(g, t[q], acc[q]);
    }

    for (int q = 0; q < 9; q++) {
        red[tid] = acc[q];
        __syncthreads();
        for (int s = 128; s > 0; s >>= 1) {
            if (tid < s) red[tid] += red[tid + s];
            __syncthreads();
        }
        if (tid == 0) g_gw3_part[(size_t)bc * 9 + q] = red[0];
        __syncthreads();
    }
}

__global__ void conv_grad_reduce_kernel()
{
    const int tid = threadIdx.x;
    __shared__ float red[576];
    float s = 0.f;
    const int c = tid / 9, q = tid % 9;
    for (int b = 0; b < B_; b++) s += g_gw3_part[(size_t)(b * 64 + c) * 9 + q];
    g_gw3[tid] = s;
    red[tid] = s * s;
    __syncthreads();
    if (tid < 64) red[tid] += red[tid + 512];
    __syncthreads();
    for (int st = 256; st > 0; st >>= 1) {
        if (tid < st && tid + st < 576) red[tid] += red[tid + st];
        __syncthreads();
    }
    if (tid == 0) g_sumsq[24] = red[0];
}

// ---------------- two-stage gw reduce ----------------
__global__ __launch_bounds__(256) void reduce_gw_stage1()
{
    const int th = blockIdx.x >> 3;
    const int g  = blockIdx.x & 7;
    const int tid = threadIdx.x;
    const float* src = g_gw_part + ((size_t)th * 128 + g * 16) * 4096;
    float s[16];
#pragma unroll
    for (int q = 0; q < 16; q++) s[q] = 0.f;
    for (int p = 0; p < 16; p++) {
        const float* row = src + (size_t)p * 4096 + tid;
#pragma unroll
        for (int q = 0; q < 16; q++) s[q] += row[q * 256];
    }
    float* dst = g_gw_stage + (size_t)(th * 8 + g) * 4096 + tid;
#pragma unroll
    for (int q = 0; q < 16; q++) dst[q * 256] = s[q];
}

__global__ __launch_bounds__(256) void reduce_gw_stage2()
{
    const int th  = blockIdx.x;
    const int tid = threadIdx.x;
    const float* src = g_gw_stage + (size_t)th * 8 * 4096;
    float* dst = g_gw + (size_t)th * 4096;

    float s[16];
#pragma unroll
    for (int q = 0; q < 16; q++) s[q] = 0.f;
    for (int p = 0; p < 8; p++) {
        const float* row = src + (size_t)p * 4096 + tid;
#pragma unroll
        for (int q = 0; q < 16; q++) s[q] += row[q * 256];
    }
    float ss = 0.f;
#pragma unroll
    for (int q = 0; q < 16; q++) { dst[tid + q * 256] = s[q]; ss += s[q] * s[q]; }

    __shared__ float red[256];
    red[tid] = ss;
    __syncthreads();
    for (int st = 128; st > 0; st >>= 1) {
        if (tid < st) red[tid] += red[tid + st];
        __syncthreads();
    }
    if (tid == 0) g_sumsq[th] = red[0];
}

// ---------------- weight update (scales fused) ----------------
__global__ void update_w_kernel(const float* __restrict__ w1g,
                                const float* __restrict__ w2g,
                                const float* __restrict__ w3g)
{
    __shared__ float sc[3];
    if (threadIdx.x == 0) {
        float s1 = 0.f, s2 = 0.f;
        for (int h = 0; h < NH; h++) { s1 += g_sumsq[h]; s2 += g_sumsq[NH + h]; }
        sc[0] = LR_ / (sqrtf(s1) + 1.f);
        sc[1] = LR_ / (sqrtf(s2) + 1.f);
        sc[2] = LR_ / (sqrtf(g_sumsq[24]) + 1.f);
    }
    __syncthreads();
    const int i = blockIdx.x * 256 + threadIdx.x;
    if (i < 49152) {
        g_mw1[i] = w1g[i] - sc[0] * g_gw[i];
    } else if (i < 98304) {
        const int k = i - 49152;
        g_mw2[k] = w2g[k] - sc[1] * g_gw[49152 + k];
    } else if (i < 98880) {
        const int k = i - 98304;
        g_mw3[k] = w3g[k] - sc[2] * g_gw3[k];
    }
}

// ---------------- conv forward (writes bf16 hi/lo directly) ----------------
__global__ __launch_bounds__(256) void conv_fwd_kernel()
{
    const int bc = blockIdx.x;
    const int b = bc >> 6, c = bc & 63;
    const int tid = threadIdx.x;
    __shared__ float q2s[32][33];
    __shared__ float wk[9];
    if (tid < 9) wk[tid] = g_mw3[c * 9 + tid];
    const float* base = g_qkv + (size_t)(b * N_) * QC;
    for (int p = tid; p < 1024; p += 256)
        q2s[p >> 5][p & 31] = base[(size_t)p * QC + 2304 + c];
    __syncthreads();

    for (int p = tid; p < 1024; p += 256) {
        const int y = p >> 5, x = p & 31;
        float f = 0.f;
#pragma unroll
        for (int dy = 0; dy < 3; dy++)
#pragma unroll
            for (int dx = 0; dx < 3; dx++) {
                int yy = y + dy - 1, xx = x + dx - 1;
                if (yy >= 0 && yy < 32 && xx >= 0 && xx < 32)
                    f = fmaf(wk[dy * 3 + dx], q2s[yy][xx], f);
            }
        __nv_bfloat16 h = __float2bfloat16(f);
        __nv_bfloat16 l = __float2bfloat16(f - __bfloat162float(h));
        const size_t idx = (size_t)(b * N_ + p) * XC + 768 + c;
        g_xch[idx] = h;
        g_xcl[idx] = l;
    }
}

// ---------------- launch ----------------
extern "C" void kernel_launch(void* const* d_in, const int* in_sizes, int n_in,
                              void* d_out, int out_size)
{
    const float *x = nullptr, *Wqkv = nullptr, *bqkv = nullptr, *w1 = nullptr,
                *w2 = nullptr, *w3 = nullptr, *Wproj = nullptr, *bproj = nullptr;
    for (int i = 0; i < n_in; i++) {
        const int s = in_sizes[i];
        const float* p = (const float*)d_in[i];
        if      (s == B_*N_*C_)   x = p;
        else if (s == C_*QC)      Wqkv = p;
        else if (s == QC)         bqkv = p;
        else if (s == NH*HD_*HD_) { if (!w1) w1 = p; else w2 = p; }
        else if (s == 64*9)       w3 = p;
        else if (s == XC*C_)      Wproj = p;
        else if (s == C_)         bproj = p;
    }

    float* qkv_ptr = nullptr;
    __nv_bfloat16 *xh, *xl, *xch, *xcl, *wqh, *wql, *wph, *wpl;
    cudaGetSymbolAddress((void**)&qkv_ptr,  g_qkv);
    cudaGetSymbolAddress((void**)&xh,  g_xh);
    cudaGetSymbolAddress((void**)&xl,  g_xl);
    cudaGetSymbolAddress((void**)&xch, g_xch);
    cudaGetSymbolAddress((void**)&xcl, g_xcl);
    cudaGetSymbolAddress((void**)&wqh, g_wqh);
    cudaGetSymbolAddress((void**)&wql, g_wql);
    cudaGetSymbolAddress((void**)&wph, g_wph);
    cudaGetSymbolAddress((void**)&wpl, g_wpl);

    cudaFuncSetAttribute(ttt_grad_kernel,
        cudaFuncAttributeMaxDynamicSharedMemorySize, 132096);
    cudaFuncSetAttribute(ttt_fwd_kernel,
        cudaFuncAttributeMaxDynamicSharedMemorySize, 66560);
    cudaFuncSetAttribute(tc_gemm,
        cudaFuncAttributeMaxDynamicSharedMemorySize, TCG_SMEM);

    // 1. split x, transpose+split weights
    split_convert<<<(B_*N_*C_/4 + 255)/256, 256>>>(x, xh, xl, B_*N_*C_/4);
    transpose_split<<<dim3(QC/32, C_/32), 256>>>(Wqkv, wqh, wql, C_, QC);
    transpose_split<<<dim3(C_/32, XC/32), 256>>>(Wproj, wph, wpl, XC, C_);

    // 2. qkv = x @ Wqkv + bqkv  (HMMA, 3-term bf16 split)
    tc_gemm<<<dim3((QC + 127)/128, (B_*N_)/128), 128, TCG_SMEM>>>(
        xh, xl, wqh, wql, bqkv, qkv_ptr, QC, C_);

    // 3. TTT + conv gradients, reduce, update (scales fused)
    ttt_grad_kernel<<<dim3(8, NH, B_), 256, 132096>>>(w1, w2);
    conv_grad_kernel<<<B_ * 64, 256>>>(w3);
    conv_grad_reduce_kernel<<<1, 576>>>();
    reduce_gw_stage1<<<192, 256>>>();
    reduce_gw_stage2<<<24, 256>>>();
    update_w_kernel<<<(98880 + 255)/256, 256>>>(w1, w2, w3);

    // 4. post-update forward (writes bf16 splits directly)
    ttt_fwd_kernel<<<dim3(8, NH, B_), 256, 66560>>>();
    conv_fwd_kernel<<<B_ * 64, 256>>>();

    // 5. proj GEMM
    tc_gemm<<<dim3(C_/128, (B_*N_)/128), 128, TCG_SMEM>>>(
        xch, xcl, wph, wpl, bproj, (float*)d_out, C_, XC);
}

// round 10
// speedup vs baseline: 1.2500x; 1.2272x over previous
#include <cuda_runtime.h>
#include <cuda_bf16.h>
#include <cuda_fp16.h>
#include <cstdint>
#include <cstdio>
#include <math.h>

#define B_  16
#define N_  1024
#define C_  768
#define NH  12
#define HD_ 64
#define QC  2496   // 3*768 + 3*64
#define XC  832    // 768 + 64
#define M1_INV (1.0f/12582912.0f)
#define M2_INV (1.0f/1048576.0f)
#define LR_ 0.001f

// ---------------- scratch ----------------
__device__ float g_qkv[B_*N_*QC];
__device__ float g_gw_part[2*NH*128*HD_*HD_];
__device__ float g_gw_stage[24*8*HD_*HD_];
__device__ float g_gw[2*NH*HD_*HD_];
__device__ float g_gw3_part[B_*64*9];
__device__ float g_gw3[64*9];
__device__ float g_sumsq[25];
__device__ float g_mw1[NH*HD_*HD_];
__device__ float g_mw2[NH*HD_*HD_];
__device__ float g_mw3[64*9];
// fp16 operands: activations hi-only; weights hi/lo split
__device__ __half g_xh[B_*N_*C_];
__device__ __half g_xch[B_*N_*XC];
__device__ __half g_wqh[QC*C_], g_wql[QC*C_];   // [N=2496][K=768]
__device__ __half g_wph[C_*XC], g_wpl[C_*XC];   // [N=768][K=832]

// ---------------- PTX helpers ----------------
__device__ __forceinline__ unsigned int smem_to_u32(const void* smem_ptr) {
    unsigned int addr;
    asm("{ .reg .u64 tmp; cvta.to.shared.u64 tmp, %1; cvt.u32.u64 %0, tmp; }"
        : "=r"(addr) : "l"(smem_ptr));
    return addr;
}
__device__ __forceinline__ void cp_async16(unsigned int saddr, const void* gaddr) {
    asm volatile("cp.async.cg.shared.global [%0], [%1], 16;"
                 :: "r"(saddr), "l"(gaddr) : "memory");
}
__device__ __forceinline__ void cp_commit() {
    asm volatile("cp.async.commit_group;" ::: "memory");
}
__device__ __forceinline__ void cp_wait1() {
    asm volatile("cp.async.wait_group 1;" ::: "memory");
}
__device__ __forceinline__ void cp_wait0() {
    asm volatile("cp.async.wait_group 0;" ::: "memory");
}
__device__ __forceinline__ void ldm_x4(unsigned int& r0, unsigned int& r1,
                                       unsigned int& r2, unsigned int& r3,
                                       unsigned int a) {
    asm volatile("ldmatrix.sync.aligned.m8n8.x4.shared.b16 {%0,%1,%2,%3}, [%4];"
                 : "=r"(r0), "=r"(r1), "=r"(r2), "=r"(r3) : "r"(a));
}
__device__ __forceinline__ void mma_f16(float& c0, float& c1, float& c2, float& c3,
                                        unsigned int a0, unsigned int a1,
                                        unsigned int a2, unsigned int a3,
                                        unsigned int b0, unsigned int b1) {
    asm volatile("mma.sync.aligned.m16n8k16.row.col.f32.f16.f16.f32 "
                 "{%0,%1,%2,%3}, {%4,%5,%6,%7}, {%8,%9}, {%0,%1,%2,%3};"
                 : "+f"(c0), "+f"(c1), "+f"(c2), "+f"(c3)
                 : "r"(a0), "r"(a1), "r"(a2), "r"(a3), "r"(b0), "r"(b1));
}

// ---------------- conversions ----------------
__device__ __forceinline__ unsigned int pack_h2(__half a, __half b) {
    return (unsigned int)__half_as_ushort(a) |
           ((unsigned int)__half_as_ushort(b) << 16);
}
// x (fp32) -> fp16 hi only
__global__ __launch_bounds__(256) void convert_f16(
    const float* __restrict__ X, __half* __restrict__ H, int n4)
{
    int i = blockIdx.x * 256 + threadIdx.x;
    if (i >= n4) return;
    float4 v = ((const float4*)X)[i];
    uint2 hh;
    hh.x = pack_h2(__float2half(v.x), __float2half(v.y));
    hh.y = pack_h2(__float2half(v.z), __float2half(v.w));
    ((uint2*)H)[i] = hh;
}
// W[K][N] -> T[N][K] split into fp16 hi/lo
__global__ __launch_bounds__(256) void transpose_split(
    const float* __restrict__ W, __half* __restrict__ Th,
    __half* __restrict__ Tl, int K, int N)
{
    __shared__ float s[32][33];
    const int n0 = blockIdx.x * 32, k0 = blockIdx.y * 32;
    const int tx = threadIdx.x & 31, ty = threadIdx.x >> 5;
    for (int r = ty; r < 32; r += 8)
        s[r][tx] = W[(size_t)(k0 + r) * N + n0 + tx];
    __syncthreads();
    for (int r = ty; r < 32; r += 8) {
        float v = s[tx][r];
        __half h = __float2half(v);
        Th[(size_t)(n0 + r) * K + k0 + tx] = h;
        Tl[(size_t)(n0 + r) * K + k0 + tx] = __float2half(v - __half2float(h));
    }
}

// ---------------- HMMA GEMM: C = A @ Bt^T + bias (fp16, 2-term weight split) ----
// D = Ah*Bh + Ah*Bl. 128x128 block, BK=32, 8 warps (64x32 each),
// cp.async.cg double buffering, R7 issue-then-wait pipeline.
#define SROW   40
#define ARR_B  (128*SROW*2)       // 10240 bytes per array
#define STG_B  (3*ARR_B)          // 30720 bytes per stage (Ah, Bh, Bl)
#define TCG_SMEM (2*STG_B)        // 61440

__global__ __launch_bounds__(256) void tc_gemm(
    const __half* __restrict__ Ah,
    const __half* __restrict__ Bh, const __half* __restrict__ Bl,
    const float* __restrict__ bias, float* __restrict__ C,
    int Nfull, int K)
{
    extern __shared__ __half smb[];
    const unsigned int smem_u = smem_to_u32(smb);
    const int t = threadIdx.x, lane = t & 31, wid = t >> 5;
    const int m0 = blockIdx.y * 128, n0 = blockIdx.x * 128;
    const int wm = (wid >> 2) * 64, wn = (wid & 3) * 32;

    float acc[4][4][4];
#pragma unroll
    for (int a = 0; a < 4; a++)
#pragma unroll
        for (int b = 0; b < 4; b++)
#pragma unroll
            for (int c = 0; c < 4; c++) acc[a][b][c] = 0.f;

    // ---- load plan: 1536 16B-chunks per stage, 6 per thread ----
    const __half* gp[6];
    unsigned int soff[6];
    bool vld[6];
#pragma unroll
    for (int p = 0; p < 6; p++) {
        int c = p * 256 + t;
        int arr = c >> 9, rem = c & 511, row = rem >> 2, c4 = rem & 3;
        const __half* base = (arr == 0) ? Ah : (arr == 1) ? Bh : Bl;
        int grow = (arr == 0) ? (m0 + row) : (n0 + row);
        vld[p]  = (arr == 0) || ((n0 + row) < Nfull);
        if (!vld[p]) grow = 0;
        gp[p]   = base + (size_t)grow * K + c4 * 8;
        soff[p] = (unsigned int)(arr * ARR_B + (row * SROW + c4 * 8) * 2);
    }

#define ISSUE(stg, ks) do {                                             \
        unsigned int _sb = smem_u + (unsigned int)(stg) * STG_B;        \
        _Pragma("unroll")                                               \
        for (int p = 0; p < 6; p++)                                     \
            if (vld[p]) cp_async16(_sb + soff[p], gp[p] + (ks) * 32);   \
        cp_commit();                                                    \
    } while (0)

    const int nk = K / 32;
    ISSUE(0, 0);

    for (int s = 0; s < nk; s++) {
        if (s + 1 < nk) { ISSUE((s + 1) & 1, s + 1); cp_wait1(); }
        else            { cp_wait0(); }
        __syncthreads();

        const unsigned int sb = smem_u + (unsigned int)(s & 1) * STG_B;
#pragma unroll
        for (int kc = 0; kc < 32; kc += 16) {
            // B fragments (hi & lo): 4 n-tiles of n8k16
            unsigned int bh[4][2], bl[4][2];
#pragma unroll
            for (int q = 0; q < 2; q++) {
                unsigned int brow = (unsigned int)(wn + q * 16 + (lane & 7) +
                                                   ((lane >> 4) << 3));
                unsigned int koff = (unsigned int)(((lane >> 3) & 1) * 8);
                unsigned int ab = sb + 1u * ARR_B + (brow * SROW + kc + koff) * 2;
                ldm_x4(bh[2*q][0], bh[2*q][1], bh[2*q+1][0], bh[2*q+1][1], ab);
                ldm_x4(bl[2*q][0], bl[2*q][1], bl[2*q+1][0], bl[2*q+1][1],
                       ab + ARR_B);
            }
#pragma unroll
            for (int mt = 0; mt < 4; mt++) {
                unsigned int arow = (unsigned int)(wm + mt * 16 + (lane & 15));
                unsigned int koff = (unsigned int)((lane >> 4) * 8);
                unsigned int aa = sb + (arow * SROW + kc + koff) * 2;
                unsigned int a0, a1, a2, a3;
                ldm_x4(a0, a1, a2, a3, aa);
#pragma unroll
                for (int nt = 0; nt < 4; nt++) {
                    mma_f16(acc[mt][nt][0], acc[mt][nt][1],
                            acc[mt][nt][2], acc[mt][nt][3],
                            a0, a1, a2, a3, bh[nt][0], bh[nt][1]);
                    mma_f16(acc[mt][nt][0], acc[mt][nt][1],
                            acc[mt][nt][2], acc[mt][nt][3],
                            a0, a1, a2, a3, bl[nt][0], bl[nt][1]);
                }
            }
        }
        __syncthreads();
    }
#undef ISSUE

    // ---- epilogue ----
    const int g = lane >> 2, tq = lane & 3;
#pragma unroll
    for (int mt = 0; mt < 4; mt++) {
        const int row = m0 + wm + mt * 16 + g;
#pragma unroll
        for (int nt = 0; nt < 4; nt++) {
            const int col = n0 + wn + nt * 8 + tq * 2;
            if (col < Nfull) {
                float b0 = bias[col], b1 = bias[col + 1];
                float2 o1; o1.x = acc[mt][nt][0] + b0; o1.y = acc[mt][nt][1] + b1;
                float2 o2v; o2v.x = acc[mt][nt][2] + b0; o2v.y = acc[mt][nt][3] + b1;
                *(float2*)(C + (size_t)row * Nfull + col) = o1;
                *(float2*)(C + (size_t)(row + 8) * Nfull + col) = o2v;
            }
        }
    }
}

// ---------------- packed f32x2 helpers ----------------
__device__ __forceinline__ unsigned long long pack_dup(float x) {
    unsigned long long d;
    asm("mov.b64 %0, {%1, %1};" : "=l"(d) : "f"(x));
    return d;
}
__device__ __forceinline__ void fma2(unsigned long long &d,
                                     unsigned long long a, unsigned long long b) {
    asm("fma.rn.f32x2 %0, %1, %2, %0;" : "+l"(d) : "l"(a), "l"(b));
}
__device__ __forceinline__ float2 unpack2(unsigned long long v) {
    float lo, hi;
    asm("mov.b64 {%0, %1}, %2;" : "=f"(lo), "=f"(hi) : "l"(v));
    return make_float2(lo, hi);
}

// ---------------- TTT gradient kernel ----------------
__global__ __launch_bounds__(256) void ttt_grad_kernel(
    const float* __restrict__ w1g, const float* __restrict__ w2g)
{
    extern __shared__ float sm_f[];
    float* w1s = sm_f;
    float* w2s = sm_f + 4096;
    float* k1t = sm_f + 8192;
    float* gA  = sm_f + 8192 + 64 * 132;
    float* gB  = gA + 128 * 64;

    const int tid   = threadIdx.x;
    const int chunk = blockIdx.x;
    const int head  = blockIdx.y;
    const int b     = blockIdx.z;
    const int n0    = chunk * 128;

    for (int e = tid * 4; e < 4096; e += 1024) {
        *(float4*)&w1s[e] = *(const float4*)&w1g[head * 4096 + e];
        *(float4*)&w2s[e] = *(const float4*)&w2g[head * 4096 + e];
    }
    {
        const float* src = g_qkv + (size_t)(b * N_ + n0) * QC + C_ + head * HD_;
        int i  = tid >> 4;
        int k4 = (tid & 15) * 4;
        for (int p = 0; p < 8; p++, i += 16) {
            float4 v = *(const float4*)(src + (size_t)i * QC + k4);
            k1t[(k4 + 0) * 132 + i] = v.x;
            k1t[(k4 + 1) * 132 + i] = v.y;
            k1t[(k4 + 2) * 132 + i] = v.z;
            k1t[(k4 + 3) * 132 + i] = v.w;
        }
    }
    __syncthreads();

    const int ty = tid >> 4, tx = tid & 15;
    const int i0 = ty * 8, j0 = tx * 4;
    unsigned long long accA2[8][2], accB2[8][2];
#pragma unroll
    for (int i = 0; i < 8; i++)
#pragma unroll
        for (int j = 0; j < 2; j++) { accA2[i][j] = 0ULL; accB2[i][j] = 0ULL; }

#pragma unroll 8
    for (int kk = 0; kk < 64; kk++) {
        float a[8];
        *(float4*)&a[0] = *(float4*)&k1t[kk * 132 + i0];
        *(float4*)&a[4] = *(float4*)&k1t[kk * 132 + i0 + 4];
        unsigned long long b1[2], b2[2];
        b1[0] = *(const unsigned long long*)&w1s[kk * 64 + j0];
        b1[1] = *(const unsigned long long*)&w1s[kk * 64 + j0 + 2];
        b2[0] = *(const unsigned long long*)&w2s[kk * 64 + j0];
        b2[1] = *(const unsigned long long*)&w2s[kk * 64 + j0 + 2];
#pragma unroll
        for (int i = 0; i < 8; i++) {
            unsigned long long a2 = pack_dup(a[i]);
            fma2(accA2[i][0], a2, b1[0]);
            fma2(accA2[i][1], a2, b1[1]);
            fma2(accB2[i][0], a2, b2[0]);
            fma2(accB2[i][1], a2, b2[1]);
        }
    }

    const float* v1p = g_qkv + (size_t)(b * N_ + n0 + i0) * QC + 2 * C_ + head * HD_ + j0;
#pragma unroll
    for (int i = 0; i < 8; i++) {
        float4 vv = *(const float4*)(v1p + (size_t)i * QC);
        float v[4] = {vv.x, vv.y, vv.z, vv.w};
        float Aarr[4], Barr[4];
        float2 tt;
        tt = unpack2(accA2[i][0]); Aarr[0] = tt.x; Aarr[1] = tt.y;
        tt = unpack2(accA2[i][1]); Aarr[2] = tt.x; Aarr[3] = tt.y;
        tt = unpack2(accB2[i][0]); Barr[0] = tt.x; Barr[1] = tt.y;
        tt = unpack2(accB2[i][1]); Barr[2] = tt.x; Barr[3] = tt.y;
#pragma unroll
        for (int j = 0; j < 4; j++) {
            float Av = Aarr[j], Bv = Barr[j];
            float sig = 1.f / (1.f + expf(-Bv));
            float sil = Bv * sig;
            float g   = (Av * sil - v[j]) * M1_INV;
            gA[(i0 + i) * 64 + j0 + j] = g * sil;
            gB[(i0 + i) * 64 + j0 + j] = g * Av * sig * (1.f + Bv * (1.f - sig));
        }
    }
    __syncthreads();

    const int k0 = ty * 4, jj0 = tx * 4;
    unsigned long long r1[4][2], r2[4][2];
#pragma unroll
    for (int q = 0; q < 4; q++)
#pragma unroll
        for (int r = 0; r < 2; r++) { r1[q][r] = 0ULL; r2[q][r] = 0ULL; }

#pragma unroll 4
    for (int i = 0; i < 128; i++) {
        float a[4];
#pragma unroll
        for (int q = 0; q < 4; q++) a[q] = k1t[(k0 + q) * 132 + i];
        unsigned long long bA[2], bB[2];
        bA[0] = *(const unsigned long long*)&gA[i * 64 + jj0];
        bA[1] = *(const unsigned long long*)&gA[i * 64 + jj0 + 2];
        bB[0] = *(const unsigned long long*)&gB[i * 64 + jj0];
        bB[1] = *(const unsigned long long*)&gB[i * 64 + jj0 + 2];
#pragma unroll
        for (int q = 0; q < 4; q++) {
            unsigned long long a2 = pack_dup(a[q]);
            fma2(r1[q][0], a2, bA[0]);
            fma2(r1[q][1], a2, bA[1]);
            fma2(r2[q][0], a2, bB[0]);
            fma2(r2[q][1], a2, bB[1]);
        }
    }

    const int pidx = b * 8 + chunk;
    float* d1 = g_gw_part + ((size_t)(0 * NH + head) * 128 + pidx) * 4096;
    float* d2 = g_gw_part + ((size_t)(1 * NH + head) * 128 + pidx) * 4096;
#pragma unroll
    for (int q = 0; q < 4; q++) {
        float2 p;
        p = unpack2(r1[q][0]); *(float2*)&d1[(k0 + q) * 64 + jj0]     = p;
        p = unpack2(r1[q][1]); *(float2*)&d1[(k0 + q) * 64 + jj0 + 2] = p;
        p = unpack2(r2[q][0]); *(float2*)&d2[(k0 + q) * 64 + jj0]     = p;
        p = unpack2(r2[q][1]); *(float2*)&d2[(k0 + q) * 64 + jj0 + 2] = p;
    }
}

// ---------------- TTT forward kernel (writes fp16 hi directly) ----------------
__global__ __launch_bounds__(256) void ttt_fwd_kernel()
{
    extern __shared__ float sm_f[];
    float* w1s = sm_f;
    float* w2s = sm_f + 4096;
    float* q1t = sm_f + 8192;

    const int tid   = threadIdx.x;
    const int chunk = blockIdx.x;
    const int head  = blockIdx.y;
    const int b     = blockIdx.z;
    const int n0    = chunk * 128;

    for (int e = tid * 4; e < 4096; e += 1024) {
        *(float4*)&w1s[e] = *(const float4*)&g_mw1[head * 4096 + e];
        *(float4*)&w2s[e] = *(const float4*)&g_mw2[head * 4096 + e];
    }
    {
        const float* src = g_qkv + (size_t)(b * N_ + n0) * QC + head * HD_;
        int i  = tid >> 4;
        int k4 = (tid & 15) * 4;
        for (int p = 0; p < 8; p++, i += 16) {
            float4 v = *(const float4*)(src + (size_t)i * QC + k4);
            q1t[(k4 + 0) * 132 + i] = v.x;
            q1t[(k4 + 1) * 132 + i] = v.y;
            q1t[(k4 + 2) * 132 + i] = v.z;
            q1t[(k4 + 3) * 132 + i] = v.w;
        }
    }
    __syncthreads();

    const int ty = tid >> 4, tx = tid & 15;
    const int i0 = ty * 8, j0 = tx * 4;
    unsigned long long accA2[8][2], accB2[8][2];
#pragma unroll
    for (int i = 0; i < 8; i++)
#pragma unroll
        for (int j = 0; j < 2; j++) { accA2[i][j] = 0ULL; accB2[i][j] = 0ULL; }

#pragma unroll 8
    for (int kk = 0; kk < 64; kk++) {
        float a[8];
        *(float4*)&a[0] = *(float4*)&q1t[kk * 132 + i0];
        *(float4*)&a[4] = *(float4*)&q1t[kk * 132 + i0 + 4];
        unsigned long long b1[2], b2[2];
        b1[0] = *(const unsigned long long*)&w1s[kk * 64 + j0];
        b1[1] = *(const unsigned long long*)&w1s[kk * 64 + j0 + 2];
        b2[0] = *(const unsigned long long*)&w2s[kk * 64 + j0];
        b2[1] = *(const unsigned long long*)&w2s[kk * 64 + j0 + 2];
#pragma unroll
        for (int i = 0; i < 8; i++) {
            unsigned long long a2 = pack_dup(a[i]);
            fma2(accA2[i][0], a2, b1[0]);
            fma2(accA2[i][1], a2, b1[1]);
            fma2(accB2[i][0], a2, b2[0]);
            fma2(accB2[i][1], a2, b2[1]);
        }
    }

#pragma unroll
    for (int i = 0; i < 8; i++) {
        float Aarr[4], Barr[4];
        float2 tt;
        tt = unpack2(accA2[i][0]); Aarr[0] = tt.x; Aarr[1] = tt.y;
        tt = unpack2(accA2[i][1]); Aarr[2] = tt.x; Aarr[3] = tt.y;
        tt = unpack2(accB2[i][0]); Barr[0] = tt.x; Barr[1] = tt.y;
        tt = unpack2(accB2[i][1]); Barr[2] = tt.x; Barr[3] = tt.y;
        float out[4];
#pragma unroll
        for (int j = 0; j < 4; j++) {
            float sig = 1.f / (1.f + expf(-Barr[j]));
            out[j] = Aarr[j] * (Barr[j] * sig);
        }
        uint2 hh;
        hh.x = pack_h2(__float2half(out[0]), __float2half(out[1]));
        hh.y = pack_h2(__float2half(out[2]), __float2half(out[3]));
        const size_t idx = (size_t)(b * N_ + n0 + i0 + i) * XC + head * HD_ + j0;
        *(uint2*)(g_xch + idx) = hh;
    }
}

// ---------------- conv grad ----------------
__global__ __launch_bounds__(256) void conv_grad_kernel(const float* __restrict__ w3g)
{
    const int bc = blockIdx.x;
    const int b = bc >> 6, c = bc & 63;
    const int tid = threadIdx.x;
    __shared__ float k2s[32][33];
    __shared__ float wk[9];
    __shared__ float red[256];

    if (tid < 9) wk[tid] = w3g[c * 9 + tid];
    const float* base = g_qkv + (size_t)(b * N_) * QC;
    for (int p = tid; p < 1024; p += 256)
        k2s[p >> 5][p & 31] = base[(size_t)p * QC + 2368 + c];
    __syncthreads();

    float acc[9];
#pragma unroll
    for (int q = 0; q < 9; q++) acc[q] = 0.f;

    for (int p = tid; p < 1024; p += 256) {
        const int y = p >> 5, x = p & 31;
        float t[9];
#pragma unroll
        for (int dy = 0; dy < 3; dy++)
#pragma unroll
            for (int dx = 0; dx < 3; dx++) {
                int yy = y + dy - 1, xx = x + dx - 1;
                t[dy * 3 + dx] = (yy >= 0 && yy < 32 && xx >= 0 && xx < 32)
                                 ? k2s[yy][xx] : 0.f;
            }
        float f = 0.f;
#pragma unroll
        for (int q = 0; q < 9; q++) f = fmaf(wk[q], t[q], f);
        float v = base[(size_t)p * QC + 2432 + c];
        float g = (f - v) * M2_INV;
#pragma unroll
        for (int q = 0; q < 9; q++) acc[q] = fmaf(g, t[q], acc[q]);
    }

    for (int q = 0; q < 9; q++) {
        red[tid] = acc[q];
        __syncthreads();
        for (int s = 128; s > 0; s >>= 1) {
            if (tid < s) red[tid] += red[tid + s];
            __syncthreads();
        }
        if (tid == 0) g_gw3_part[(size_t)bc * 9 + q] = red[0];
        __syncthreads();
    }
}

__global__ void conv_grad_reduce_kernel()
{
    const int tid = threadIdx.x;
    __shared__ float red[576];
    float s = 0.f;
    const int c = tid / 9, q = tid % 9;
    for (int b = 0; b < B_; b++) s += g_gw3_part[(size_t)(b * 64 + c) * 9 + q];
    g_gw3[tid] = s;
    red[tid] = s * s;
    __syncthreads();
    if (tid < 64) red[tid] += red[tid + 512];
    __syncthreads();
    for (int st = 256; st > 0; st >>= 1) {
        if (tid < st && tid + st < 576) red[tid] += red[tid + st];
        __syncthreads();
    }
    if (tid == 0) g_sumsq[24] = red[0];
}

// ---------------- two-stage gw reduce ----------------
__global__ __launch_bounds__(256) void reduce_gw_stage1()
{
    const int th = blockIdx.x >> 3;
    const int g  = blockIdx.x & 7;
    const int tid = threadIdx.x;
    const float* src = g_gw_part + ((size_t)th * 128 + g * 16) * 4096;
    float s[16];
#pragma unroll
    for (int q = 0; q < 16; q++) s[q] = 0.f;
    for (int p = 0; p < 16; p++) {
        const float* row = src + (size_t)p * 4096 + tid;
#pragma unroll
        for (int q = 0; q < 16; q++) s[q] += row[q * 256];
    }
    float* dst = g_gw_stage + (size_t)(th * 8 + g) * 4096 + tid;
#pragma unroll
    for (int q = 0; q < 16; q++) dst[q * 256] = s[q];
}

__global__ __launch_bounds__(256) void reduce_gw_stage2()
{
    const int th  = blockIdx.x;
    const int tid = threadIdx.x;
    const float* src = g_gw_stage + (size_t)th * 8 * 4096;
    float* dst = g_gw + (size_t)th * 4096;

    float s[16];
#pragma unroll
    for (int q = 0; q < 16; q++) s[q] = 0.f;
    for (int p = 0; p < 8; p++) {
        const float* row = src + (size_t)p * 4096 + tid;
#pragma unroll
        for (int q = 0; q < 16; q++) s[q] += row[q * 256];
    }
    float ss = 0.f;
#pragma unroll
    for (int q = 0; q < 16; q++) { dst[tid + q * 256] = s[q]; ss += s[q] * s[q]; }

    __shared__ float red[256];
    red[tid] = ss;
    __syncthreads();
    for (int st = 128; st > 0; st >>= 1) {
        if (tid < st) red[tid] += red[tid + st];
        __syncthreads();
    }
    if (tid == 0) g_sumsq[th] = red[0];
}

// ---------------- weight update (scales fused) ----------------
__global__ void update_w_kernel(const float* __restrict__ w1g,
                                const float* __restrict__ w2g,
                                const float* __restrict__ w3g)
{
    __shared__ float sc[3];
    if (threadIdx.x == 0) {
        float s1 = 0.f, s2 = 0.f;
        for (int h = 0; h < NH; h++) { s1 += g_sumsq[h]; s2 += g_sumsq[NH + h]; }
        sc[0] = LR_ / (sqrtf(s1) + 1.f);
        sc[1] = LR_ / (sqrtf(s2) + 1.f);
        sc[2] = LR_ / (sqrtf(g_sumsq[24]) + 1.f);
    }
    __syncthreads();
    const int i = blockIdx.x * 256 + threadIdx.x;
    if (i < 49152) {
        g_mw1[i] = w1g[i] - sc[0] * g_gw[i];
    } else if (i < 98304) {
        const int k = i - 49152;
        g_mw2[k] = w2g[k] - sc[1] * g_gw[49152 + k];
    } else if (i < 98880) {
        const int k = i - 98304;
        g_mw3[k] = w3g[k] - sc[2] * g_gw3[k];
    }
}

// ---------------- conv forward (writes fp16 hi directly) ----------------
__global__ __launch_bounds__(256) void conv_fwd_kernel()
{
    const int bc = blockIdx.x;
    const int b = bc >> 6, c = bc & 63;
    const int tid = threadIdx.x;
    __shared__ float q2s[32][33];
    __shared__ float wk[9];
    if (tid < 9) wk[tid] = g_mw3[c * 9 + tid];
    const float* base = g_qkv + (size_t)(b * N_) * QC;
    for (int p = tid; p < 1024; p += 256)
        q2s[p >> 5][p & 31] = base[(size_t)p * QC + 2304 + c];
    __syncthreads();

    for (int p = tid; p < 1024; p += 256) {
        const int y = p >> 5, x = p & 31;
        float f = 0.f;
#pragma unroll
        for (int dy = 0; dy < 3; dy++)
#pragma unroll
            for (int dx = 0; dx < 3; dx++) {
                int yy = y + dy - 1, xx = x + dx - 1;
                if (yy >= 0 && yy < 32 && xx >= 0 && xx < 32)
                    f = fmaf(wk[dy * 3 + dx], q2s[yy][xx], f);
            }
        g_xch[(size_t)(b * N_ + p) * XC + 768 + c] = __float2half(f);
    }
}

// ---------------- launch ----------------
extern "C" void kernel_launch(void* const* d_in, const int* in_sizes, int n_in,
                              void* d_out, int out_size)
{
    const float *x = nullptr, *Wqkv = nullptr, *bqkv = nullptr, *w1 = nullptr,
                *w2 = nullptr, *w3 = nullptr, *Wproj = nullptr, *bproj = nullptr;
    for (int i = 0; i < n_in; i++) {
        const int s = in_sizes[i];
        const float* p = (const float*)d_in[i];
        if      (s == B_*N_*C_)   x = p;
        else if (s == C_*QC)      Wqkv = p;
        else if (s == QC)         bqkv = p;
        else if (s == NH*HD_*HD_) { if (!w1) w1 = p; else w2 = p; }
        else if (s == 64*9)       w3 = p;
        else if (s == XC*C_)      Wproj = p;
        else if (s == C_)         bproj = p;
    }

    float* qkv_ptr = nullptr;
    __half *xh, *xch, *wqh, *wql, *wph, *wpl;
    cudaGetSymbolAddress((void**)&qkv_ptr, g_qkv);
    cudaGetSymbolAddress((void**)&xh,  g_xh);
    cudaGetSymbolAddress((void**)&xch, g_xch);
    cudaGetSymbolAddress((void**)&wqh, g_wqh);
    cudaGetSymbolAddress((void**)&wql, g_wql);
    cudaGetSymbolAddress((void**)&wph, g_wph);
    cudaGetSymbolAddress((void**)&wpl, g_wpl);

    cudaFuncSetAttribute(ttt_grad_kernel,
        cudaFuncAttributeMaxDynamicSharedMemorySize, 132096);
    cudaFuncSetAttribute(ttt_fwd_kernel,
        cudaFuncAttributeMaxDynamicSharedMemorySize, 66560);
    cudaFuncSetAttribute(tc_gemm,
        cudaFuncAttributeMaxDynamicSharedMemorySize, TCG_SMEM);

    // 1. convert x (hi only), transpose+split weights (hi/lo)
    convert_f16<<<(B_*N_*C_/4 + 255)/256, 256>>>(x, xh, B_*N_*C_/4);
    transpose_split<<<dim3(QC/32, C_/32), 256>>>(Wqkv, wqh, wql, C_, QC);
    transpose_split<<<dim3(C_/32, XC/32), 256>>>(Wproj, wph, wpl, XC, C_);

    // 2. qkv = x @ Wqkv + bqkv  (HMMA fp16, 2-term weight split)
    tc_gemm<<<dim3((QC + 127)/128, (B_*N_)/128), 256, TCG_SMEM>>>(
        xh, wqh, wql, bqkv, qkv_ptr, QC, C_);

    // 3. TTT + conv gradients, reduce, update (scales fused)
    ttt_grad_kernel<<<dim3(8, NH, B_), 256, 132096>>>(w1, w2);
    conv_grad_kernel<<<B_ * 64, 256>>>(w3);
    conv_grad_reduce_kernel<<<1, 576>>>();
    reduce_gw_stage1<<<192, 256>>>();
    reduce_gw_stage2<<<24, 256>>>();
    update_w_kernel<<<(98880 + 255)/256, 256>>>(w1, w2, w3);

    // 4. post-update forward (writes fp16 hi directly)
    ttt_fwd_kernel<<<dim3(8, NH, B_), 256, 66560>>>();
    conv_fwd_kernel<<<B_ * 64, 256>>>();

    // 5. proj GEMM
    tc_gemm<<<dim3(C_/128, (B_*N_)/128), 256, TCG_SMEM>>>(
        xch, wph, wpl, bproj, (float*)d_out, C_, XC);
}

// round 11
// speedup vs baseline: 1.4638x; 1.1711x over previous
#include <cuda_runtime.h>
#include <cuda_bf16.h>
#include <cuda_fp16.h>
#include <cstdint>
#include <cstdio>
#include <math.h>

#define B_  16
#define N_  1024
#define C_  768
#define NH  12
#define HD_ 64
#define QC  2496   // 3*768 + 3*64
#define XC  832    // 768 + 64
#define M1_INV (1.0f/12582912.0f)
#define M2_INV (1.0f/1048576.0f)
#define LR_ 0.001f

// ---------------- scratch ----------------
__device__ float g_qkv[B_*N_*QC];
__device__ float g_gw_part[2*NH*128*HD_*HD_];
__device__ float g_gw_stage[24*8*HD_*HD_];
__device__ float g_gw[2*NH*HD_*HD_];
__device__ float g_gw3_part[B_*64*9];
__device__ float g_gw3[64*9];
__device__ float g_sumsq[25];
__device__ float g_mw1[NH*HD_*HD_];
__device__ float g_mw2[NH*HD_*HD_];
__device__ float g_mw3[64*9];
// fp16 operands: activations hi-only; weights hi/lo split
__device__ __half g_xh[B_*N_*C_];
__device__ __half g_xch[B_*N_*XC];
__device__ __half g_wqh[QC*C_], g_wql[QC*C_];   // [N=2496][K=768]
__device__ __half g_wph[C_*XC], g_wpl[C_*XC];   // [N=768][K=832]

// ---------------- PTX helpers ----------------
__device__ __forceinline__ unsigned int smem_to_u32(const void* smem_ptr) {
    unsigned int addr;
    asm("{ .reg .u64 tmp; cvta.to.shared.u64 tmp, %1; cvt.u32.u64 %0, tmp; }"
        : "=r"(addr) : "l"(smem_ptr));
    return addr;
}
__device__ __forceinline__ void cp_async16(unsigned int saddr, const void* gaddr) {
    asm volatile("cp.async.cg.shared.global [%0], [%1], 16;"
                 :: "r"(saddr), "l"(gaddr) : "memory");
}
__device__ __forceinline__ void cp_commit() {
    asm volatile("cp.async.commit_group;" ::: "memory");
}
__device__ __forceinline__ void cp_wait1() {
    asm volatile("cp.async.wait_group 1;" ::: "memory");
}
__device__ __forceinline__ void cp_wait0() {
    asm volatile("cp.async.wait_group 0;" ::: "memory");
}
__device__ __forceinline__ void ldm_x4(unsigned int& r0, unsigned int& r1,
                                       unsigned int& r2, unsigned int& r3,
                                       unsigned int a) {
    asm volatile("ldmatrix.sync.aligned.m8n8.x4.shared.b16 {%0,%1,%2,%3}, [%4];"
                 : "=r"(r0), "=r"(r1), "=r"(r2), "=r"(r3) : "r"(a));
}
__device__ __forceinline__ void ldm_x4t(unsigned int& r0, unsigned int& r1,
                                        unsigned int& r2, unsigned int& r3,
                                        unsigned int a) {
    asm volatile("ldmatrix.sync.aligned.m8n8.x4.trans.shared.b16 {%0,%1,%2,%3}, [%4];"
                 : "=r"(r0), "=r"(r1), "=r"(r2), "=r"(r3) : "r"(a));
}
__device__ __forceinline__ void mma_f16(float& c0, float& c1, float& c2, float& c3,
                                        unsigned int a0, unsigned int a1,
                                        unsigned int a2, unsigned int a3,
                                        unsigned int b0, unsigned int b1) {
    asm volatile("mma.sync.aligned.m16n8k16.row.col.f32.f16.f16.f32 "
                 "{%0,%1,%2,%3}, {%4,%5,%6,%7}, {%8,%9}, {%0,%1,%2,%3};"
                 : "+f"(c0), "+f"(c1), "+f"(c2), "+f"(c3)
                 : "r"(a0), "r"(a1), "r"(a2), "r"(a3), "r"(b0), "r"(b1));
}

// ---------------- conversions ----------------
__device__ __forceinline__ unsigned int pack_h2(__half a, __half b) {
    return (unsigned int)__half_as_ushort(a) |
           ((unsigned int)__half_as_ushort(b) << 16);
}
__global__ __launch_bounds__(256) void convert_f16(
    const float* __restrict__ X, __half* __restrict__ H, int n4)
{
    int i = blockIdx.x * 256 + threadIdx.x;
    if (i >= n4) return;
    float4 v = ((const float4*)X)[i];
    uint2 hh;
    hh.x = pack_h2(__float2half(v.x), __float2half(v.y));
    hh.y = pack_h2(__float2half(v.z), __float2half(v.w));
    ((uint2*)H)[i] = hh;
}
__global__ __launch_bounds__(256) void transpose_split(
    const float* __restrict__ W, __half* __restrict__ Th,
    __half* __restrict__ Tl, int K, int N)
{
    __shared__ float s[32][33];
    const int n0 = blockIdx.x * 32, k0 = blockIdx.y * 32;
    const int tx = threadIdx.x & 31, ty = threadIdx.x >> 5;
    for (int r = ty; r < 32; r += 8)
        s[r][tx] = W[(size_t)(k0 + r) * N + n0 + tx];
    __syncthreads();
    for (int r = ty; r < 32; r += 8) {
        float v = s[tx][r];
        __half h = __float2half(v);
        Th[(size_t)(n0 + r) * K + k0 + tx] = h;
        Tl[(size_t)(n0 + r) * K + k0 + tx] = __float2half(v - __half2float(h));
    }
}

// ---------------- HMMA GEMM (fp16, 2-term weight split) — unchanged from R10 ----
#define SROW   40
#define ARR_B  (128*SROW*2)
#define STG_B  (3*ARR_B)
#define TCG_SMEM (2*STG_B)

__global__ __launch_bounds__(256) void tc_gemm(
    const __half* __restrict__ Ah,
    const __half* __restrict__ Bh, const __half* __restrict__ Bl,
    const float* __restrict__ bias, float* __restrict__ C,
    int Nfull, int K)
{
    extern __shared__ __half smb[];
    const unsigned int smem_u = smem_to_u32(smb);
    const int t = threadIdx.x, lane = t & 31, wid = t >> 5;
    const int m0 = blockIdx.y * 128, n0 = blockIdx.x * 128;
    const int wm = (wid >> 2) * 64, wn = (wid & 3) * 32;

    float acc[4][4][4];
#pragma unroll
    for (int a = 0; a < 4; a++)
#pragma unroll
        for (int b = 0; b < 4; b++)
#pragma unroll
            for (int c = 0; c < 4; c++) acc[a][b][c] = 0.f;

    const __half* gp[6];
    unsigned int soff[6];
    bool vld[6];
#pragma unroll
    for (int p = 0; p < 6; p++) {
        int c = p * 256 + t;
        int arr = c >> 9, rem = c & 511, row = rem >> 2, c4 = rem & 3;
        const __half* base = (arr == 0) ? Ah : (arr == 1) ? Bh : Bl;
        int grow = (arr == 0) ? (m0 + row) : (n0 + row);
        vld[p]  = (arr == 0) || ((n0 + row) < Nfull);
        if (!vld[p]) grow = 0;
        gp[p]   = base + (size_t)grow * K + c4 * 8;
        soff[p] = (unsigned int)(arr * ARR_B + (row * SROW + c4 * 8) * 2);
    }

#define ISSUE(stg, ks) do {                                             \
        unsigned int _sb = smem_u + (unsigned int)(stg) * STG_B;        \
        _Pragma("unroll")                                               \
        for (int p = 0; p < 6; p++)                                     \
            if (vld[p]) cp_async16(_sb + soff[p], gp[p] + (ks) * 32);   \
        cp_commit();                                                    \
    } while (0)

    const int nk = K / 32;
    ISSUE(0, 0);

    for (int s = 0; s < nk; s++) {
        if (s + 1 < nk) { ISSUE((s + 1) & 1, s + 1); cp_wait1(); }
        else            { cp_wait0(); }
        __syncthreads();

        const unsigned int sb = smem_u + (unsigned int)(s & 1) * STG_B;
#pragma unroll
        for (int kc = 0; kc < 32; kc += 16) {
            unsigned int bh[4][2], bl[4][2];
#pragma unroll
            for (int q = 0; q < 2; q++) {
                unsigned int brow = (unsigned int)(wn + q * 16 + (lane & 7) +
                                                   ((lane >> 4) << 3));
                unsigned int koff = (unsigned int)(((lane >> 3) & 1) * 8);
                unsigned int ab = sb + 1u * ARR_B + (brow * SROW + kc + koff) * 2;
                ldm_x4(bh[2*q][0], bh[2*q][1], bh[2*q+1][0], bh[2*q+1][1], ab);
                ldm_x4(bl[2*q][0], bl[2*q][1], bl[2*q+1][0], bl[2*q+1][1],
                       ab + ARR_B);
            }
#pragma unroll
            for (int mt = 0; mt < 4; mt++) {
                unsigned int arow = (unsigned int)(wm + mt * 16 + (lane & 15));
                unsigned int koff = (unsigned int)((lane >> 4) * 8);
                unsigned int aa = sb + (arow * SROW + kc + koff) * 2;
                unsigned int a0, a1, a2, a3;
                ldm_x4(a0, a1, a2, a3, aa);
#pragma unroll
                for (int nt = 0; nt < 4; nt++) {
                    mma_f16(acc[mt][nt][0], acc[mt][nt][1],
                            acc[mt][nt][2], acc[mt][nt][3],
                            a0, a1, a2, a3, bh[nt][0], bh[nt][1]);
                    mma_f16(acc[mt][nt][0], acc[mt][nt][1],
                            acc[mt][nt][2], acc[mt][nt][3],
                            a0, a1, a2, a3, bl[nt][0], bl[nt][1]);
                }
            }
        }
        __syncthreads();
    }
#undef ISSUE

    const int g = lane >> 2, tq = lane & 3;
#pragma unroll
    for (int mt = 0; mt < 4; mt++) {
        const int row = m0 + wm + mt * 16 + g;
#pragma unroll
        for (int nt = 0; nt < 4; nt++) {
            const int col = n0 + wn + nt * 8 + tq * 2;
            if (col < Nfull) {
                float b0 = bias[col], b1 = bias[col + 1];
                float2 o1; o1.x = acc[mt][nt][0] + b0; o1.y = acc[mt][nt][1] + b1;
                float2 o2v; o2v.x = acc[mt][nt][2] + b0; o2v.y = acc[mt][nt][3] + b1;
                *(float2*)(C + (size_t)row * Nfull + col) = o1;
                *(float2*)(C + (size_t)(row + 8) * Nfull + col) = o2v;
            }
        }
    }
}

// ---------------- packed f32x2 helpers ----------------
__device__ __forceinline__ unsigned long long pack_dup(float x) {
    unsigned long long d;
    asm("mov.b64 %0, {%1, %1};" : "=l"(d) : "f"(x));
    return d;
}
__device__ __forceinline__ void fma2(unsigned long long &d,
                                     unsigned long long a, unsigned long long b) {
    asm("fma.rn.f32x2 %0, %1, %2, %0;" : "+l"(d) : "l"(a), "l"(b));
}
__device__ __forceinline__ float2 unpack2(unsigned long long v) {
    float lo, hi;
    asm("mov.b64 {%0, %1}, %2;" : "=f"(lo), "=f"(hi) : "l"(v));
    return make_float2(lo, hi);
}

// ---------------- TTT gradient kernel — HMMA version ----------------
// SMEM (fp16, row stride 72): w1T[64][72], w2T[64][72], k1h[128][72],
// gAh[128][72], gBh[128][72]. Total 36864 halves = 73728 B.
#define TG_SMEM 73728
__global__ __launch_bounds__(256) void ttt_grad_kernel(
    const float* __restrict__ w1g, const float* __restrict__ w2g)
{
    extern __shared__ __half smh[];
    const unsigned int su  = smem_to_u32(smh);
    const unsigned int w1u = su;
    const unsigned int w2u = su + 4608u * 2;
    const unsigned int k1u = su + 9216u * 2;
    const unsigned int gAu = k1u + 9216u * 2;
    const unsigned int gBu = gAu + 9216u * 2;
    __half* w1T = smh;
    __half* w2T = smh + 4608;
    __half* k1h = smh + 9216;
    __half* gAh = smh + 9216 + 9216;
    __half* gBh = gAh + 9216;

    const int tid = threadIdx.x, lane = tid & 31, wid = tid >> 5;
    const int chunk = blockIdx.x, head = blockIdx.y, b = blockIdx.z;
    const int n0 = chunk * 128;

    // load w1T[n][k] = w1[k][n], fp16 (transpose)
    for (int idx = tid; idx < 4096; idx += 256) {
        const int k = idx >> 6, n = idx & 63;
        w1T[n * 72 + k] = __float2half(w1g[head * 4096 + idx]);
        w2T[n * 72 + k] = __float2half(w2g[head * 4096 + idx]);
    }
    // load k1h[128][64] fp16, row-major
    {
        const float* src = g_qkv + (size_t)(b * N_ + n0) * QC + C_ + head * HD_;
        const int row = tid >> 1, c8 = (tid & 1) * 32;
#pragma unroll
        for (int c = 0; c < 32; c += 4) {
            float4 v = *(const float4*)(src + (size_t)row * QC + c8 + c);
            *(__half2*)&k1h[row * 72 + c8 + c]     = __floats2half2_rn(v.x, v.y);
            *(__half2*)&k1h[row * 72 + c8 + c + 2] = __floats2half2_rn(v.z, v.w);
        }
    }
    __syncthreads();

    // ---- Phase 1: each warp computes 16 rows (m0w..+15) x 64 cols of A,B ----
    const int m0w = wid * 16;
    float accA[8][4], accB[8][4];
#pragma unroll
    for (int nt = 0; nt < 8; nt++)
#pragma unroll
        for (int c = 0; c < 4; c++) { accA[nt][c] = 0.f; accB[nt][c] = 0.f; }

#pragma unroll
    for (int kk = 0; kk < 4; kk++) {
        const unsigned int ak = (unsigned int)(kk * 16 + ((lane >> 4) << 3));
        const unsigned int aa = k1u + ((unsigned int)(m0w + (lane & 15)) * 72 + ak) * 2;
        unsigned int a0, a1, a2, a3;
        ldm_x4(a0, a1, a2, a3, aa);
        unsigned int b1[8][2], b2[8][2];
#pragma unroll
        for (int q = 0; q < 4; q++) {
            const unsigned int brow = (unsigned int)(q * 16 + (lane & 7) +
                                                     ((lane >> 4) << 3));
            const unsigned int bk = (unsigned int)(kk * 16 + ((lane >> 3) & 1) * 8);
            ldm_x4(b1[2*q][0], b1[2*q][1], b1[2*q+1][0], b1[2*q+1][1],
                   w1u + (brow * 72 + bk) * 2);
            ldm_x4(b2[2*q][0], b2[2*q][1], b2[2*q+1][0], b2[2*q+1][1],
                   w2u + (brow * 72 + bk) * 2);
        }
#pragma unroll
        for (int nt = 0; nt < 8; nt++) {
            mma_f16(accA[nt][0], accA[nt][1], accA[nt][2], accA[nt][3],
                    a0, a1, a2, a3, b1[nt][0], b1[nt][1]);
            mma_f16(accB[nt][0], accB[nt][1], accB[nt][2], accB[nt][3],
                    a0, a1, a2, a3, b2[nt][0], b2[nt][1]);
        }
    }

    // ---- elementwise: g' = (A*silu(B) - v)  (M1_INV deferred to store) ----
    const int g = lane >> 2, tq = lane & 3;
    const float* vbase = g_qkv + (size_t)(b * N_ + n0 + m0w) * QC + 2 * C_ + head * HD_;
#pragma unroll
    for (int nt = 0; nt < 8; nt++) {
        const int col = nt * 8 + tq * 2;
#pragma unroll
        for (int h = 0; h < 2; h++) {
            const int row = g + h * 8;
            float2 v = *(const float2*)(vbase + (size_t)row * QC + col);
            float Av0 = accA[nt][2*h + 0], Av1 = accA[nt][2*h + 1];
            float Bv0 = accB[nt][2*h + 0], Bv1 = accB[nt][2*h + 1];
            float sig0 = 1.f / (1.f + expf(-Bv0));
            float sig1 = 1.f / (1.f + expf(-Bv1));
            float sil0 = Bv0 * sig0, sil1 = Bv1 * sig1;
            float g0 = Av0 * sil0 - v.x;
            float g1 = Av1 * sil1 - v.y;
            float gA0 = g0 * sil0, gA1 = g1 * sil1;
            float gB0 = g0 * Av0 * sig0 * (1.f + Bv0 * (1.f - sig0));
            float gB1 = g1 * Av1 * sig1 * (1.f + Bv1 * (1.f - sig1));
            *(__half2*)&gAh[(m0w + row) * 72 + col] = __floats2half2_rn(gA0, gA1);
            *(__half2*)&gBh[(m0w + row) * 72 + col] = __floats2half2_rn(gB0, gB1);
        }
    }
    __syncthreads();

    // ---- Phase 2: gw = k1^T[64x128] @ gA/gB[128x64] via trans ldmatrix ----
    const int mt = wid >> 1;            // 0..3 -> m rows mt*16..+15 (k-dim of gw)
    const int nh = (wid & 1) * 32;      // n half
    float r1[4][4], r2[4][4];
#pragma unroll
    for (int nt = 0; nt < 4; nt++)
#pragma unroll
        for (int c = 0; c < 4; c++) { r1[nt][c] = 0.f; r2[nt][c] = 0.f; }

#pragma unroll
    for (int ks = 0; ks < 8; ks++) {
        const int k0 = ks * 16;
        // A = k1^T: trans load from k1h[k][m]
        const unsigned int arow = (unsigned int)(k0 + ((lane >> 4) << 3) + (lane & 7));
        const unsigned int acol = (unsigned int)(mt * 16 + (((lane >> 3) & 1) << 3));
        unsigned int a0, a1, a2, a3;
        ldm_x4t(a0, a1, a2, a3, k1u + (arow * 72 + acol) * 2);
        unsigned int bA[4][2], bB[4][2];
#pragma unroll
        for (int q = 0; q < 2; q++) {
            const unsigned int brow = (unsigned int)(k0 + (((lane >> 3) & 1) << 3) +
                                                     (lane & 7));
            const unsigned int bcol = (unsigned int)(nh + q * 16 + ((lane >> 4) << 3));
            ldm_x4t(bA[2*q][0], bA[2*q][1], bA[2*q+1][0], bA[2*q+1][1],
                    gAu + (brow * 72 + bcol) * 2);
            ldm_x4t(bB[2*q][0], bB[2*q][1], bB[2*q+1][0], bB[2*q+1][1],
                    gBu + (brow * 72 + bcol) * 2);
        }
#pragma unroll
        for (int nt = 0; nt < 4; nt++) {
            mma_f16(r1[nt][0], r1[nt][1], r1[nt][2], r1[nt][3],
                    a0, a1, a2, a3, bA[nt][0], bA[nt][1]);
            mma_f16(r2[nt][0], r2[nt][1], r2[nt][2], r2[nt][3],
                    a0, a1, a2, a3, bB[nt][0], bB[nt][1]);
        }
    }

    // ---- store partials (apply deferred M1_INV) ----
    const int pidx = b * 8 + chunk;
    float* d1 = g_gw_part + ((size_t)(0 * NH + head) * 128 + pidx) * 4096;
    float* d2 = g_gw_part + ((size_t)(1 * NH + head) * 128 + pidx) * 4096;
#pragma unroll
    for (int nt = 0; nt < 4; nt++) {
        const int row = mt * 16 + g;
        const int col = nh + nt * 8 + tq * 2;
        float2 p;
        p.x = r1[nt][0] * M1_INV; p.y = r1[nt][1] * M1_INV;
        *(float2*)&d1[row * 64 + col] = p;
        p.x = r1[nt][2] * M1_INV; p.y = r1[nt][3] * M1_INV;
        *(float2*)&d1[(row + 8) * 64 + col] = p;
        p.x = r2[nt][0] * M1_INV; p.y = r2[nt][1] * M1_INV;
        *(float2*)&d2[row * 64 + col] = p;
        p.x = r2[nt][2] * M1_INV; p.y = r2[nt][3] * M1_INV;
        *(float2*)&d2[(row + 8) * 64 + col] = p;
    }
}

// ---------------- TTT forward kernel (fp32 fma2; writes fp16 hi) ----------------
__global__ __launch_bounds__(256) void ttt_fwd_kernel()
{
    extern __shared__ float sm_f[];
    float* w1s = sm_f;
    float* w2s = sm_f + 4096;
    float* q1t = sm_f + 8192;

    const int tid   = threadIdx.x;
    const int chunk = blockIdx.x;
    const int head  = blockIdx.y;
    const int b     = blockIdx.z;
    const int n0    = chunk * 128;

    for (int e = tid * 4; e < 4096; e += 1024) {
        *(float4*)&w1s[e] = *(const float4*)&g_mw1[head * 4096 + e];
        *(float4*)&w2s[e] = *(const float4*)&g_mw2[head * 4096 + e];
    }
    {
        const float* src = g_qkv + (size_t)(b * N_ + n0) * QC + head * HD_;
        int i  = tid >> 4;
        int k4 = (tid & 15) * 4;
        for (int p = 0; p < 8; p++, i += 16) {
            float4 v = *(const float4*)(src + (size_t)i * QC + k4);
            q1t[(k4 + 0) * 132 + i] = v.x;
            q1t[(k4 + 1) * 132 + i] = v.y;
            q1t[(k4 + 2) * 132 + i] = v.z;
            q1t[(k4 + 3) * 132 + i] = v.w;
        }
    }
    __syncthreads();

    const int ty = tid >> 4, tx = tid & 15;
    const int i0 = ty * 8, j0 = tx * 4;
    unsigned long long accA2[8][2], accB2[8][2];
#pragma unroll
    for (int i = 0; i < 8; i++)
#pragma unroll
        for (int j = 0; j < 2; j++) { accA2[i][j] = 0ULL; accB2[i][j] = 0ULL; }

#pragma unroll 8
    for (int kk = 0; kk < 64; kk++) {
        float a[8];
        *(float4*)&a[0] = *(float4*)&q1t[kk * 132 + i0];
        *(float4*)&a[4] = *(float4*)&q1t[kk * 132 + i0 + 4];
        unsigned long long b1[2], b2[2];
        b1[0] = *(const unsigned long long*)&w1s[kk * 64 + j0];
        b1[1] = *(const unsigned long long*)&w1s[kk * 64 + j0 + 2];
        b2[0] = *(const unsigned long long*)&w2s[kk * 64 + j0];
        b2[1] = *(const unsigned long long*)&w2s[kk * 64 + j0 + 2];
#pragma unroll
        for (int i = 0; i < 8; i++) {
            unsigned long long a2 = pack_dup(a[i]);
            fma2(accA2[i][0], a2, b1[0]);
            fma2(accA2[i][1], a2, b1[1]);
            fma2(accB2[i][0], a2, b2[0]);
            fma2(accB2[i][1], a2, b2[1]);
        }
    }

#pragma unroll
    for (int i = 0; i < 8; i++) {
        float Aarr[4], Barr[4];
        float2 tt;
        tt = unpack2(accA2[i][0]); Aarr[0] = tt.x; Aarr[1] = tt.y;
        tt = unpack2(accA2[i][1]); Aarr[2] = tt.x; Aarr[3] = tt.y;
        tt = unpack2(accB2[i][0]); Barr[0] = tt.x; Barr[1] = tt.y;
        tt = unpack2(accB2[i][1]); Barr[2] = tt.x; Barr[3] = tt.y;
        float out[4];
#pragma unroll
        for (int j = 0; j < 4; j++) {
            float sig = 1.f / (1.f + expf(-Barr[j]));
            out[j] = Aarr[j] * (Barr[j] * sig);
        }
        uint2 hh;
        hh.x = pack_h2(__float2half(out[0]), __float2half(out[1]));
        hh.y = pack_h2(__float2half(out[2]), __float2half(out[3]));
        const size_t idx = (size_t)(b * N_ + n0 + i0 + i) * XC + head * HD_ + j0;
        *(uint2*)(g_xch + idx) = hh;
    }
}

// ---------------- conv grad ----------------
__global__ __launch_bounds__(256) void conv_grad_kernel(const float* __restrict__ w3g)
{
    const int bc = blockIdx.x;
    const int b = bc >> 6, c = bc & 63;
    const int tid = threadIdx.x;
    __shared__ float k2s[32][33];
    __shared__ float wk[9];
    __shared__ float red[256];

    if (tid < 9) wk[tid] = w3g[c * 9 + tid];
    const float* base = g_qkv + (size_t)(b * N_) * QC;
    for (int p = tid; p < 1024; p += 256)
        k2s[p >> 5][p & 31] = base[(size_t)p * QC + 2368 + c];
    __syncthreads();

    float acc[9];
#pragma unroll
    for (int q = 0; q < 9; q++) acc[q] = 0.f;

    for (int p = tid; p < 1024; p += 256) {
        const int y = p >> 5, x = p & 31;
        float t[9];
#pragma unroll
        for (int dy = 0; dy < 3; dy++)
#pragma unroll
            for (int dx = 0; dx < 3; dx++) {
                int yy = y + dy - 1, xx = x + dx - 1;
                t[dy * 3 + dx] = (yy >= 0 && yy < 32 && xx >= 0 && xx < 32)
                                 ? k2s[yy][xx] : 0.f;
            }
        float f = 0.f;
#pragma unroll
        for (int q = 0; q < 9; q++) f = fmaf(wk[q], t[q], f);
        float v = base[(size_t)p * QC + 2432 + c];
        float g = (f - v) * M2_INV;
#pragma unroll
        for (int q = 0; q < 9; q++) acc[q] = fmaf(g, t[q], acc[q]);
    }

    for (int q = 0; q < 9; q++) {
        red[tid] = acc[q];
        __syncthreads();
        for (int s = 128; s > 0; s >>= 1) {
            if (tid < s) red[tid] += red[tid + s];
            __syncthreads();
        }
        if (tid == 0) g_gw3_part[(size_t)bc * 9 + q] = red[0];
        __syncthreads();
    }
}

__global__ void conv_grad_reduce_kernel()
{
    const int tid = threadIdx.x;
    __shared__ float red[576];
    float s = 0.f;
    const int c = tid / 9, q = tid % 9;
    for (int b = 0; b < B_; b++) s += g_gw3_part[(size_t)(b * 64 + c) * 9 + q];
    g_gw3[tid] = s;
    red[tid] = s * s;
    __syncthreads();
    if (tid < 64) red[tid] += red[tid + 512];
    __syncthreads();
    for (int st = 256; st > 0; st >>= 1) {
        if (tid < st && tid + st < 576) red[tid] += red[tid + st];
        __syncthreads();
    }
    if (tid == 0) g_sumsq[24] = red[0];
}

// ---------------- two-stage gw reduce ----------------
__global__ __launch_bounds__(256) void reduce_gw_stage1()
{
    const int th = blockIdx.x >> 3;
    const int g  = blockIdx.x & 7;
    const int tid = threadIdx.x;
    const float* src = g_gw_part + ((size_t)th * 128 + g * 16) * 4096;
    float s[16];
#pragma unroll
    for (int q = 0; q < 16; q++) s[q] = 0.f;
    for (int p = 0; p < 16; p++) {
        const float* row = src + (size_t)p * 4096 + tid;
#pragma unroll
        for (int q = 0; q < 16; q++) s[q] += row[q * 256];
    }
    float* dst = g_gw_stage + (size_t)(th * 8 + g) * 4096 + tid;
#pragma unroll
    for (int q = 0; q < 16; q++) dst[q * 256] = s[q];
}

__global__ __launch_bounds__(256) void reduce_gw_stage2()
{
    const int th  = blockIdx.x;
    const int tid = threadIdx.x;
    const float* src = g_gw_stage + (size_t)th * 8 * 4096;
    float* dst = g_gw + (size_t)th * 4096;

    float s[16];
#pragma unroll
    for (int q = 0; q < 16; q++) s[q] = 0.f;
    for (int p = 0; p < 8; p++) {
        const float* row = src + (size_t)p * 4096 + tid;
#pragma unroll
        for (int q = 0; q < 16; q++) s[q] += row[q * 256];
    }
    float ss = 0.f;
#pragma unroll
    for (int q = 0; q < 16; q++) { dst[tid + q * 256] = s[q]; ss += s[q] * s[q]; }

    __shared__ float red[256];
    red[tid] = ss;
    __syncthreads();
    for (int st = 128; st > 0; st >>= 1) {
        if (tid < st) red[tid] += red[tid + st];
        __syncthreads();
    }
    if (tid == 0) g_sumsq[th] = red[0];
}

// ---------------- weight update (scales fused) ----------------
__global__ void update_w_kernel(const float* __restrict__ w1g,
                                const float* __restrict__ w2g,
                                const float* __restrict__ w3g)
{
    __shared__ float sc[3];
    if (threadIdx.x == 0) {
        float s1 = 0.f, s2 = 0.f;
        for (int h = 0; h < NH; h++) { s1 += g_sumsq[h]; s2 += g_sumsq[NH + h]; }
        sc[0] = LR_ / (sqrtf(s1) + 1.f);
        sc[1] = LR_ / (sqrtf(s2) + 1.f);
        sc[2] = LR_ / (sqrtf(g_sumsq[24]) + 1.f);
    }
    __syncthreads();
    const int i = blockIdx.x * 256 + threadIdx.x;
    if (i < 49152) {
        g_mw1[i] = w1g[i] - sc[0] * g_gw[i];
    } else if (i < 98304) {
        const int k = i - 49152;
        g_mw2[k] = w2g[k] - sc[1] * g_gw[49152 + k];
    } else if (i < 98880) {
        const int k = i - 98304;
        g_mw3[k] = w3g[k] - sc[2] * g_gw3[k];
    }
}

// ---------------- conv forward (writes fp16 hi directly) ----------------
__global__ __launch_bounds__(256) void conv_fwd_kernel()
{
    const int bc = blockIdx.x;
    const int b = bc >> 6, c = bc & 63;
    const int tid = threadIdx.x;
    __shared__ float q2s[32][33];
    __shared__ float wk[9];
    if (tid < 9) wk[tid] = g_mw3[c * 9 + tid];
    const float* base = g_qkv + (size_t)(b * N_) * QC;
    for (int p = tid; p < 1024; p += 256)
        q2s[p >> 5][p & 31] = base[(size_t)p * QC + 2304 + c];
    __syncthreads();

    for (int p = tid; p < 1024; p += 256) {
        const int y = p >> 5, x = p & 31;
        float f = 0.f;
#pragma unroll
        for (int dy = 0; dy < 3; dy++)
#pragma unroll
            for (int dx = 0; dx < 3; dx++) {
                int yy = y + dy - 1, xx = x + dx - 1;
                if (yy >= 0 && yy < 32 && xx >= 0 && xx < 32)
                    f = fmaf(wk[dy * 3 + dx], q2s[yy][xx], f);
            }
        g_xch[(size_t)(b * N_ + p) * XC + 768 + c] = __float2half(f);
    }
}

// ---------------- launch ----------------
extern "C" void kernel_launch(void* const* d_in, const int* in_sizes, int n_in,
                              void* d_out, int out_size)
{
    const float *x = nullptr, *Wqkv = nullptr, *bqkv = nullptr, *w1 = nullptr,
                *w2 = nullptr, *w3 = nullptr, *Wproj = nullptr, *bproj = nullptr;
    for (int i = 0; i < n_in; i++) {
        const int s = in_sizes[i];
        const float* p = (const float*)d_in[i];
        if      (s == B_*N_*C_)   x = p;
        else if (s == C_*QC)      Wqkv = p;
        else if (s == QC)         bqkv = p;
        else if (s == NH*HD_*HD_) { if (!w1) w1 = p; else w2 = p; }
        else if (s == 64*9)       w3 = p;
        else if (s == XC*C_)      Wproj = p;
        else if (s == C_)         bproj = p;
    }

    float* qkv_ptr = nullptr;
    __half *xh, *xch, *wqh, *wql, *wph, *wpl;
    cudaGetSymbolAddress((void**)&qkv_ptr, g_qkv);
    cudaGetSymbolAddress((void**)&xh,  g_xh);
    cudaGetSymbolAddress((void**)&xch, g_xch);
    cudaGetSymbolAddress((void**)&wqh, g_wqh);
    cudaGetSymbolAddress((void**)&wql, g_wql);
    cudaGetSymbolAddress((void**)&wph, g_wph);
    cudaGetSymbolAddress((void**)&wpl, g_wpl);

    cudaFuncSetAttribute(ttt_grad_kernel,
        cudaFuncAttributeMaxDynamicSharedMemorySize, TG_SMEM);
    cudaFuncSetAttribute(ttt_fwd_kernel,
        cudaFuncAttributeMaxDynamicSharedMemorySize, 66560);
    cudaFuncSetAttribute(tc_gemm,
        cudaFuncAttributeMaxDynamicSharedMemorySize, TCG_SMEM);

    // 1. convert x (hi only), transpose+split weights (hi/lo)
    convert_f16<<<(B_*N_*C_/4 + 255)/256, 256>>>(x, xh, B_*N_*C_/4);
    transpose_split<<<dim3(QC/32, C_/32), 256>>>(Wqkv, wqh, wql, C_, QC);
    transpose_split<<<dim3(C_/32, XC/32), 256>>>(Wproj, wph, wpl, XC, C_);

    // 2. qkv = x @ Wqkv + bqkv
    tc_gemm<<<dim3((QC + 127)/128, (B_*N_)/128), 256, TCG_SMEM>>>(
        xh, wqh, wql, bqkv, qkv_ptr, QC, C_);

    // 3. TTT (HMMA) + conv gradients, reduce, update
    ttt_grad_kernel<<<dim3(8, NH, B_), 256, TG_SMEM>>>(w1, w2);
    conv_grad_kernel<<<B_ * 64, 256>>>(w3);
    conv_grad_reduce_kernel<<<1, 576>>>();
    reduce_gw_stage1<<<192, 256>>>();
    reduce_gw_stage2<<<24, 256>>>();
    update_w_kernel<<<(98880 + 255)/256, 256>>>(w1, w2, w3);

    // 4. post-update forward
    ttt_fwd_kernel<<<dim3(8, NH, B_), 256, 66560>>>();
    conv_fwd_kernel<<<B_ * 64, 256>>>();

    // 5. proj GEMM
    tc_gemm<<<dim3(C_/128, (B_*N_)/128), 256, TCG_SMEM>>>(
        xch, wph, wpl, bproj, (float*)d_out, C_, XC);
}

// round 12
// speedup vs baseline: 1.4714x; 1.0052x over previous
#include <cuda_runtime.h>
#include <cuda_bf16.h>
#include <cuda_fp16.h>
#include <cstdint>
#include <cstdio>
#include <math.h>

#define B_  16
#define N_  1024
#define C_  768
#define NH  12
#define HD_ 64
#define QC  2496   // 3*768 + 3*64
#define XC  832    // 768 + 64
#define M1_INV (1.0f/12582912.0f)
#define M2_INV (1.0f/1048576.0f)
#define LR_ 0.001f

// ---------------- scratch ----------------
__device__ float g_qkv[B_*N_*QC];
__device__ float g_gw_part[2*NH*128*HD_*HD_];
__device__ float g_gw_stage[24*8*HD_*HD_];
__device__ float g_gw[2*NH*HD_*HD_];
__device__ float g_gw3_part[B_*64*9];
__device__ float g_gw3[64*9];
__device__ float g_sumsq[25];
__device__ float g_mw1[NH*HD_*HD_];
__device__ float g_mw2[NH*HD_*HD_];
__device__ float g_mw3[64*9];
// fp16 operands: activations hi-only; weights hi/lo split
__device__ __half g_xh[B_*N_*C_];
__device__ __half g_xch[B_*N_*XC];
__device__ __half g_wqh[QC*C_], g_wql[QC*C_];   // [N=2496][K=768]
__device__ __half g_wph[C_*XC], g_wpl[C_*XC];   // [N=768][K=832]

// ---------------- PTX helpers ----------------
__device__ __forceinline__ unsigned int smem_to_u32(const void* smem_ptr) {
    unsigned int addr;
    asm("{ .reg .u64 tmp; cvta.to.shared.u64 tmp, %1; cvt.u32.u64 %0, tmp; }"
        : "=r"(addr) : "l"(smem_ptr));
    return addr;
}
__device__ __forceinline__ void cp_async16(unsigned int saddr, const void* gaddr) {
    asm volatile("cp.async.cg.shared.global [%0], [%1], 16;"
                 :: "r"(saddr), "l"(gaddr) : "memory");
}
__device__ __forceinline__ void cp_commit() {
    asm volatile("cp.async.commit_group;" ::: "memory");
}
__device__ __forceinline__ void cp_wait1() {
    asm volatile("cp.async.wait_group 1;" ::: "memory");
}
__device__ __forceinline__ void cp_wait0() {
    asm volatile("cp.async.wait_group 0;" ::: "memory");
}
__device__ __forceinline__ void ldm_x4(unsigned int& r0, unsigned int& r1,
                                       unsigned int& r2, unsigned int& r3,
                                       unsigned int a) {
    asm volatile("ldmatrix.sync.aligned.m8n8.x4.shared.b16 {%0,%1,%2,%3}, [%4];"
                 : "=r"(r0), "=r"(r1), "=r"(r2), "=r"(r3) : "r"(a));
}
__device__ __forceinline__ void ldm_x4t(unsigned int& r0, unsigned int& r1,
                                        unsigned int& r2, unsigned int& r3,
                                        unsigned int a) {
    asm volatile("ldmatrix.sync.aligned.m8n8.x4.trans.shared.b16 {%0,%1,%2,%3}, [%4];"
                 : "=r"(r0), "=r"(r1), "=r"(r2), "=r"(r3) : "r"(a));
}
__device__ __forceinline__ void mma_f16(float& c0, float& c1, float& c2, float& c3,
                                        unsigned int a0, unsigned int a1,
                                        unsigned int a2, unsigned int a3,
                                        unsigned int b0, unsigned int b1) {
    asm volatile("mma.sync.aligned.m16n8k16.row.col.f32.f16.f16.f32 "
                 "{%0,%1,%2,%3}, {%4,%5,%6,%7}, {%8,%9}, {%0,%1,%2,%3};"
                 : "+f"(c0), "+f"(c1), "+f"(c2), "+f"(c3)
                 : "r"(a0), "r"(a1), "r"(a2), "r"(a3), "r"(b0), "r"(b1));
}

// ---------------- conversions ----------------
__device__ __forceinline__ unsigned int pack_h2(__half a, __half b) {
    return (unsigned int)__half_as_ushort(a) |
           ((unsigned int)__half_as_ushort(b) << 16);
}
__global__ __launch_bounds__(256) void convert_f16(
    const float* __restrict__ X, __half* __restrict__ H, int n4)
{
    int i = blockIdx.x * 256 + threadIdx.x;
    if (i >= n4) return;
    float4 v = ((const float4*)X)[i];
    uint2 hh;
    hh.x = pack_h2(__float2half(v.x), __float2half(v.y));
    hh.y = pack_h2(__float2half(v.z), __float2half(v.w));
    ((uint2*)H)[i] = hh;
}
__global__ __launch_bounds__(256) void transpose_split(
    const float* __restrict__ W, __half* __restrict__ Th,
    __half* __restrict__ Tl, int K, int N)
{
    __shared__ float s[32][33];
    const int n0 = blockIdx.x * 32, k0 = blockIdx.y * 32;
    const int tx = threadIdx.x & 31, ty = threadIdx.x >> 5;
    for (int r = ty; r < 32; r += 8)
        s[r][tx] = W[(size_t)(k0 + r) * N + n0 + tx];
    __syncthreads();
    for (int r = ty; r < 32; r += 8) {
        float v = s[tx][r];
        __half h = __float2half(v);
        Th[(size_t)(n0 + r) * K + k0 + tx] = h;
        Tl[(size_t)(n0 + r) * K + k0 + tx] = __float2half(v - __half2float(h));
    }
}

// ---------------- HMMA GEMM (fp16, 2-term weight split) ----------------
#define SROW   40
#define ARR_B  (128*SROW*2)
#define STG_B  (3*ARR_B)
#define TCG_SMEM (2*STG_B)

__global__ __launch_bounds__(256) void tc_gemm(
    const __half* __restrict__ Ah,
    const __half* __restrict__ Bh, const __half* __restrict__ Bl,
    const float* __restrict__ bias, float* __restrict__ C,
    int Nfull, int K)
{
    extern __shared__ __half smb[];
    const unsigned int smem_u = smem_to_u32(smb);
    const int t = threadIdx.x, lane = t & 31, wid = t >> 5;
    const int m0 = blockIdx.y * 128, n0 = blockIdx.x * 128;
    const int wm = (wid >> 2) * 64, wn = (wid & 3) * 32;

    float acc[4][4][4];
#pragma unroll
    for (int a = 0; a < 4; a++)
#pragma unroll
        for (int b = 0; b < 4; b++)
#pragma unroll
            for (int c = 0; c < 4; c++) acc[a][b][c] = 0.f;

    const __half* gp[6];
    unsigned int soff[6];
    bool vld[6];
#pragma unroll
    for (int p = 0; p < 6; p++) {
        int c = p * 256 + t;
        int arr = c >> 9, rem = c & 511, row = rem >> 2, c4 = rem & 3;
        const __half* base = (arr == 0) ? Ah : (arr == 1) ? Bh : Bl;
        int grow = (arr == 0) ? (m0 + row) : (n0 + row);
        vld[p]  = (arr == 0) || ((n0 + row) < Nfull);
        if (!vld[p]) grow = 0;
        gp[p]   = base + (size_t)grow * K + c4 * 8;
        soff[p] = (unsigned int)(arr * ARR_B + (row * SROW + c4 * 8) * 2);
    }

#define ISSUE(stg, ks) do {                                             \
        unsigned int _sb = smem_u + (unsigned int)(stg) * STG_B;        \
        _Pragma("unroll")                                               \
        for (int p = 0; p < 6; p++)                                     \
            if (vld[p]) cp_async16(_sb + soff[p], gp[p] + (ks) * 32);   \
        cp_commit();                                                    \
    } while (0)

    const int nk = K / 32;
    ISSUE(0, 0);

    for (int s = 0; s < nk; s++) {
        if (s + 1 < nk) { ISSUE((s + 1) & 1, s + 1); cp_wait1(); }
        else            { cp_wait0(); }
        __syncthreads();

        const unsigned int sb = smem_u + (unsigned int)(s & 1) * STG_B;
#pragma unroll
        for (int kc = 0; kc < 32; kc += 16) {
            unsigned int bh[4][2], bl[4][2];
#pragma unroll
            for (int q = 0; q < 2; q++) {
                unsigned int brow = (unsigned int)(wn + q * 16 + (lane & 7) +
                                                   ((lane >> 4) << 3));
                unsigned int koff = (unsigned int)(((lane >> 3) & 1) * 8);
                unsigned int ab = sb + 1u * ARR_B + (brow * SROW + kc + koff) * 2;
                ldm_x4(bh[2*q][0], bh[2*q][1], bh[2*q+1][0], bh[2*q+1][1], ab);
                ldm_x4(bl[2*q][0], bl[2*q][1], bl[2*q+1][0], bl[2*q+1][1],
                       ab + ARR_B);
            }
#pragma unroll
            for (int mt = 0; mt < 4; mt++) {
                unsigned int arow = (unsigned int)(wm + mt * 16 + (lane & 15));
                unsigned int koff = (unsigned int)((lane >> 4) * 8);
                unsigned int aa = sb + (arow * SROW + kc + koff) * 2;
                unsigned int a0, a1, a2, a3;
                ldm_x4(a0, a1, a2, a3, aa);
#pragma unroll
                for (int nt = 0; nt < 4; nt++) {
                    mma_f16(acc[mt][nt][0], acc[mt][nt][1],
                            acc[mt][nt][2], acc[mt][nt][3],
                            a0, a1, a2, a3, bh[nt][0], bh[nt][1]);
                    mma_f16(acc[mt][nt][0], acc[mt][nt][1],
                            acc[mt][nt][2], acc[mt][nt][3],
                            a0, a1, a2, a3, bl[nt][0], bl[nt][1]);
                }
            }
        }
        __syncthreads();
    }
#undef ISSUE

    const int g = lane >> 2, tq = lane & 3;
#pragma unroll
    for (int mt = 0; mt < 4; mt++) {
        const int row = m0 + wm + mt * 16 + g;
#pragma unroll
        for (int nt = 0; nt < 4; nt++) {
            const int col = n0 + wn + nt * 8 + tq * 2;
            if (col < Nfull) {
                float b0 = bias[col], b1 = bias[col + 1];
                float2 o1; o1.x = acc[mt][nt][0] + b0; o1.y = acc[mt][nt][1] + b1;
                float2 o2v; o2v.x = acc[mt][nt][2] + b0; o2v.y = acc[mt][nt][3] + b1;
                *(float2*)(C + (size_t)row * Nfull + col) = o1;
                *(float2*)(C + (size_t)(row + 8) * Nfull + col) = o2v;
            }
        }
    }
}

// ---------------- TTT gradient kernel — HMMA (unchanged from R11) ----------------
#define TG_SMEM 73728
__global__ __launch_bounds__(256) void ttt_grad_kernel(
    const float* __restrict__ w1g, const float* __restrict__ w2g)
{
    extern __shared__ __half smh[];
    const unsigned int su  = smem_to_u32(smh);
    const unsigned int w1u = su;
    const unsigned int w2u = su + 4608u * 2;
    const unsigned int k1u = su + 9216u * 2;
    const unsigned int gAu = k1u + 9216u * 2;
    const unsigned int gBu = gAu + 9216u * 2;
    __half* w1T = smh;
    __half* w2T = smh + 4608;
    __half* k1h = smh + 9216;
    __half* gAh = smh + 9216 + 9216;
    __half* gBh = gAh + 9216;

    const int tid = threadIdx.x, lane = tid & 31, wid = tid >> 5;
    const int chunk = blockIdx.x, head = blockIdx.y, b = blockIdx.z;
    const int n0 = chunk * 128;

    for (int idx = tid; idx < 4096; idx += 256) {
        const int k = idx >> 6, n = idx & 63;
        w1T[n * 72 + k] = __float2half(w1g[head * 4096 + idx]);
        w2T[n * 72 + k] = __float2half(w2g[head * 4096 + idx]);
    }
    {
        const float* src = g_qkv + (size_t)(b * N_ + n0) * QC + C_ + head * HD_;
        const int row = tid >> 1, c8 = (tid & 1) * 32;
#pragma unroll
        for (int c = 0; c < 32; c += 4) {
            float4 v = *(const float4*)(src + (size_t)row * QC + c8 + c);
            *(__half2*)&k1h[row * 72 + c8 + c]     = __floats2half2_rn(v.x, v.y);
            *(__half2*)&k1h[row * 72 + c8 + c + 2] = __floats2half2_rn(v.z, v.w);
        }
    }
    __syncthreads();

    const int m0w = wid * 16;
    float accA[8][4], accB[8][4];
#pragma unroll
    for (int nt = 0; nt < 8; nt++)
#pragma unroll
        for (int c = 0; c < 4; c++) { accA[nt][c] = 0.f; accB[nt][c] = 0.f; }

#pragma unroll
    for (int kk = 0; kk < 4; kk++) {
        const unsigned int ak = (unsigned int)(kk * 16 + ((lane >> 4) << 3));
        const unsigned int aa = k1u + ((unsigned int)(m0w + (lane & 15)) * 72 + ak) * 2;
        unsigned int a0, a1, a2, a3;
        ldm_x4(a0, a1, a2, a3, aa);
        unsigned int b1[8][2], b2[8][2];
#pragma unroll
        for (int q = 0; q < 4; q++) {
            const unsigned int brow = (unsigned int)(q * 16 + (lane & 7) +
                                                     ((lane >> 4) << 3));
            const unsigned int bk = (unsigned int)(kk * 16 + ((lane >> 3) & 1) * 8);
            ldm_x4(b1[2*q][0], b1[2*q][1], b1[2*q+1][0], b1[2*q+1][1],
                   w1u + (brow * 72 + bk) * 2);
            ldm_x4(b2[2*q][0], b2[2*q][1], b2[2*q+1][0], b2[2*q+1][1],
                   w2u + (brow * 72 + bk) * 2);
        }
#pragma unroll
        for (int nt = 0; nt < 8; nt++) {
            mma_f16(accA[nt][0], accA[nt][1], accA[nt][2], accA[nt][3],
                    a0, a1, a2, a3, b1[nt][0], b1[nt][1]);
            mma_f16(accB[nt][0], accB[nt][1], accB[nt][2], accB[nt][3],
                    a0, a1, a2, a3, b2[nt][0], b2[nt][1]);
        }
    }

    const int g = lane >> 2, tq = lane & 3;
    const float* vbase = g_qkv + (size_t)(b * N_ + n0 + m0w) * QC + 2 * C_ + head * HD_;
#pragma unroll
    for (int nt = 0; nt < 8; nt++) {
        const int col = nt * 8 + tq * 2;
#pragma unroll
        for (int h = 0; h < 2; h++) {
            const int row = g + h * 8;
            float2 v = *(const float2*)(vbase + (size_t)row * QC + col);
            float Av0 = accA[nt][2*h + 0], Av1 = accA[nt][2*h + 1];
            float Bv0 = accB[nt][2*h + 0], Bv1 = accB[nt][2*h + 1];
            float sig0 = 1.f / (1.f + expf(-Bv0));
            float sig1 = 1.f / (1.f + expf(-Bv1));
            float sil0 = Bv0 * sig0, sil1 = Bv1 * sig1;
            float g0 = Av0 * sil0 - v.x;
            float g1 = Av1 * sil1 - v.y;
            float gA0 = g0 * sil0, gA1 = g1 * sil1;
            float gB0 = g0 * Av0 * sig0 * (1.f + Bv0 * (1.f - sig0));
            float gB1 = g1 * Av1 * sig1 * (1.f + Bv1 * (1.f - sig1));
            *(__half2*)&gAh[(m0w + row) * 72 + col] = __floats2half2_rn(gA0, gA1);
            *(__half2*)&gBh[(m0w + row) * 72 + col] = __floats2half2_rn(gB0, gB1);
        }
    }
    __syncthreads();

    const int mt = wid >> 1;
    const int nh = (wid & 1) * 32;
    float r1[4][4], r2[4][4];
#pragma unroll
    for (int nt = 0; nt < 4; nt++)
#pragma unroll
        for (int c = 0; c < 4; c++) { r1[nt][c] = 0.f; r2[nt][c] = 0.f; }

#pragma unroll
    for (int ks = 0; ks < 8; ks++) {
        const int k0 = ks * 16;
        const unsigned int arow = (unsigned int)(k0 + ((lane >> 4) << 3) + (lane & 7));
        const unsigned int acol = (unsigned int)(mt * 16 + (((lane >> 3) & 1) << 3));
        unsigned int a0, a1, a2, a3;
        ldm_x4t(a0, a1, a2, a3, k1u + (arow * 72 + acol) * 2);
        unsigned int bA[4][2], bB[4][2];
#pragma unroll
        for (int q = 0; q < 2; q++) {
            const unsigned int brow = (unsigned int)(k0 + (((lane >> 3) & 1) << 3) +
                                                     (lane & 7));
            const unsigned int bcol = (unsigned int)(nh + q * 16 + ((lane >> 4) << 3));
            ldm_x4t(bA[2*q][0], bA[2*q][1], bA[2*q+1][0], bA[2*q+1][1],
                    gAu + (brow * 72 + bcol) * 2);
            ldm_x4t(bB[2*q][0], bB[2*q][1], bB[2*q+1][0], bB[2*q+1][1],
                    gBu + (brow * 72 + bcol) * 2);
        }
#pragma unroll
        for (int nt = 0; nt < 4; nt++) {
            mma_f16(r1[nt][0], r1[nt][1], r1[nt][2], r1[nt][3],
                    a0, a1, a2, a3, bA[nt][0], bA[nt][1]);
            mma_f16(r2[nt][0], r2[nt][1], r2[nt][2], r2[nt][3],
                    a0, a1, a2, a3, bB[nt][0], bB[nt][1]);
        }
    }

    const int pidx = b * 8 + chunk;
    float* d1 = g_gw_part + ((size_t)(0 * NH + head) * 128 + pidx) * 4096;
    float* d2 = g_gw_part + ((size_t)(1 * NH + head) * 128 + pidx) * 4096;
#pragma unroll
    for (int nt = 0; nt < 4; nt++) {
        const int row = mt * 16 + g;
        const int col = nh + nt * 8 + tq * 2;
        float2 p;
        p.x = r1[nt][0] * M1_INV; p.y = r1[nt][1] * M1_INV;
        *(float2*)&d1[row * 64 + col] = p;
        p.x = r1[nt][2] * M1_INV; p.y = r1[nt][3] * M1_INV;
        *(float2*)&d1[(row + 8) * 64 + col] = p;
        p.x = r2[nt][0] * M1_INV; p.y = r2[nt][1] * M1_INV;
        *(float2*)&d2[row * 64 + col] = p;
        p.x = r2[nt][2] * M1_INV; p.y = r2[nt][3] * M1_INV;
        *(float2*)&d2[(row + 8) * 64 + col] = p;
    }
}

// ---------------- TTT forward kernel — HMMA, 3-term hi/lo split ----------------
// SMEM (fp16, stride 72): w1h/w1l/w2h/w2l[64][72] (transposed), q1h/q1l[128][72].
// Total 4*4608 + 2*9216 = 36864 halves = 73728 B.
#define TF_SMEM 73728
__global__ __launch_bounds__(256) void ttt_fwd_kernel()
{
    extern __shared__ __half smh[];
    const unsigned int su   = smem_to_u32(smh);
    const unsigned int w1hu = su;
    const unsigned int w1lu = su + 4608u * 2;
    const unsigned int w2hu = su + 9216u * 2;
    const unsigned int w2lu = su + 13824u * 2;
    const unsigned int q1hu = su + 18432u * 2;
    const unsigned int q1lu = su + 27648u * 2;
    __half* w1h = smh;
    __half* w1l = smh + 4608;
    __half* w2h = smh + 9216;
    __half* w2l = smh + 13824;
    __half* q1h = smh + 18432;
    __half* q1l = smh + 27648;

    const int tid = threadIdx.x, lane = tid & 31, wid = tid >> 5;
    const int chunk = blockIdx.x, head = blockIdx.y, b = blockIdx.z;
    const int n0 = chunk * 128;

    // weights: transpose + split
    for (int idx = tid; idx < 4096; idx += 256) {
        const int k = idx >> 6, n = idx & 63;
        float v1 = g_mw1[head * 4096 + idx];
        float v2 = g_mw2[head * 4096 + idx];
        __half h1 = __float2half(v1), h2 = __float2half(v2);
        w1h[n * 72 + k] = h1;
        w1l[n * 72 + k] = __float2half(v1 - __half2float(h1));
        w2h[n * 72 + k] = h2;
        w2l[n * 72 + k] = __float2half(v2 - __half2float(h2));
    }
    // q1: split
    {
        const float* src = g_qkv + (size_t)(b * N_ + n0) * QC + head * HD_;
        const int row = tid >> 1, c8 = (tid & 1) * 32;
#pragma unroll
        for (int c = 0; c < 32; c += 2) {
            float2 v = *(const float2*)(src + (size_t)row * QC + c8 + c);
            __half h0 = __float2half(v.x), h1 = __float2half(v.y);
            *(__half2*)&q1h[row * 72 + c8 + c] =
                __halves2half2(h0, h1);
            *(__half2*)&q1l[row * 72 + c8 + c] =
                __floats2half2_rn(v.x - __half2float(h0), v.y - __half2float(h1));
        }
    }
    __syncthreads();

    // each warp: 16 rows x 64 cols, A = q1@w1, B = q1@w2, 3-term
    const int m0w = wid * 16;
    float accA[8][4], accB[8][4];
#pragma unroll
    for (int nt = 0; nt < 8; nt++)
#pragma unroll
        for (int c = 0; c < 4; c++) { accA[nt][c] = 0.f; accB[nt][c] = 0.f; }

#pragma unroll
    for (int kk = 0; kk < 4; kk++) {
        const unsigned int ak = (unsigned int)(kk * 16 + ((lane >> 4) << 3));
        const unsigned int ao = ((unsigned int)(m0w + (lane & 15)) * 72 + ak) * 2;
        unsigned int ah0, ah1, ah2, ah3, al0, al1, al2, al3;
        ldm_x4(ah0, ah1, ah2, ah3, q1hu + ao);
        ldm_x4(al0, al1, al2, al3, q1lu + ao);
        unsigned int b1h[8][2], b1l[8][2], b2h[8][2], b2l[8][2];
#pragma unroll
        for (int q = 0; q < 4; q++) {
            const unsigned int brow = (unsigned int)(q * 16 + (lane & 7) +
                                                     ((lane >> 4) << 3));
            const unsigned int bk = (unsigned int)(kk * 16 + ((lane >> 3) & 1) * 8);
            const unsigned int bo = (brow * 72 + bk) * 2;
            ldm_x4(b1h[2*q][0], b1h[2*q][1], b1h[2*q+1][0], b1h[2*q+1][1], w1hu + bo);
            ldm_x4(b1l[2*q][0], b1l[2*q][1], b1l[2*q+1][0], b1l[2*q+1][1], w1lu + bo);
            ldm_x4(b2h[2*q][0], b2h[2*q][1], b2h[2*q+1][0], b2h[2*q+1][1], w2hu + bo);
            ldm_x4(b2l[2*q][0], b2l[2*q][1], b2l[2*q+1][0], b2l[2*q+1][1], w2lu + bo);
        }
#pragma unroll
        for (int nt = 0; nt < 8; nt++) {
            mma_f16(accA[nt][0], accA[nt][1], accA[nt][2], accA[nt][3],
                    ah0, ah1, ah2, ah3, b1h[nt][0], b1h[nt][1]);
            mma_f16(accA[nt][0], accA[nt][1], accA[nt][2], accA[nt][3],
                    ah0, ah1, ah2, ah3, b1l[nt][0], b1l[nt][1]);
            mma_f16(accA[nt][0], accA[nt][1], accA[nt][2], accA[nt][3],
                    al0, al1, al2, al3, b1h[nt][0], b1h[nt][1]);
            mma_f16(accB[nt][0], accB[nt][1], accB[nt][2], accB[nt][3],
                    ah0, ah1, ah2, ah3, b2h[nt][0], b2h[nt][1]);
            mma_f16(accB[nt][0], accB[nt][1], accB[nt][2], accB[nt][3],
                    ah0, ah1, ah2, ah3, b2l[nt][0], b2l[nt][1]);
            mma_f16(accB[nt][0], accB[nt][1], accB[nt][2], accB[nt][3],
                    al0, al1, al2, al3, b2h[nt][0], b2h[nt][1]);
        }
    }

    // epilogue: silu, write fp16 to g_xch
    const int g = lane >> 2, tq = lane & 3;
    __half* obase = g_xch + (size_t)(b * N_ + n0 + m0w) * XC + head * HD_;
#pragma unroll
    for (int nt = 0; nt < 8; nt++) {
        const int col = nt * 8 + tq * 2;
#pragma unroll
        for (int h = 0; h < 2; h++) {
            const int row = g + h * 8;
            float Av0 = accA[nt][2*h + 0], Av1 = accA[nt][2*h + 1];
            float Bv0 = accB[nt][2*h + 0], Bv1 = accB[nt][2*h + 1];
            float sig0 = 1.f / (1.f + expf(-Bv0));
            float sig1 = 1.f / (1.f + expf(-Bv1));
            float o0 = Av0 * (Bv0 * sig0);
            float o1 = Av1 * (Bv1 * sig1);
            *(__half2*)(obase + (size_t)row * XC + col) = __floats2half2_rn(o0, o1);
        }
    }
}

// ---------------- conv grad ----------------
__global__ __launch_bounds__(256) void conv_grad_kernel(const float* __restrict__ w3g)
{
    const int bc = blockIdx.x;
    const int b = bc >> 6, c = bc & 63;
    const int tid = threadIdx.x;
    __shared__ float k2s[32][33];
    __shared__ float wk[9];
    __shared__ float red[256];

    if (tid < 9) wk[tid] = w3g[c * 9 + tid];
    const float* base = g_qkv + (size_t)(b * N_) * QC;
    for (int p = tid; p < 1024; p += 256)
        k2s[p >> 5][p & 31] = base[(size_t)p * QC + 2368 + c];
    __syncthreads();

    float acc[9];
#pragma unroll
    for (int q = 0; q < 9; q++) acc[q] = 0.f;

    for (int p = tid; p < 1024; p += 256) {
        const int y = p >> 5, x = p & 31;
        float t[9];
#pragma unroll
        for (int dy = 0; dy < 3; dy++)
#pragma unroll
            for (int dx = 0; dx < 3; dx++) {
                int yy = y + dy - 1, xx = x + dx - 1;
                t[dy * 3 + dx] = (yy >= 0 && yy < 32 && xx >= 0 && xx < 32)
                                 ? k2s[yy][xx] : 0.f;
            }
        float f = 0.f;
#pragma unroll
        for (int q = 0; q < 9; q++) f = fmaf(wk[q], t[q], f);
        float v = base[(size_t)p * QC + 2432 + c];
        float g = (f - v) * M2_INV;
#pragma unroll
        for (int q = 0; q < 9; q++) acc[q] = fmaf(g, t[q], acc[q]);
    }

    for (int q = 0; q < 9; q++) {
        red[tid] = acc[q];
        __syncthreads();
        for (int s = 128; s > 0; s >>= 1) {
            if (tid < s) red[tid] += red[tid + s];
            __syncthreads();
        }
        if (tid == 0) g_gw3_part[(size_t)bc * 9 + q] = red[0];
        __syncthreads();
    }
}

__global__ void conv_grad_reduce_kernel()
{
    const int tid = threadIdx.x;
    __shared__ float red[576];
    float s = 0.f;
    const int c = tid / 9, q = tid % 9;
    for (int b = 0; b < B_; b++) s += g_gw3_part[(size_t)(b * 64 + c) * 9 + q];
    g_gw3[tid] = s;
    red[tid] = s * s;
    __syncthreads();
    if (tid < 64) red[tid] += red[tid + 512];
    __syncthreads();
    for (int st = 256; st > 0; st >>= 1) {
        if (tid < st && tid + st < 576) red[tid] += red[tid + st];
        __syncthreads();
    }
    if (tid == 0) g_sumsq[24] = red[0];
}

// ---------------- two-stage gw reduce ----------------
__global__ __launch_bounds__(256) void reduce_gw_stage1()
{
    const int th = blockIdx.x >> 3;
    const int g  = blockIdx.x & 7;
    const int tid = threadIdx.x;
    const float* src = g_gw_part + ((size_t)th * 128 + g * 16) * 4096;
    float s[16];
#pragma unroll
    for (int q = 0; q < 16; q++) s[q] = 0.f;
    for (int p = 0; p < 16; p++) {
        const float* row = src + (size_t)p * 4096 + tid;
#pragma unroll
        for (int q = 0; q < 16; q++) s[q] += row[q * 256];
    }
    float* dst = g_gw_stage + (size_t)(th * 8 + g) * 4096 + tid;
#pragma unroll
    for (int q = 0; q < 16; q++) dst[q * 256] = s[q];
}

__global__ __launch_bounds__(256) void reduce_gw_stage2()
{
    const int th  = blockIdx.x;
    const int tid = threadIdx.x;
    const float* src = g_gw_stage + (size_t)th * 8 * 4096;
    float* dst = g_gw + (size_t)th * 4096;

    float s[16];
#pragma unroll
    for (int q = 0; q < 16; q++) s[q] = 0.f;
    for (int p = 0; p < 8; p++) {
        const float* row = src + (size_t)p * 4096 + tid;
#pragma unroll
        for (int q = 0; q < 16; q++) s[q] += row[q * 256];
    }
    float ss = 0.f;
#pragma unroll
    for (int q = 0; q < 16; q++) { dst[tid + q * 256] = s[q]; ss += s[q] * s[q]; }

    __shared__ float red[256];
    red[tid] = ss;
    __syncthreads();
    for (int st = 128; st > 0; st >>= 1) {
        if (tid < st) red[tid] += red[tid + st];
        __syncthreads();
    }
    if (tid == 0) g_sumsq[th] = red[0];
}

// ---------------- weight update (scales fused) ----------------
__global__ void update_w_kernel(const float* __restrict__ w1g,
                                const float* __restrict__ w2g,
                                const float* __restrict__ w3g)
{
    __shared__ float sc[3];
    if (threadIdx.x == 0) {
        float s1 = 0.f, s2 = 0.f;
        for (int h = 0; h < NH; h++) { s1 += g_sumsq[h]; s2 += g_sumsq[NH + h]; }
        sc[0] = LR_ / (sqrtf(s1) + 1.f);
        sc[1] = LR_ / (sqrtf(s2) + 1.f);
        sc[2] = LR_ / (sqrtf(g_sumsq[24]) + 1.f);
    }
    __syncthreads();
    const int i = blockIdx.x * 256 + threadIdx.x;
    if (i < 49152) {
        g_mw1[i] = w1g[i] - sc[0] * g_gw[i];
    } else if (i < 98304) {
        const int k = i - 49152;
        g_mw2[k] = w2g[k] - sc[1] * g_gw[49152 + k];
    } else if (i < 98880) {
        const int k = i - 98304;
        g_mw3[k] = w3g[k] - sc[2] * g_gw3[k];
    }
}

// ---------------- conv forward (writes fp16 hi directly) ----------------
__global__ __launch_bounds__(256) void conv_fwd_kernel()
{
    const int bc = blockIdx.x;
    const int b = bc >> 6, c = bc & 63;
    const int tid = threadIdx.x;
    __shared__ float q2s[32][33];
    __shared__ float wk[9];
    if (tid < 9) wk[tid] = g_mw3[c * 9 + tid];
    const float* base = g_qkv + (size_t)(b * N_) * QC;
    for (int p = tid; p < 1024; p += 256)
        q2s[p >> 5][p & 31] = base[(size_t)p * QC + 2304 + c];
    __syncthreads();

    for (int p = tid; p < 1024; p += 256) {
        const int y = p >> 5, x = p & 31;
        float f = 0.f;
#pragma unroll
        for (int dy = 0; dy < 3; dy++)
#pragma unroll
            for (int dx = 0; dx < 3; dx++) {
                int yy = y + dy - 1, xx = x + dx - 1;
                if (yy >= 0 && yy < 32 && xx >= 0 && xx < 32)
                    f = fmaf(wk[dy * 3 + dx], q2s[yy][xx], f);
            }
        g_xch[(size_t)(b * N_ + p) * XC + 768 + c] = __float2half(f);
    }
}

// ---------------- launch ----------------
extern "C" void kernel_launch(void* const* d_in, const int* in_sizes, int n_in,
                              void* d_out, int out_size)
{
    const float *x = nullptr, *Wqkv = nullptr, *bqkv = nullptr, *w1 = nullptr,
                *w2 = nullptr, *w3 = nullptr, *Wproj = nullptr, *bproj = nullptr;
    for (int i = 0; i < n_in; i++) {
        const int s = in_sizes[i];
        const float* p = (const float*)d_in[i];
        if      (s == B_*N_*C_)   x = p;
        else if (s == C_*QC)      Wqkv = p;
        else if (s == QC)         bqkv = p;
        else if (s == NH*HD_*HD_) { if (!w1) w1 = p; else w2 = p; }
        else if (s == 64*9)       w3 = p;
        else if (s == XC*C_)      Wproj = p;
        else if (s == C_)         bproj = p;
    }

    float* qkv_ptr = nullptr;
    __half *xh, *xch, *wqh, *wql, *wph, *wpl;
    cudaGetSymbolAddress((void**)&qkv_ptr, g_qkv);
    cudaGetSymbolAddress((void**)&xh,  g_xh);
    cudaGetSymbolAddress((void**)&xch, g_xch);
    cudaGetSymbolAddress((void**)&wqh, g_wqh);
    cudaGetSymbolAddress((void**)&wql, g_wql);
    cudaGetSymbolAddress((void**)&wph, g_wph);
    cudaGetSymbolAddress((void**)&wpl, g_wpl);

    cudaFuncSetAttribute(ttt_grad_kernel,
        cudaFuncAttributeMaxDynamicSharedMemorySize, TG_SMEM);
    cudaFuncSetAttribute(ttt_fwd_kernel,
        cudaFuncAttributeMaxDynamicSharedMemorySize, TF_SMEM);
    cudaFuncSetAttribute(tc_gemm,
        cudaFuncAttributeMaxDynamicSharedMemorySize, TCG_SMEM);

    // 1. convert x (hi only), transpose+split weights (hi/lo)
    convert_f16<<<(B_*N_*C_/4 + 255)/256, 256>>>(x, xh, B_*N_*C_/4);
    transpose_split<<<dim3(QC/32, C_/32), 256>>>(Wqkv, wqh, wql, C_, QC);
    transpose_split<<<dim3(C_/32, XC/32), 256>>>(Wproj, wph, wpl, XC, C_);

    // 2. qkv = x @ Wqkv + bqkv
    tc_gemm<<<dim3((QC + 127)/128, (B_*N_)/128), 256, TCG_SMEM>>>(
        xh, wqh, wql, bqkv, qkv_ptr, QC, C_);

    // 3. TTT (HMMA) + conv gradients, reduce, update
    ttt_grad_kernel<<<dim3(8, NH, B_), 256, TG_SMEM>>>(w1, w2);
    conv_grad_kernel<<<B_ * 64, 256>>>(w3);
    conv_grad_reduce_kernel<<<1, 576>>>();
    reduce_gw_stage1<<<192, 256>>>();
    reduce_gw_stage2<<<24, 256>>>();
    update_w_kernel<<<(98880 + 255)/256, 256>>>(w1, w2, w3);

    // 4. post-update forward (HMMA, 3-term split)
    ttt_fwd_kernel<<<dim3(8, NH, B_), 256, TF_SMEM>>>();
    conv_fwd_kernel<<<B_ * 64, 256>>>();

    // 5. proj GEMM
    tc_gemm<<<dim3(C_/128, (B_*N_)/128), 256, TCG_SMEM>>>(
        xch, wph, wpl, bproj, (float*)d_out, C_, XC);
}

// round 13
// speedup vs baseline: 1.8143x; 1.2330x over previous
#include <cuda_runtime.h>
#include <cuda_bf16.h>
#include <cuda_fp16.h>
#include <cstdint>
#include <cstdio>
#include <math.h>

#define B_  16
#define N_  1024
#define C_  768
#define NH  12
#define HD_ 64
#define QC  2496   // 3*768 + 3*64
#define XC  832    // 768 + 64
#define M1_INV (1.0f/12582912.0f)
#define M2_INV (1.0f/1048576.0f)
#define LR_ 0.001f

// ---------------- scratch ----------------
__device__ float g_qkv[B_*N_*QC];
__device__ float g_gw_part[2*NH*128*HD_*HD_];
__device__ float g_gw_stage[24*8*HD_*HD_];
__device__ float g_gw[2*NH*HD_*HD_];
__device__ float g_gw3_part[B_*64*9];
__device__ float g_gw3[64*9];
__device__ float g_sumsq[25];
__device__ float g_mw1[NH*HD_*HD_];
__device__ float g_mw2[NH*HD_*HD_];
__device__ float g_mw3[64*9];
// fp16 operands (plain fp16, no splits)
__device__ __half g_xh[B_*N_*C_];
__device__ __half g_xch[B_*N_*XC];
__device__ __half g_wqh[QC*C_];   // [N=2496][K=768]
__device__ __half g_wph[C_*XC];   // [N=768][K=832]

// ---------------- PTX helpers ----------------
__device__ __forceinline__ unsigned int smem_to_u32(const void* smem_ptr) {
    unsigned int addr;
    asm("{ .reg .u64 tmp; cvta.to.shared.u64 tmp, %1; cvt.u32.u64 %0, tmp; }"
        : "=r"(addr) : "l"(smem_ptr));
    return addr;
}
__device__ __forceinline__ void cp_async16(unsigned int saddr, const void* gaddr) {
    asm volatile("cp.async.cg.shared.global [%0], [%1], 16;"
                 :: "r"(saddr), "l"(gaddr) : "memory");
}
__device__ __forceinline__ void cp_commit() {
    asm volatile("cp.async.commit_group;" ::: "memory");
}
__device__ __forceinline__ void cp_wait1() {
    asm volatile("cp.async.wait_group 1;" ::: "memory");
}
__device__ __forceinline__ void cp_wait0() {
    asm volatile("cp.async.wait_group 0;" ::: "memory");
}
__device__ __forceinline__ void ldm_x4(unsigned int& r0, unsigned int& r1,
                                       unsigned int& r2, unsigned int& r3,
                                       unsigned int a) {
    asm volatile("ldmatrix.sync.aligned.m8n8.x4.shared.b16 {%0,%1,%2,%3}, [%4];"
                 : "=r"(r0), "=r"(r1), "=r"(r2), "=r"(r3) : "r"(a));
}
__device__ __forceinline__ void ldm_x4t(unsigned int& r0, unsigned int& r1,
                                        unsigned int& r2, unsigned int& r3,
                                        unsigned int a) {
    asm volatile("ldmatrix.sync.aligned.m8n8.x4.trans.shared.b16 {%0,%1,%2,%3}, [%4];"
                 : "=r"(r0), "=r"(r1), "=r"(r2), "=r"(r3) : "r"(a));
}
__device__ __forceinline__ void mma_f16(float& c0, float& c1, float& c2, float& c3,
                                        unsigned int a0, unsigned int a1,
                                        unsigned int a2, unsigned int a3,
                                        unsigned int b0, unsigned int b1) {
    asm volatile("mma.sync.aligned.m16n8k16.row.col.f32.f16.f16.f32 "
                 "{%0,%1,%2,%3}, {%4,%5,%6,%7}, {%8,%9}, {%0,%1,%2,%3};"
                 : "+f"(c0), "+f"(c1), "+f"(c2), "+f"(c3)
                 : "r"(a0), "r"(a1), "r"(a2), "r"(a3), "r"(b0), "r"(b1));
}

// ---------------- conversions ----------------
__device__ __forceinline__ unsigned int pack_h2(__half a, __half b) {
    return (unsigned int)__half_as_ushort(a) |
           ((unsigned int)__half_as_ushort(b) << 16);
}
__global__ __launch_bounds__(256) void convert_f16(
    const float* __restrict__ X, __half* __restrict__ H, int n4)
{
    int i = blockIdx.x * 256 + threadIdx.x;
    if (i >= n4) return;
    float4 v = ((const float4*)X)[i];
    uint2 hh;
    hh.x = pack_h2(__float2half(v.x), __float2half(v.y));
    hh.y = pack_h2(__float2half(v.z), __float2half(v.w));
    ((uint2*)H)[i] = hh;
}
// W[K][N] -> T[N][K] fp16 (no split)
__global__ __launch_bounds__(256) void transpose_f16(
    const float* __restrict__ W, __half* __restrict__ Th, int K, int N)
{
    __shared__ float s[32][33];
    const int n0 = blockIdx.x * 32, k0 = blockIdx.y * 32;
    const int tx = threadIdx.x & 31, ty = threadIdx.x >> 5;
    for (int r = ty; r < 32; r += 8)
        s[r][tx] = W[(size_t)(k0 + r) * N + n0 + tx];
    __syncthreads();
    for (int r = ty; r < 32; r += 8)
        Th[(size_t)(n0 + r) * K + k0 + tx] = __float2half(s[tx][r]);
}

// ---------------- HMMA GEMM (plain fp16) ----------------
#define SROW   40
#define ARR_B  (128*SROW*2)
#define STG_B  (2*ARR_B)
#define TCG_SMEM (2*STG_B)        // 40960

__global__ __launch_bounds__(256) void tc_gemm(
    const __half* __restrict__ Ah, const __half* __restrict__ Bh,
    const float* __restrict__ bias, float* __restrict__ C,
    int Nfull, int K)
{
    extern __shared__ __half smb[];
    const unsigned int smem_u = smem_to_u32(smb);
    const int t = threadIdx.x, lane = t & 31, wid = t >> 5;
    const int m0 = blockIdx.y * 128, n0 = blockIdx.x * 128;
    const int wm = (wid >> 2) * 64, wn = (wid & 3) * 32;

    float acc[4][4][4];
#pragma unroll
    for (int a = 0; a < 4; a++)
#pragma unroll
        for (int b = 0; b < 4; b++)
#pragma unroll
            for (int c = 0; c < 4; c++) acc[a][b][c] = 0.f;

    // load plan: 1024 16B-chunks per stage, 4 per thread
    const __half* gp[4];
    unsigned int soff[4];
    bool vld[4];
#pragma unroll
    for (int p = 0; p < 4; p++) {
        int c = p * 256 + t;
        int arr = c >> 9, rem = c & 511, row = rem >> 2, c4 = rem & 3;
        const __half* base = (arr == 0) ? Ah : Bh;
        int grow = (arr == 0) ? (m0 + row) : (n0 + row);
        vld[p]  = (arr == 0) || ((n0 + row) < Nfull);
        if (!vld[p]) grow = 0;
        gp[p]   = base + (size_t)grow * K + c4 * 8;
        soff[p] = (unsigned int)(arr * ARR_B + (row * SROW + c4 * 8) * 2);
    }

#define ISSUE(stg, ks) do {                                             \
        unsigned int _sb = smem_u + (unsigned int)(stg) * STG_B;        \
        _Pragma("unroll")                                               \
        for (int p = 0; p < 4; p++)                                     \
            if (vld[p]) cp_async16(_sb + soff[p], gp[p] + (ks) * 32);   \
        cp_commit();                                                    \
    } while (0)

    const int nk = K / 32;
    ISSUE(0, 0);

    for (int s = 0; s < nk; s++) {
        if (s + 1 < nk) { ISSUE((s + 1) & 1, s + 1); cp_wait1(); }
        else            { cp_wait0(); }
        __syncthreads();

        const unsigned int sb = smem_u + (unsigned int)(s & 1) * STG_B;
#pragma unroll
        for (int kc = 0; kc < 32; kc += 16) {
            unsigned int bh[4][2];
#pragma unroll
            for (int q = 0; q < 2; q++) {
                unsigned int brow = (unsigned int)(wn + q * 16 + (lane & 7) +
                                                   ((lane >> 4) << 3));
                unsigned int koff = (unsigned int)(((lane >> 3) & 1) * 8);
                unsigned int ab = sb + 1u * ARR_B + (brow * SROW + kc + koff) * 2;
                ldm_x4(bh[2*q][0], bh[2*q][1], bh[2*q+1][0], bh[2*q+1][1], ab);
            }
#pragma unroll
            for (int mt = 0; mt < 4; mt++) {
                unsigned int arow = (unsigned int)(wm + mt * 16 + (lane & 15));
                unsigned int koff = (unsigned int)((lane >> 4) * 8);
                unsigned int aa = sb + (arow * SROW + kc + koff) * 2;
                unsigned int a0, a1, a2, a3;
                ldm_x4(a0, a1, a2, a3, aa);
#pragma unroll
                for (int nt = 0; nt < 4; nt++)
                    mma_f16(acc[mt][nt][0], acc[mt][nt][1],
                            acc[mt][nt][2], acc[mt][nt][3],
                            a0, a1, a2, a3, bh[nt][0], bh[nt][1]);
            }
        }
        __syncthreads();
    }
#undef ISSUE

    const int g = lane >> 2, tq = lane & 3;
#pragma unroll
    for (int mt = 0; mt < 4; mt++) {
        const int row = m0 + wm + mt * 16 + g;
#pragma unroll
        for (int nt = 0; nt < 4; nt++) {
            const int col = n0 + wn + nt * 8 + tq * 2;
            if (col < Nfull) {
                float b0 = bias[col], b1 = bias[col + 1];
                float2 o1; o1.x = acc[mt][nt][0] + b0; o1.y = acc[mt][nt][1] + b1;
                float2 o2v; o2v.x = acc[mt][nt][2] + b0; o2v.y = acc[mt][nt][3] + b1;
                *(float2*)(C + (size_t)row * Nfull + col) = o1;
                *(float2*)(C + (size_t)(row + 8) * Nfull + col) = o2v;
            }
        }
    }
}

// ---------------- TTT gradient kernel — HMMA (unchanged from R11/R12) ----------
#define TG_SMEM 73728
__global__ __launch_bounds__(256) void ttt_grad_kernel(
    const float* __restrict__ w1g, const float* __restrict__ w2g)
{
    extern __shared__ __half smh[];
    const unsigned int su  = smem_to_u32(smh);
    const unsigned int w1u = su;
    const unsigned int w2u = su + 4608u * 2;
    const unsigned int k1u = su + 9216u * 2;
    const unsigned int gAu = k1u + 9216u * 2;
    const unsigned int gBu = gAu + 9216u * 2;
    __half* w1T = smh;
    __half* w2T = smh + 4608;
    __half* k1h = smh + 9216;
    __half* gAh = smh + 9216 + 9216;
    __half* gBh = gAh + 9216;

    const int tid = threadIdx.x, lane = tid & 31, wid = tid >> 5;
    const int chunk = blockIdx.x, head = blockIdx.y, b = blockIdx.z;
    const int n0 = chunk * 128;

    for (int idx = tid; idx < 4096; idx += 256) {
        const int k = idx >> 6, n = idx & 63;
        w1T[n * 72 + k] = __float2half(w1g[head * 4096 + idx]);
        w2T[n * 72 + k] = __float2half(w2g[head * 4096 + idx]);
    }
    {
        const float* src = g_qkv + (size_t)(b * N_ + n0) * QC + C_ + head * HD_;
        const int row = tid >> 1, c8 = (tid & 1) * 32;
#pragma unroll
        for (int c = 0; c < 32; c += 4) {
            float4 v = *(const float4*)(src + (size_t)row * QC + c8 + c);
            *(__half2*)&k1h[row * 72 + c8 + c]     = __floats2half2_rn(v.x, v.y);
            *(__half2*)&k1h[row * 72 + c8 + c + 2] = __floats2half2_rn(v.z, v.w);
        }
    }
    __syncthreads();

    const int m0w = wid * 16;
    float accA[8][4], accB[8][4];
#pragma unroll
    for (int nt = 0; nt < 8; nt++)
#pragma unroll
        for (int c = 0; c < 4; c++) { accA[nt][c] = 0.f; accB[nt][c] = 0.f; }

#pragma unroll
    for (int kk = 0; kk < 4; kk++) {
        const unsigned int ak = (unsigned int)(kk * 16 + ((lane >> 4) << 3));
        const unsigned int aa = k1u + ((unsigned int)(m0w + (lane & 15)) * 72 + ak) * 2;
        unsigned int a0, a1, a2, a3;
        ldm_x4(a0, a1, a2, a3, aa);
        unsigned int b1[8][2], b2[8][2];
#pragma unroll
        for (int q = 0; q < 4; q++) {
            const unsigned int brow = (unsigned int)(q * 16 + (lane & 7) +
                                                     ((lane >> 4) << 3));
            const unsigned int bk = (unsigned int)(kk * 16 + ((lane >> 3) & 1) * 8);
            ldm_x4(b1[2*q][0], b1[2*q][1], b1[2*q+1][0], b1[2*q+1][1],
                   w1u + (brow * 72 + bk) * 2);
            ldm_x4(b2[2*q][0], b2[2*q][1], b2[2*q+1][0], b2[2*q+1][1],
                   w2u + (brow * 72 + bk) * 2);
        }
#pragma unroll
        for (int nt = 0; nt < 8; nt++) {
            mma_f16(accA[nt][0], accA[nt][1], accA[nt][2], accA[nt][3],
                    a0, a1, a2, a3, b1[nt][0], b1[nt][1]);
            mma_f16(accB[nt][0], accB[nt][1], accB[nt][2], accB[nt][3],
                    a0, a1, a2, a3, b2[nt][0], b2[nt][1]);
        }
    }

    const int g = lane >> 2, tq = lane & 3;
    const float* vbase = g_qkv + (size_t)(b * N_ + n0 + m0w) * QC + 2 * C_ + head * HD_;
#pragma unroll
    for (int nt = 0; nt < 8; nt++) {
        const int col = nt * 8 + tq * 2;
#pragma unroll
        for (int h = 0; h < 2; h++) {
            const int row = g + h * 8;
            float2 v = *(const float2*)(vbase + (size_t)row * QC + col);
            float Av0 = accA[nt][2*h + 0], Av1 = accA[nt][2*h + 1];
            float Bv0 = accB[nt][2*h + 0], Bv1 = accB[nt][2*h + 1];
            float sig0 = 1.f / (1.f + expf(-Bv0));
            float sig1 = 1.f / (1.f + expf(-Bv1));
            float sil0 = Bv0 * sig0, sil1 = Bv1 * sig1;
            float g0 = Av0 * sil0 - v.x;
            float g1 = Av1 * sil1 - v.y;
            float gA0 = g0 * sil0, gA1 = g1 * sil1;
            float gB0 = g0 * Av0 * sig0 * (1.f + Bv0 * (1.f - sig0));
            float gB1 = g1 * Av1 * sig1 * (1.f + Bv1 * (1.f - sig1));
            *(__half2*)&gAh[(m0w + row) * 72 + col] = __floats2half2_rn(gA0, gA1);
            *(__half2*)&gBh[(m0w + row) * 72 + col] = __floats2half2_rn(gB0, gB1);
        }
    }
    __syncthreads();

    const int mt = wid >> 1;
    const int nh = (wid & 1) * 32;
    float r1[4][4], r2[4][4];
#pragma unroll
    for (int nt = 0; nt < 4; nt++)
#pragma unroll
        for (int c = 0; c < 4; c++) { r1[nt][c] = 0.f; r2[nt][c] = 0.f; }

#pragma unroll
    for (int ks = 0; ks < 8; ks++) {
        const int k0 = ks * 16;
        const unsigned int arow = (unsigned int)(k0 + ((lane >> 4) << 3) + (lane & 7));
        const unsigned int acol = (unsigned int)(mt * 16 + (((lane >> 3) & 1) << 3));
        unsigned int a0, a1, a2, a3;
        ldm_x4t(a0, a1, a2, a3, k1u + (arow * 72 + acol) * 2);
        unsigned int bA[4][2], bB[4][2];
#pragma unroll
        for (int q = 0; q < 2; q++) {
            const unsigned int brow = (unsigned int)(k0 + (((lane >> 3) & 1) << 3) +
                                                     (lane & 7));
            const unsigned int bcol = (unsigned int)(nh + q * 16 + ((lane >> 4) << 3));
            ldm_x4t(bA[2*q][0], bA[2*q][1], bA[2*q+1][0], bA[2*q+1][1],
                    gAu + (brow * 72 + bcol) * 2);
            ldm_x4t(bB[2*q][0], bB[2*q][1], bB[2*q+1][0], bB[2*q+1][1],
                    gBu + (brow * 72 + bcol) * 2);
        }
#pragma unroll
        for (int nt = 0; nt < 4; nt++) {
            mma_f16(r1[nt][0], r1[nt][1], r1[nt][2], r1[nt][3],
                    a0, a1, a2, a3, bA[nt][0], bA[nt][1]);
            mma_f16(r2[nt][0], r2[nt][1], r2[nt][2], r2[nt][3],
                    a0, a1, a2, a3, bB[nt][0], bB[nt][1]);
        }
    }

    const int pidx = b * 8 + chunk;
    float* d1 = g_gw_part + ((size_t)(0 * NH + head) * 128 + pidx) * 4096;
    float* d2 = g_gw_part + ((size_t)(1 * NH + head) * 128 + pidx) * 4096;
#pragma unroll
    for (int nt = 0; nt < 4; nt++) {
        const int row = mt * 16 + g;
        const int col = nh + nt * 8 + tq * 2;
        float2 p;
        p.x = r1[nt][0] * M1_INV; p.y = r1[nt][1] * M1_INV;
        *(float2*)&d1[row * 64 + col] = p;
        p.x = r1[nt][2] * M1_INV; p.y = r1[nt][3] * M1_INV;
        *(float2*)&d1[(row + 8) * 64 + col] = p;
        p.x = r2[nt][0] * M1_INV; p.y = r2[nt][1] * M1_INV;
        *(float2*)&d2[row * 64 + col] = p;
        p.x = r2[nt][2] * M1_INV; p.y = r2[nt][3] * M1_INV;
        *(float2*)&d2[(row + 8) * 64 + col] = p;
    }
}

// ---------------- TTT forward kernel — HMMA, 3-term hi/lo split (R12) ----------
#define TF_SMEM 73728
__global__ __launch_bounds__(256) void ttt_fwd_kernel()
{
    extern __shared__ __half smh[];
    const unsigned int su   = smem_to_u32(smh);
    const unsigned int w1hu = su;
    const unsigned int w1lu = su + 4608u * 2;
    const unsigned int w2hu = su + 9216u * 2;
    const unsigned int w2lu = su + 13824u * 2;
    const unsigned int q1hu = su + 18432u * 2;
    const unsigned int q1lu = su + 27648u * 2;
    __half* w1h = smh;
    __half* w1l = smh + 4608;
    __half* w2h = smh + 9216;
    __half* w2l = smh + 13824;
    __half* q1h = smh + 18432;
    __half* q1l = smh + 27648;

    const int tid = threadIdx.x, lane = tid & 31, wid = tid >> 5;
    const int chunk = blockIdx.x, head = blockIdx.y, b = blockIdx.z;
    const int n0 = chunk * 128;

    for (int idx = tid; idx < 4096; idx += 256) {
        const int k = idx >> 6, n = idx & 63;
        float v1 = g_mw1[head * 4096 + idx];
        float v2 = g_mw2[head * 4096 + idx];
        __half h1 = __float2half(v1), h2 = __float2half(v2);
        w1h[n * 72 + k] = h1;
        w1l[n * 72 + k] = __float2half(v1 - __half2float(h1));
        w2h[n * 72 + k] = h2;
        w2l[n * 72 + k] = __float2half(v2 - __half2float(h2));
    }
    {
        const float* src = g_qkv + (size_t)(b * N_ + n0) * QC + head * HD_;
        const int row = tid >> 1, c8 = (tid & 1) * 32;
#pragma unroll
        for (int c = 0; c < 32; c += 2) {
            float2 v = *(const float2*)(src + (size_t)row * QC + c8 + c);
            __half h0 = __float2half(v.x), h1 = __float2half(v.y);
            *(__half2*)&q1h[row * 72 + c8 + c] = __halves2half2(h0, h1);
            *(__half2*)&q1l[row * 72 + c8 + c] =
                __floats2half2_rn(v.x - __half2float(h0), v.y - __half2float(h1));
        }
    }
    __syncthreads();

    const int m0w = wid * 16;
    float accA[8][4], accB[8][4];
#pragma unroll
    for (int nt = 0; nt < 8; nt++)
#pragma unroll
        for (int c = 0; c < 4; c++) { accA[nt][c] = 0.f; accB[nt][c] = 0.f; }

#pragma unroll
    for (int kk = 0; kk < 4; kk++) {
        const unsigned int ak = (unsigned int)(kk * 16 + ((lane >> 4) << 3));
        const unsigned int ao = ((unsigned int)(m0w + (lane & 15)) * 72 + ak) * 2;
        unsigned int ah0, ah1, ah2, ah3, al0, al1, al2, al3;
        ldm_x4(ah0, ah1, ah2, ah3, q1hu + ao);
        ldm_x4(al0, al1, al2, al3, q1lu + ao);
        unsigned int b1h[8][2], b1l[8][2], b2h[8][2], b2l[8][2];
#pragma unroll
        for (int q = 0; q < 4; q++) {
            const unsigned int brow = (unsigned int)(q * 16 + (lane & 7) +
                                                     ((lane >> 4) << 3));
            const unsigned int bk = (unsigned int)(kk * 16 + ((lane >> 3) & 1) * 8);
            const unsigned int bo = (brow * 72 + bk) * 2;
            ldm_x4(b1h[2*q][0], b1h[2*q][1], b1h[2*q+1][0], b1h[2*q+1][1], w1hu + bo);
            ldm_x4(b1l[2*q][0], b1l[2*q][1], b1l[2*q+1][0], b1l[2*q+1][1], w1lu + bo);
            ldm_x4(b2h[2*q][0], b2h[2*q][1], b2h[2*q+1][0], b2h[2*q+1][1], w2hu + bo);
            ldm_x4(b2l[2*q][0], b2l[2*q][1], b2l[2*q+1][0], b2l[2*q+1][1], w2lu + bo);
        }
#pragma unroll
        for (int nt = 0; nt < 8; nt++) {
            mma_f16(accA[nt][0], accA[nt][1], accA[nt][2], accA[nt][3],
                    ah0, ah1, ah2, ah3, b1h[nt][0], b1h[nt][1]);
            mma_f16(accA[nt][0], accA[nt][1], accA[nt][2], accA[nt][3],
                    ah0, ah1, ah2, ah3, b1l[nt][0], b1l[nt][1]);
            mma_f16(accA[nt][0], accA[nt][1], accA[nt][2], accA[nt][3],
                    al0, al1, al2, al3, b1h[nt][0], b1h[nt][1]);
            mma_f16(accB[nt][0], accB[nt][1], accB[nt][2], accB[nt][3],
                    ah0, ah1, ah2, ah3, b2h[nt][0], b2h[nt][1]);
            mma_f16(accB[nt][0], accB[nt][1], accB[nt][2], accB[nt][3],
                    ah0, ah1, ah2, ah3, b2l[nt][0], b2l[nt][1]);
            mma_f16(accB[nt][0], accB[nt][1], accB[nt][2], accB[nt][3],
                    al0, al1, al2, al3, b2h[nt][0], b2h[nt][1]);
        }
    }

    const int g = lane >> 2, tq = lane & 3;
    __half* obase = g_xch + (size_t)(b * N_ + n0 + m0w) * XC + head * HD_;
#pragma unroll
    for (int nt = 0; nt < 8; nt++) {
        const int col = nt * 8 + tq * 2;
#pragma unroll
        for (int h = 0; h < 2; h++) {
            const int row = g + h * 8;
            float Av0 = accA[nt][2*h + 0], Av1 = accA[nt][2*h + 1];
            float Bv0 = accB[nt][2*h + 0], Bv1 = accB[nt][2*h + 1];
            float sig0 = 1.f / (1.f + expf(-Bv0));
            float sig1 = 1.f / (1.f + expf(-Bv1));
            float o0 = Av0 * (Bv0 * sig0);
            float o1 = Av1 * (Bv1 * sig1);
            *(__half2*)(obase + (size_t)row * XC + col) = __floats2half2_rn(o0, o1);
        }
    }
}

// ---------------- conv grad ----------------
__global__ __launch_bounds__(256) void conv_grad_kernel(const float* __restrict__ w3g)
{
    const int bc = blockIdx.x;
    const int b = bc >> 6, c = bc & 63;
    const int tid = threadIdx.x;
    __shared__ float k2s[32][33];
    __shared__ float wk[9];
    __shared__ float red[256];

    if (tid < 9) wk[tid] = w3g[c * 9 + tid];
    const float* base = g_qkv + (size_t)(b * N_) * QC;
    for (int p = tid; p < 1024; p += 256)
        k2s[p >> 5][p & 31] = base[(size_t)p * QC + 2368 + c];
    __syncthreads();

    float acc[9];
#pragma unroll
    for (int q = 0; q < 9; q++) acc[q] = 0.f;

    for (int p = tid; p < 1024; p += 256) {
        const int y = p >> 5, x = p & 31;
        float t[9];
#pragma unroll
        for (int dy = 0; dy < 3; dy++)
#pragma unroll
            for (int dx = 0; dx < 3; dx++) {
                int yy = y + dy - 1, xx = x + dx - 1;
                t[dy * 3 + dx] = (yy >= 0 && yy < 32 && xx >= 0 && xx < 32)
                                 ? k2s[yy][xx] : 0.f;
            }
        float f = 0.f;
#pragma unroll
        for (int q = 0; q < 9; q++) f = fmaf(wk[q], t[q], f);
        float v = base[(size_t)p * QC + 2432 + c];
        float g = (f - v) * M2_INV;
#pragma unroll
        for (int q = 0; q < 9; q++) acc[q] = fmaf(g, t[q], acc[q]);
    }

    for (int q = 0; q < 9; q++) {
        red[tid] = acc[q];
        __syncthreads();
        for (int s = 128; s > 0; s >>= 1) {
            if (tid < s) red[tid] += red[tid + s];
            __syncthreads();
        }
        if (tid == 0) g_gw3_part[(size_t)bc * 9 + q] = red[0];
        __syncthreads();
    }
}

__global__ void conv_grad_reduce_kernel()
{
    const int tid = threadIdx.x;
    __shared__ float red[576];
    float s = 0.f;
    const int c = tid / 9, q = tid % 9;
    for (int b = 0; b < B_; b++) s += g_gw3_part[(size_t)(b * 64 + c) * 9 + q];
    g_gw3[tid] = s;
    red[tid] = s * s;
    __syncthreads();
    if (tid < 64) red[tid] += red[tid + 512];
    __syncthreads();
    for (int st = 256; st > 0; st >>= 1) {
        if (tid < st && tid + st < 576) red[tid] += red[tid + st];
        __syncthreads();
    }
    if (tid == 0) g_sumsq[24] = red[0];
}

// ---------------- two-stage gw reduce ----------------
__global__ __launch_bounds__(256) void reduce_gw_stage1()
{
    const int th = blockIdx.x >> 3;
    const int g  = blockIdx.x & 7;
    const int tid = threadIdx.x;
    const float* src = g_gw_part + ((size_t)th * 128 + g * 16) * 4096;
    float s[16];
#pragma unroll
    for (int q = 0; q < 16; q++) s[q] = 0.f;
    for (int p = 0; p < 16; p++) {
        const float* row = src + (size_t)p * 4096 + tid;
#pragma unroll
        for (int q = 0; q < 16; q++) s[q] += row[q * 256];
    }
    float* dst = g_gw_stage + (size_t)(th * 8 + g) * 4096 + tid;
#pragma unroll
    for (int q = 0; q < 16; q++) dst[q * 256] = s[q];
}

__global__ __launch_bounds__(256) void reduce_gw_stage2()
{
    const int th  = blockIdx.x;
    const int tid = threadIdx.x;
    const float* src = g_gw_stage + (size_t)th * 8 * 4096;
    float* dst = g_gw + (size_t)th * 4096;

    float s[16];
#pragma unroll
    for (int q = 0; q < 16; q++) s[q] = 0.f;
    for (int p = 0; p < 8; p++) {
        const float* row = src + (size_t)p * 4096 + tid;
#pragma unroll
        for (int q = 0; q < 16; q++) s[q] += row[q * 256];
    }
    float ss = 0.f;
#pragma unroll
    for (int q = 0; q < 16; q++) { dst[tid + q * 256] = s[q]; ss += s[q] * s[q]; }

    __shared__ float red[256];
    red[tid] = ss;
    __syncthreads();
    for (int st = 128; st > 0; st >>= 1) {
        if (tid < st) red[tid] += red[tid + st];
        __syncthreads();
    }
    if (tid == 0) g_sumsq[th] = red[0];
}

// ---------------- weight update (scales fused) ----------------
__global__ void update_w_kernel(const float* __restrict__ w1g,
                                const float* __restrict__ w2g,
                                const float* __restrict__ w3g)
{
    __shared__ float sc[3];
    if (threadIdx.x == 0) {
        float s1 = 0.f, s2 = 0.f;
        for (int h = 0; h < NH; h++) { s1 += g_sumsq[h]; s2 += g_sumsq[NH + h]; }
        sc[0] = LR_ / (sqrtf(s1) + 1.f);
        sc[1] = LR_ / (sqrtf(s2) + 1.f);
        sc[2] = LR_ / (sqrtf(g_sumsq[24]) + 1.f);
    }
    __syncthreads();
    const int i = blockIdx.x * 256 + threadIdx.x;
    if (i < 49152) {
        g_mw1[i] = w1g[i] - sc[0] * g_gw[i];
    } else if (i < 98304) {
        const int k = i - 49152;
        g_mw2[k] = w2g[k] - sc[1] * g_gw[49152 + k];
    } else if (i < 98880) {
        const int k = i - 98304;
        g_mw3[k] = w3g[k] - sc[2] * g_gw3[k];
    }
}

// ---------------- conv forward (writes fp16 hi directly) ----------------
__global__ __launch_bounds__(256) void conv_fwd_kernel()
{
    const int bc = blockIdx.x;
    const int b = bc >> 6, c = bc & 63;
    const int tid = threadIdx.x;
    __shared__ float q2s[32][33];
    __shared__ float wk[9];
    if (tid < 9) wk[tid] = g_mw3[c * 9 + tid];
    const float* base = g_qkv + (size_t)(b * N_) * QC;
    for (int p = tid; p < 1024; p += 256)
        q2s[p >> 5][p & 31] = base[(size_t)p * QC + 2304 + c];
    __syncthreads();

    for (int p = tid; p < 1024; p += 256) {
        const int y = p >> 5, x = p & 31;
        float f = 0.f;
#pragma unroll
        for (int dy = 0; dy < 3; dy++)
#pragma unroll
            for (int dx = 0; dx < 3; dx++) {
                int yy = y + dy - 1, xx = x + dx - 1;
                if (yy >= 0 && yy < 32 && xx >= 0 && xx < 32)
                    f = fmaf(wk[dy * 3 + dx], q2s[yy][xx], f);
            }
        g_xch[(size_t)(b * N_ + p) * XC + 768 + c] = __float2half(f);
    }
}

// ---------------- launch ----------------
extern "C" void kernel_launch(void* const* d_in, const int* in_sizes, int n_in,
                              void* d_out, int out_size)
{
    const float *x = nullptr, *Wqkv = nullptr, *bqkv = nullptr, *w1 = nullptr,
                *w2 = nullptr, *w3 = nullptr, *Wproj = nullptr, *bproj = nullptr;
    for (int i = 0; i < n_in; i++) {
        const int s = in_sizes[i];
        const float* p = (const float*)d_in[i];
        if      (s == B_*N_*C_)   x = p;
        else if (s == C_*QC)      Wqkv = p;
        else if (s == QC)         bqkv = p;
        else if (s == NH*HD_*HD_) { if (!w1) w1 = p; else w2 = p; }
        else if (s == 64*9)       w3 = p;
        else if (s == XC*C_)      Wproj = p;
        else if (s == C_)         bproj = p;
    }

    float* qkv_ptr = nullptr;
    __half *xh, *xch, *wqh, *wph;
    cudaGetSymbolAddress((void**)&qkv_ptr, g_qkv);
    cudaGetSymbolAddress((void**)&xh,  g_xh);
    cudaGetSymbolAddress((void**)&xch, g_xch);
    cudaGetSymbolAddress((void**)&wqh, g_wqh);
    cudaGetSymbolAddress((void**)&wph, g_wph);

    cudaFuncSetAttribute(ttt_grad_kernel,
        cudaFuncAttributeMaxDynamicSharedMemorySize, TG_SMEM);
    cudaFuncSetAttribute(ttt_fwd_kernel,
        cudaFuncAttributeMaxDynamicSharedMemorySize, TF_SMEM);
    cudaFuncSetAttribute(tc_gemm,
        cudaFuncAttributeMaxDynamicSharedMemorySize, TCG_SMEM);

    // 1. convert x, transpose weights (plain fp16)
    convert_f16<<<(B_*N_*C_/4 + 255)/256, 256>>>(x, xh, B_*N_*C_/4);
    transpose_f16<<<dim3(QC/32, C_/32), 256>>>(Wqkv, wqh, C_, QC);
    transpose_f16<<<dim3(C_/32, XC/32), 256>>>(Wproj, wph, XC, C_);

    // 2. qkv = x @ Wqkv + bqkv  (plain fp16 HMMA)
    tc_gemm<<<dim3((QC + 127)/128, (B_*N_)/128), 256, TCG_SMEM>>>(
        xh, wqh, bqkv, qkv_ptr, QC, C_);

    // 3. TTT (HMMA) + conv gradients, reduce, update
    ttt_grad_kernel<<<dim3(8, NH, B_), 256, TG_SMEM>>>(w1, w2);
    conv_grad_kernel<<<B_ * 64, 256>>>(w3);
    conv_grad_reduce_kernel<<<1, 576>>>();
    reduce_gw_stage1<<<192, 256>>>();
    reduce_gw_stage2<<<24, 256>>>();
    update_w_kernel<<<(98880 + 255)/256, 256>>>(w1, w2, w3);

    // 4. post-update forward (HMMA, 3-term split)
    ttt_fwd_kernel<<<dim3(8, NH, B_), 256, TF_SMEM>>>();
    conv_fwd_kernel<<<B_ * 64, 256>>>();

    // 5. proj GEMM (plain fp16 HMMA)
    tc_gemm<<<dim3(C_/128, (B_*N_)/128), 256, TCG_SMEM>>>(
        xch, wph, bproj, (float*)d_out, C_, XC);
}

// round 14
// speedup vs baseline: 2.0274x; 1.1175x over previous
#include <cuda_runtime.h>
#include <cuda_bf16.h>
#include <cuda_fp16.h>
#include <cstdint>
#include <cstdio>
#include <math.h>

#define B_  16
#define N_  1024
#define C_  768
#define NH  12
#define HD_ 64
#define QC  2496   // 3*768 + 3*64
#define XC  832    // 768 + 64
#define M1_INV (1.0f/12582912.0f)
#define M2_INV (1.0f/1048576.0f)
#define LR_ 0.001f

// ---------------- scratch ----------------
__device__ float g_qkv[B_*N_*QC];
__device__ float g_gw_part[2*NH*128*HD_*HD_];
__device__ float g_gw_stage[24*8*HD_*HD_];
__device__ float g_gw[2*NH*HD_*HD_];
__device__ float g_gw3_part[B_*64*9];
__device__ float g_gw3[64*9];
__device__ float g_sumsq[25];
__device__ float g_mw1[NH*HD_*HD_];
__device__ float g_mw2[NH*HD_*HD_];
__device__ float g_mw3[64*9];
// fp16 operands (plain fp16, no splits)
__device__ __half g_xh[B_*N_*C_];
__device__ __half g_xch[B_*N_*XC];
__device__ __half g_wqh[QC*C_];   // [N=2496][K=768]
__device__ __half g_wph[C_*XC];   // [N=768][K=832]

// ---------------- PTX helpers ----------------
__device__ __forceinline__ unsigned int smem_to_u32(const void* smem_ptr) {
    unsigned int addr;
    asm("{ .reg .u64 tmp; cvta.to.shared.u64 tmp, %1; cvt.u32.u64 %0, tmp; }"
        : "=r"(addr) : "l"(smem_ptr));
    return addr;
}
__device__ __forceinline__ void cp_async16(unsigned int saddr, const void* gaddr) {
    asm volatile("cp.async.cg.shared.global [%0], [%1], 16;"
                 :: "r"(saddr), "l"(gaddr) : "memory");
}
__device__ __forceinline__ void cp_commit() {
    asm volatile("cp.async.commit_group;" ::: "memory");
}
__device__ __forceinline__ void cp_wait1() {
    asm volatile("cp.async.wait_group 1;" ::: "memory");
}
__device__ __forceinline__ void cp_wait0() {
    asm volatile("cp.async.wait_group 0;" ::: "memory");
}
__device__ __forceinline__ void ldm_x4(unsigned int& r0, unsigned int& r1,
                                       unsigned int& r2, unsigned int& r3,
                                       unsigned int a) {
    asm volatile("ldmatrix.sync.aligned.m8n8.x4.shared.b16 {%0,%1,%2,%3}, [%4];"
                 : "=r"(r0), "=r"(r1), "=r"(r2), "=r"(r3) : "r"(a));
}
__device__ __forceinline__ void ldm_x4t(unsigned int& r0, unsigned int& r1,
                                        unsigned int& r2, unsigned int& r3,
                                        unsigned int a) {
    asm volatile("ldmatrix.sync.aligned.m8n8.x4.trans.shared.b16 {%0,%1,%2,%3}, [%4];"
                 : "=r"(r0), "=r"(r1), "=r"(r2), "=r"(r3) : "r"(a));
}
__device__ __forceinline__ void mma_f16(float& c0, float& c1, float& c2, float& c3,
                                        unsigned int a0, unsigned int a1,
                                        unsigned int a2, unsigned int a3,
                                        unsigned int b0, unsigned int b1) {
    asm volatile("mma.sync.aligned.m16n8k16.row.col.f32.f16.f16.f32 "
                 "{%0,%1,%2,%3}, {%4,%5,%6,%7}, {%8,%9}, {%0,%1,%2,%3};"
                 : "+f"(c0), "+f"(c1), "+f"(c2), "+f"(c3)
                 : "r"(a0), "r"(a1), "r"(a2), "r"(a3), "r"(b0), "r"(b1));
}

// ---------------- conversions ----------------
__device__ __forceinline__ unsigned int pack_h2(__half a, __half b) {
    return (unsigned int)__half_as_ushort(a) |
           ((unsigned int)__half_as_ushort(b) << 16);
}
__global__ __launch_bounds__(256) void convert_f16(
    const float* __restrict__ X, __half* __restrict__ H, int n4)
{
    int i = blockIdx.x * 256 + threadIdx.x;
    if (i >= n4) return;
    float4 v = ((const float4*)X)[i];
    uint2 hh;
    hh.x = pack_h2(__float2half(v.x), __float2half(v.y));
    hh.y = pack_h2(__float2half(v.z), __float2half(v.w));
    ((uint2*)H)[i] = hh;
}
// W[K][N] -> T[N][K] fp16 (no split)
__global__ __launch_bounds__(256) void transpose_f16(
    const float* __restrict__ W, __half* __restrict__ Th, int K, int N)
{
    __shared__ float s[32][33];
    const int n0 = blockIdx.x * 32, k0 = blockIdx.y * 32;
    const int tx = threadIdx.x & 31, ty = threadIdx.x >> 5;
    for (int r = ty; r < 32; r += 8)
        s[r][tx] = W[(size_t)(k0 + r) * N + n0 + tx];
    __syncthreads();
    for (int r = ty; r < 32; r += 8)
        Th[(size_t)(n0 + r) * K + k0 + tx] = __float2half(s[tx][r]);
}

// ---------------- HMMA GEMM (plain fp16, 4 warps x 64x64 tiles) ----------------
#define SROW   40
#define ARR_B  (128*SROW*2)
#define STG_B  (2*ARR_B)
#define TCG_SMEM (2*STG_B)        // 40960

__global__ __launch_bounds__(128) void tc_gemm(
    const __half* __restrict__ Ah, const __half* __restrict__ Bh,
    const float* __restrict__ bias, float* __restrict__ C,
    int Nfull, int K)
{
    extern __shared__ __half smb[];
    const unsigned int smem_u = smem_to_u32(smb);
    const int t = threadIdx.x, lane = t & 31, wid = t >> 5;    // 4 warps
    const int m0 = blockIdx.y * 128, n0 = blockIdx.x * 128;
    const int wm = (wid >> 1) * 64, wn = (wid & 1) * 64;

    float acc[4][8][4];
#pragma unroll
    for (int a = 0; a < 4; a++)
#pragma unroll
        for (int b = 0; b < 8; b++)
#pragma unroll
            for (int c = 0; c < 4; c++) acc[a][b][c] = 0.f;

    // load plan: thread t fills rows r0, r0+32, r0+64, r0+96 of A and B arrays
    const int r0 = t >> 2, c4 = t & 3;
    const unsigned int s0 = (unsigned int)((r0 * SROW + c4 * 8) * 2);
    const unsigned int sstep = (unsigned int)(32 * SROW * 2);
    bool vB[4];
    size_t offA[4], offB[4];
#pragma unroll
    for (int j = 0; j < 4; j++) {
        const int rr = r0 + 32 * j;
        vB[j]   = (n0 + rr) < Nfull;
        offA[j] = (size_t)(m0 + rr) * K + c4 * 8;
        offB[j] = (size_t)(vB[j] ? (n0 + rr) : 0) * K + c4 * 8;
    }

#define ISSUE(stg, ks) do {                                                  \
        unsigned int _sb = smem_u + (unsigned int)(stg) * STG_B;             \
        const int _ko = (ks) * 32;                                           \
        _Pragma("unroll")                                                    \
        for (int j = 0; j < 4; j++) {                                        \
            unsigned int _s = _sb + s0 + (unsigned int)j * sstep;            \
            cp_async16(_s,          Ah + offA[j] + _ko);                     \
            if (vB[j]) cp_async16(_s + ARR_B, Bh + offB[j] + _ko);           \
        }                                                                    \
        cp_commit();                                                         \
    } while (0)

    const int nk = K / 32;
    ISSUE(0, 0);

    for (int s = 0; s < nk; s++) {
        if (s + 1 < nk) { ISSUE((s + 1) & 1, s + 1); cp_wait1(); }
        else            { cp_wait0(); }
        __syncthreads();

        const unsigned int sb = smem_u + (unsigned int)(s & 1) * STG_B;
#pragma unroll
        for (int kc = 0; kc < 32; kc += 16) {
            // B fragments: 8 n-tiles via 4 ldm_x4
            unsigned int bh[8][2];
#pragma unroll
            for (int q = 0; q < 4; q++) {
                unsigned int brow = (unsigned int)(wn + q * 16 + (lane & 7) +
                                                   ((lane >> 4) << 3));
                unsigned int koff = (unsigned int)(((lane >> 3) & 1) * 8);
                unsigned int ab = sb + 1u * ARR_B + (brow * SROW + kc + koff) * 2;
                ldm_x4(bh[2*q][0], bh[2*q][1], bh[2*q+1][0], bh[2*q+1][1], ab);
            }
#pragma unroll
            for (int mt = 0; mt < 4; mt++) {
                unsigned int arow = (unsigned int)(wm + mt * 16 + (lane & 15));
                unsigned int koff = (unsigned int)((lane >> 4) * 8);
                unsigned int aa = sb + (arow * SROW + kc + koff) * 2;
                unsigned int a0, a1, a2, a3;
                ldm_x4(a0, a1, a2, a3, aa);
#pragma unroll
                for (int nt = 0; nt < 8; nt++)
                    mma_f16(acc[mt][nt][0], acc[mt][nt][1],
                            acc[mt][nt][2], acc[mt][nt][3],
                            a0, a1, a2, a3, bh[nt][0], bh[nt][1]);
            }
        }
        __syncthreads();
    }
#undef ISSUE

    const int g = lane >> 2, tq = lane & 3;
#pragma unroll
    for (int mt = 0; mt < 4; mt++) {
        const int row = m0 + wm + mt * 16 + g;
#pragma unroll
        for (int nt = 0; nt < 8; nt++) {
            const int col = n0 + wn + nt * 8 + tq * 2;
            if (col < Nfull) {
                float b0 = bias[col], b1 = bias[col + 1];
                float2 o1; o1.x = acc[mt][nt][0] + b0; o1.y = acc[mt][nt][1] + b1;
                float2 o2v; o2v.x = acc[mt][nt][2] + b0; o2v.y = acc[mt][nt][3] + b1;
                *(float2*)(C + (size_t)row * Nfull + col) = o1;
                *(float2*)(C + (size_t)(row + 8) * Nfull + col) = o2v;
            }
        }
    }
}

// ---------------- TTT gradient kernel — HMMA (unchanged) ----------------
#define TG_SMEM 73728
__global__ __launch_bounds__(256) void ttt_grad_kernel(
    const float* __restrict__ w1g, const float* __restrict__ w2g)
{
    extern __shared__ __half smh[];
    const unsigned int su  = smem_to_u32(smh);
    const unsigned int w1u = su;
    const unsigned int w2u = su + 4608u * 2;
    const unsigned int k1u = su + 9216u * 2;
    const unsigned int gAu = k1u + 9216u * 2;
    const unsigned int gBu = gAu + 9216u * 2;
    __half* w1T = smh;
    __half* w2T = smh + 4608;
    __half* k1h = smh + 9216;
    __half* gAh = smh + 9216 + 9216;
    __half* gBh = gAh + 9216;

    const int tid = threadIdx.x, lane = tid & 31, wid = tid >> 5;
    const int chunk = blockIdx.x, head = blockIdx.y, b = blockIdx.z;
    const int n0 = chunk * 128;

    for (int idx = tid; idx < 4096; idx += 256) {
        const int k = idx >> 6, n = idx & 63;
        w1T[n * 72 + k] = __float2half(w1g[head * 4096 + idx]);
        w2T[n * 72 + k] = __float2half(w2g[head * 4096 + idx]);
    }
    {
        const float* src = g_qkv + (size_t)(b * N_ + n0) * QC + C_ + head * HD_;
        const int row = tid >> 1, c8 = (tid & 1) * 32;
#pragma unroll
        for (int c = 0; c < 32; c += 4) {
            float4 v = *(const float4*)(src + (size_t)row * QC + c8 + c);
            *(__half2*)&k1h[row * 72 + c8 + c]     = __floats2half2_rn(v.x, v.y);
            *(__half2*)&k1h[row * 72 + c8 + c + 2] = __floats2half2_rn(v.z, v.w);
        }
    }
    __syncthreads();

    const int m0w = wid * 16;
    float accA[8][4], accB[8][4];
#pragma unroll
    for (int nt = 0; nt < 8; nt++)
#pragma unroll
        for (int c = 0; c < 4; c++) { accA[nt][c] = 0.f; accB[nt][c] = 0.f; }

#pragma unroll
    for (int kk = 0; kk < 4; kk++) {
        const unsigned int ak = (unsigned int)(kk * 16 + ((lane >> 4) << 3));
        const unsigned int aa = k1u + ((unsigned int)(m0w + (lane & 15)) * 72 + ak) * 2;
        unsigned int a0, a1, a2, a3;
        ldm_x4(a0, a1, a2, a3, aa);
        unsigned int b1[8][2], b2[8][2];
#pragma unroll
        for (int q = 0; q < 4; q++) {
            const unsigned int brow = (unsigned int)(q * 16 + (lane & 7) +
                                                     ((lane >> 4) << 3));
            const unsigned int bk = (unsigned int)(kk * 16 + ((lane >> 3) & 1) * 8);
            ldm_x4(b1[2*q][0], b1[2*q][1], b1[2*q+1][0], b1[2*q+1][1],
                   w1u + (brow * 72 + bk) * 2);
            ldm_x4(b2[2*q][0], b2[2*q][1], b2[2*q+1][0], b2[2*q+1][1],
                   w2u + (brow * 72 + bk) * 2);
        }
#pragma unroll
        for (int nt = 0; nt < 8; nt++) {
            mma_f16(accA[nt][0], accA[nt][1], accA[nt][2], accA[nt][3],
                    a0, a1, a2, a3, b1[nt][0], b1[nt][1]);
            mma_f16(accB[nt][0], accB[nt][1], accB[nt][2], accB[nt][3],
                    a0, a1, a2, a3, b2[nt][0], b2[nt][1]);
        }
    }

    const int g = lane >> 2, tq = lane & 3;
    const float* vbase = g_qkv + (size_t)(b * N_ + n0 + m0w) * QC + 2 * C_ + head * HD_;
#pragma unroll
    for (int nt = 0; nt < 8; nt++) {
        const int col = nt * 8 + tq * 2;
#pragma unroll
        for (int h = 0; h < 2; h++) {
            const int row = g + h * 8;
            float2 v = *(const float2*)(vbase + (size_t)row * QC + col);
            float Av0 = accA[nt][2*h + 0], Av1 = accA[nt][2*h + 1];
            float Bv0 = accB[nt][2*h + 0], Bv1 = accB[nt][2*h + 1];
            float sig0 = 1.f / (1.f + expf(-Bv0));
            float sig1 = 1.f / (1.f + expf(-Bv1));
            float sil0 = Bv0 * sig0, sil1 = Bv1 * sig1;
            float g0 = Av0 * sil0 - v.x;
            float g1 = Av1 * sil1 - v.y;
            float gA0 = g0 * sil0, gA1 = g1 * sil1;
            float gB0 = g0 * Av0 * sig0 * (1.f + Bv0 * (1.f - sig0));
            float gB1 = g1 * Av1 * sig1 * (1.f + Bv1 * (1.f - sig1));
            *(__half2*)&gAh[(m0w + row) * 72 + col] = __floats2half2_rn(gA0, gA1);
            *(__half2*)&gBh[(m0w + row) * 72 + col] = __floats2half2_rn(gB0, gB1);
        }
    }
    __syncthreads();

    const int mt = wid >> 1;
    const int nh = (wid & 1) * 32;
    float r1[4][4], r2[4][4];
#pragma unroll
    for (int nt = 0; nt < 4; nt++)
#pragma unroll
        for (int c = 0; c < 4; c++) { r1[nt][c] = 0.f; r2[nt][c] = 0.f; }

#pragma unroll
    for (int ks = 0; ks < 8; ks++) {
        const int k0 = ks * 16;
        const unsigned int arow = (unsigned int)(k0 + ((lane >> 4) << 3) + (lane & 7));
        const unsigned int acol = (unsigned int)(mt * 16 + (((lane >> 3) & 1) << 3));
        unsigned int a0, a1, a2, a3;
        ldm_x4t(a0, a1, a2, a3, k1u + (arow * 72 + acol) * 2);
        unsigned int bA[4][2], bB[4][2];
#pragma unroll
        for (int q = 0; q < 2; q++) {
            const unsigned int brow = (unsigned int)(k0 + (((lane >> 3) & 1) << 3) +
                                                     (lane & 7));
            const unsigned int bcol = (unsigned int)(nh + q * 16 + ((lane >> 4) << 3));
            ldm_x4t(bA[2*q][0], bA[2*q][1], bA[2*q+1][0], bA[2*q+1][1],
                    gAu + (brow * 72 + bcol) * 2);
            ldm_x4t(bB[2*q][0], bB[2*q][1], bB[2*q+1][0], bB[2*q+1][1],
                    gBu + (brow * 72 + bcol) * 2);
        }
#pragma unroll
        for (int nt = 0; nt < 4; nt++) {
            mma_f16(r1[nt][0], r1[nt][1], r1[nt][2], r1[nt][3],
                    a0, a1, a2, a3, bA[nt][0], bA[nt][1]);
            mma_f16(r2[nt][0], r2[nt][1], r2[nt][2], r2[nt][3],
                    a0, a1, a2, a3, bB[nt][0], bB[nt][1]);
        }
    }

    const int pidx = b * 8 + chunk;
    float* d1 = g_gw_part + ((size_t)(0 * NH + head) * 128 + pidx) * 4096;
    float* d2 = g_gw_part + ((size_t)(1 * NH + head) * 128 + pidx) * 4096;
#pragma unroll
    for (int nt = 0; nt < 4; nt++) {
        const int row = mt * 16 + g;
        const int col = nh + nt * 8 + tq * 2;
        float2 p;
        p.x = r1[nt][0] * M1_INV; p.y = r1[nt][1] * M1_INV;
        *(float2*)&d1[row * 64 + col] = p;
        p.x = r1[nt][2] * M1_INV; p.y = r1[nt][3] * M1_INV;
        *(float2*)&d1[(row + 8) * 64 + col] = p;
        p.x = r2[nt][0] * M1_INV; p.y = r2[nt][1] * M1_INV;
        *(float2*)&d2[row * 64 + col] = p;
        p.x = r2[nt][2] * M1_INV; p.y = r2[nt][3] * M1_INV;
        *(float2*)&d2[(row + 8) * 64 + col] = p;
    }
}

// ---------------- TTT forward kernel — HMMA, 3-term hi/lo split (unchanged) ----
#define TF_SMEM 73728
__global__ __launch_bounds__(256) void ttt_fwd_kernel()
{
    extern __shared__ __half smh[];
    const unsigned int su   = smem_to_u32(smh);
    const unsigned int w1hu = su;
    const unsigned int w1lu = su + 4608u * 2;
    const unsigned int w2hu = su + 9216u * 2;
    const unsigned int w2lu = su + 13824u * 2;
    const unsigned int q1hu = su + 18432u * 2;
    const unsigned int q1lu = su + 27648u * 2;
    __half* w1h = smh;
    __half* w1l = smh + 4608;
    __half* w2h = smh + 9216;
    __half* w2l = smh + 13824;
    __half* q1h = smh + 18432;
    __half* q1l = smh + 27648;

    const int tid = threadIdx.x, lane = tid & 31, wid = tid >> 5;
    const int chunk = blockIdx.x, head = blockIdx.y, b = blockIdx.z;
    const int n0 = chunk * 128;

    for (int idx = tid; idx < 4096; idx += 256) {
        const int k = idx >> 6, n = idx & 63;
        float v1 = g_mw1[head * 4096 + idx];
        float v2 = g_mw2[head * 4096 + idx];
        __half h1 = __float2half(v1), h2 = __float2half(v2);
        w1h[n * 72 + k] = h1;
        w1l[n * 72 + k] = __float2half(v1 - __half2float(h1));
        w2h[n * 72 + k] = h2;
        w2l[n * 72 + k] = __float2half(v2 - __half2float(h2));
    }
    {
        const float* src = g_qkv + (size_t)(b * N_ + n0) * QC + head * HD_;
        const int row = tid >> 1, c8 = (tid & 1) * 32;
#pragma unroll
        for (int c = 0; c < 32; c += 2) {
            float2 v = *(const float2*)(src + (size_t)row * QC + c8 + c);
            __half h0 = __float2half(v.x), h1 = __float2half(v.y);
            *(__half2*)&q1h[row * 72 + c8 + c] = __halves2half2(h0, h1);
            *(__half2*)&q1l[row * 72 + c8 + c] =
                __floats2half2_rn(v.x - __half2float(h0), v.y - __half2float(h1));
        }
    }
    __syncthreads();

    const int m0w = wid * 16;
    float accA[8][4], accB[8][4];
#pragma unroll
    for (int nt = 0; nt < 8; nt++)
#pragma unroll
        for (int c = 0; c < 4; c++) { accA[nt][c] = 0.f; accB[nt][c] = 0.f; }

#pragma unroll
    for (int kk = 0; kk < 4; kk++) {
        const unsigned int ak = (unsigned int)(kk * 16 + ((lane >> 4) << 3));
        const unsigned int ao = ((unsigned int)(m0w + (lane & 15)) * 72 + ak) * 2;
        unsigned int ah0, ah1, ah2, ah3, al0, al1, al2, al3;
        ldm_x4(ah0, ah1, ah2, ah3, q1hu + ao);
        ldm_x4(al0, al1, al2, al3, q1lu + ao);
        unsigned int b1h[8][2], b1l[8][2], b2h[8][2], b2l[8][2];
#pragma unroll
        for (int q = 0; q < 4; q++) {
            const unsigned int brow = (unsigned int)(q * 16 + (lane & 7) +
                                                     ((lane >> 4) << 3));
            const unsigned int bk = (unsigned int)(kk * 16 + ((lane >> 3) & 1) * 8);
            const unsigned int bo = (brow * 72 + bk) * 2;
            ldm_x4(b1h[2*q][0], b1h[2*q][1], b1h[2*q+1][0], b1h[2*q+1][1], w1hu + bo);
            ldm_x4(b1l[2*q][0], b1l[2*q][1], b1l[2*q+1][0], b1l[2*q+1][1], w1lu + bo);
            ldm_x4(b2h[2*q][0], b2h[2*q][1], b2h[2*q+1][0], b2h[2*q+1][1], w2hu + bo);
            ldm_x4(b2l[2*q][0], b2l[2*q][1], b2l[2*q+1][0], b2l[2*q+1][1], w2lu + bo);
        }
#pragma unroll
        for (int nt = 0; nt < 8; nt++) {
            mma_f16(accA[nt][0], accA[nt][1], accA[nt][2], accA[nt][3],
                    ah0, ah1, ah2, ah3, b1h[nt][0], b1h[nt][1]);
            mma_f16(accA[nt][0], accA[nt][1], accA[nt][2], accA[nt][3],
                    ah0, ah1, ah2, ah3, b1l[nt][0], b1l[nt][1]);
            mma_f16(accA[nt][0], accA[nt][1], accA[nt][2], accA[nt][3],
                    al0, al1, al2, al3, b1h[nt][0], b1h[nt][1]);
            mma_f16(accB[nt][0], accB[nt][1], accB[nt][2], accB[nt][3],
                    ah0, ah1, ah2, ah3, b2h[nt][0], b2h[nt][1]);
            mma_f16(accB[nt][0], accB[nt][1], accB[nt][2], accB[nt][3],
                    ah0, ah1, ah2, ah3, b2l[nt][0], b2l[nt][1]);
            mma_f16(accB[nt][0], accB[nt][1], accB[nt][2], accB[nt][3],
                    al0, al1, al2, al3, b2h[nt][0], b2h[nt][1]);
        }
    }

    const int g = lane >> 2, tq = lane & 3;
    __half* obase = g_xch + (size_t)(b * N_ + n0 + m0w) * XC + head * HD_;
#pragma unroll
    for (int nt = 0; nt < 8; nt++) {
        const int col = nt * 8 + tq * 2;
#pragma unroll
        for (int h = 0; h < 2; h++) {
            const int row = g + h * 8;
            float Av0 = accA[nt][2*h + 0], Av1 = accA[nt][2*h + 1];
            float Bv0 = accB[nt][2*h + 0], Bv1 = accB[nt][2*h + 1];
            float sig0 = 1.f / (1.f + expf(-Bv0));
            float sig1 = 1.f / (1.f + expf(-Bv1));
            float o0 = Av0 * (Bv0 * sig0);
            float o1 = Av1 * (Bv1 * sig1);
            *(__half2*)(obase + (size_t)row * XC + col) = __floats2half2_rn(o0, o1);
        }
    }
}

// ---------------- conv grad ----------------
__global__ __launch_bounds__(256) void conv_grad_kernel(const float* __restrict__ w3g)
{
    const int bc = blockIdx.x;
    const int b = bc >> 6, c = bc & 63;
    const int tid = threadIdx.x;
    __shared__ float k2s[32][33];
    __shared__ float wk[9];
    __shared__ float red[256];

    if (tid < 9) wk[tid] = w3g[c * 9 + tid];
    const float* base = g_qkv + (size_t)(b * N_) * QC;
    for (int p = tid; p < 1024; p += 256)
        k2s[p >> 5][p & 31] = base[(size_t)p * QC + 2368 + c];
    __syncthreads();

    float acc[9];
#pragma unroll
    for (int q = 0; q < 9; q++) acc[q] = 0.f;

    for (int p = tid; p < 1024; p += 256) {
        const int y = p >> 5, x = p & 31;
        float t[9];
#pragma unroll
        for (int dy = 0; dy < 3; dy++)
#pragma unroll
            for (int dx = 0; dx < 3; dx++) {
                int yy = y + dy - 1, xx = x + dx - 1;
                t[dy * 3 + dx] = (yy >= 0 && yy < 32 && xx >= 0 && xx < 32)
                                 ? k2s[yy][xx] : 0.f;
            }
        float f = 0.f;
#pragma unroll
        for (int q = 0; q < 9; q++) f = fmaf(wk[q], t[q], f);
        float v = base[(size_t)p * QC + 2432 + c];
        float g = (f - v) * M2_INV;
#pragma unroll
        for (int q = 0; q < 9; q++) acc[q] = fmaf(g, t[q], acc[q]);
    }

    for (int q = 0; q < 9; q++) {
        red[tid] = acc[q];
        __syncthreads();
        for (int s = 128; s > 0; s >>= 1) {
            if (tid < s) red[tid] += red[tid + s];
            __syncthreads();
        }
        if (tid == 0) g_gw3_part[(size_t)bc * 9 + q] = red[0];
        __syncthreads();
    }
}

__global__ void conv_grad_reduce_kernel()
{
    const int tid = threadIdx.x;
    __shared__ float red[576];
    float s = 0.f;
    const int c = tid / 9, q = tid % 9;
    for (int b = 0; b < B_; b++) s += g_gw3_part[(size_t)(b * 64 + c) * 9 + q];
    g_gw3[tid] = s;
    red[tid] = s * s;
    __syncthreads();
    if (tid < 64) red[tid] += red[tid + 512];
    __syncthreads();
    for (int st = 256; st > 0; st >>= 1) {
        if (tid < st && tid + st < 576) red[tid] += red[tid + st];
        __syncthreads();
    }
    if (tid == 0) g_sumsq[24] = red[0];
}

// ---------------- two-stage gw reduce ----------------
__global__ __launch_bounds__(256) void reduce_gw_stage1()
{
    const int th = blockIdx.x >> 3;
    const int g  = blockIdx.x & 7;
    const int tid = threadIdx.x;
    const float* src = g_gw_part + ((size_t)th * 128 + g * 16) * 4096;
    float s[16];
#pragma unroll
    for (int q = 0; q < 16; q++) s[q] = 0.f;
    for (int p = 0; p < 16; p++) {
        const float* row = src + (size_t)p * 4096 + tid;
#pragma unroll
        for (int q = 0; q < 16; q++) s[q] += row[q * 256];
    }
    float* dst = g_gw_stage + (size_t)(th * 8 + g) * 4096 + tid;
#pragma unroll
    for (int q = 0; q < 16; q++) dst[q * 256] = s[q];
}

__global__ __launch_bounds__(256) void reduce_gw_stage2()
{
    const int th  = blockIdx.x;
    const int tid = threadIdx.x;
    const float* src = g_gw_stage + (size_t)th * 8 * 4096;
    float* dst = g_gw + (size_t)th * 4096;

    float s[16];
#pragma unroll
    for (int q = 0; q < 16; q++) s[q] = 0.f;
    for (int p = 0; p < 8; p++) {
        const float* row = src + (size_t)p * 4096 + tid;
#pragma unroll
        for (int q = 0; q < 16; q++) s[q] += row[q * 256];
    }
    float ss = 0.f;
#pragma unroll
    for (int q = 0; q < 16; q++) { dst[tid + q * 256] = s[q]; ss += s[q] * s[q]; }

    __shared__ float red[256];
    red[tid] = ss;
    __syncthreads();
    for (int st = 128; st > 0; st >>= 1) {
        if (tid < st) red[tid] += red[tid + st];
        __syncthreads();
    }
    if (tid == 0) g_sumsq[th] = red[0];
}

// ---------------- weight update (scales fused) ----------------
__global__ void update_w_kernel(const float* __restrict__ w1g,
                                const float* __restrict__ w2g,
                                const float* __restrict__ w3g)
{
    __shared__ float sc[3];
    if (threadIdx.x == 0) {
        float s1 = 0.f, s2 = 0.f;
        for (int h = 0; h < NH; h++) { s1 += g_sumsq[h]; s2 += g_sumsq[NH + h]; }
        sc[0] = LR_ / (sqrtf(s1) + 1.f);
        sc[1] = LR_ / (sqrtf(s2) + 1.f);
        sc[2] = LR_ / (sqrtf(g_sumsq[24]) + 1.f);
    }
    __syncthreads();
    const int i = blockIdx.x * 256 + threadIdx.x;
    if (i < 49152) {
        g_mw1[i] = w1g[i] - sc[0] * g_gw[i];
    } else if (i < 98304) {
        const int k = i - 49152;
        g_mw2[k] = w2g[k] - sc[1] * g_gw[49152 + k];
    } else if (i < 98880) {
        const int k = i - 98304;
        g_mw3[k] = w3g[k] - sc[2] * g_gw3[k];
    }
}

// ---------------- conv forward (writes fp16 hi directly) ----------------
__global__ __launch_bounds__(256) void conv_fwd_kernel()
{
    const int bc = blockIdx.x;
    const int b = bc >> 6, c = bc & 63;
    const int tid = threadIdx.x;
    __shared__ float q2s[32][33];
    __shared__ float wk[9];
    if (tid < 9) wk[tid] = g_mw3[c * 9 + tid];
    const float* base = g_qkv + (size_t)(b * N_) * QC;
    for (int p = tid; p < 1024; p += 256)
        q2s[p >> 5][p & 31] = base[(size_t)p * QC + 2304 + c];
    __syncthreads();

    for (int p = tid; p < 1024; p += 256) {
        const int y = p >> 5, x = p & 31;
        float f = 0.f;
#pragma unroll
        for (int dy = 0; dy < 3; dy++)
#pragma unroll
            for (int dx = 0; dx < 3; dx++) {
                int yy = y + dy - 1, xx = x + dx - 1;
                if (yy >= 0 && yy < 32 && xx >= 0 && xx < 32)
                    f = fmaf(wk[dy * 3 + dx], q2s[yy][xx], f);
            }
        g_xch[(size_t)(b * N_ + p) * XC + 768 + c] = __float2half(f);
    }
}

// ---------------- launch ----------------
extern "C" void kernel_launch(void* const* d_in, const int* in_sizes, int n_in,
                              void* d_out, int out_size)
{
    const float *x = nullptr, *Wqkv = nullptr, *bqkv = nullptr, *w1 = nullptr,
                *w2 = nullptr, *w3 = nullptr, *Wproj = nullptr, *bproj = nullptr;
    for (int i = 0; i < n_in; i++) {
        const int s = in_sizes[i];
        const float* p = (const float*)d_in[i];
        if      (s == B_*N_*C_)   x = p;
        else if (s == C_*QC)      Wqkv = p;
        else if (s == QC)         bqkv = p;
        else if (s == NH*HD_*HD_) { if (!w1) w1 = p; else w2 = p; }
        else if (s == 64*9)       w3 = p;
        else if (s == XC*C_)      Wproj = p;
        else if (s == C_)         bproj = p;
    }

    float* qkv_ptr = nullptr;
    __half *xh, *xch, *wqh, *wph;
    cudaGetSymbolAddress((void**)&qkv_ptr, g_qkv);
    cudaGetSymbolAddress((void**)&xh,  g_xh);
    cudaGetSymbolAddress((void**)&xch, g_xch);
    cudaGetSymbolAddress((void**)&wqh, g_wqh);
    cudaGetSymbolAddress((void**)&wph, g_wph);

    cudaFuncSetAttribute(ttt_grad_kernel,
        cudaFuncAttributeMaxDynamicSharedMemorySize, TG_SMEM);
    cudaFuncSetAttribute(ttt_fwd_kernel,
        cudaFuncAttributeMaxDynamicSharedMemorySize, TF_SMEM);
    cudaFuncSetAttribute(tc_gemm,
        cudaFuncAttributeMaxDynamicSharedMemorySize, TCG_SMEM);

    // 1. convert x, transpose weights (plain fp16)
    convert_f16<<<(B_*N_*C_/4 + 255)/256, 256>>>(x, xh, B_*N_*C_/4);
    transpose_f16<<<dim3(QC/32, C_/32), 256>>>(Wqkv, wqh, C_, QC);
    transpose_f16<<<dim3(C_/32, XC/32), 256>>>(Wproj, wph, XC, C_);

    // 2. qkv = x @ Wqkv + bqkv  (plain fp16 HMMA, 64x64 warp tiles)
    tc_gemm<<<dim3((QC + 127)/128, (B_*N_)/128), 128, TCG_SMEM>>>(
        xh, wqh, bqkv, qkv_ptr, QC, C_);

    // 3. TTT (HMMA) + conv gradients, reduce, update
    ttt_grad_kernel<<<dim3(8, NH, B_), 256, TG_SMEM>>>(w1, w2);
    conv_grad_kernel<<<B_ * 64, 256>>>(w3);
    conv_grad_reduce_kernel<<<1, 576>>>();
    reduce_gw_stage1<<<192, 256>>>();
    reduce_gw_stage2<<<24, 256>>>();
    update_w_kernel<<<(98880 + 255)/256, 256>>>(w1, w2, w3);

    // 4. post-update forward (HMMA, 3-term split)
    ttt_fwd_kernel<<<dim3(8, NH, B_), 256, TF_SMEM>>>();
    conv_fwd_kernel<<<B_ * 64, 256>>>();

    // 5. proj GEMM (plain fp16 HMMA, 64x64 warp tiles)
    tc_gemm<<<dim3(C_/128, (B_*N_)/128), 128, TCG_SMEM>>>(
        xch, wph, bproj, (float*)d_out, C_, XC);
}